// round 12
// baseline (speedup 1.0000x reference)
#include <cuda_runtime.h>
#include <math.h>

// ---------------------------------------------------------------------------
// Problem constants
// ---------------------------------------------------------------------------
#define T_  1024
#define D_  768
#define H_  12
#define FF_ 3072
#define V_  8192
#define HD_ 64

// output layout: xt_new [T*D] | xe_new [T*D] | dict_weights [H*T*V] | loss [1]
#define OFF_XE   (T_*D_)
#define OFF_W    (2*T_*D_)
#define OFF_LOSS (2*T_*D_ + H_*T_*V_)

// ---------------------------------------------------------------------------
// Device scratch (allocation-free: __device__ globals)
// ---------------------------------------------------------------------------
__device__ __align__(16) float g_xnorm[T_*D_];
__device__ __align__(16) float g_qk[T_*2*D_];
__device__ __align__(16) float g_v[H_*T_*HD_];
__device__ __align__(16) float g_vT[H_*HD_*T_];
__device__ __align__(16) float g_scores[H_*T_*T_];          // 50 MB
__device__ __align__(16) float g_y[T_*D_];
__device__ __align__(16) float g_x2[T_*D_];
__device__ __align__(16) float g_h[T_*H_*FF_];              // 151 MB
__device__ __align__(16) float g_xpre[T_*D_];
__device__ __align__(16) float g_xhat[T_*D_];
__device__ __align__(16) float g_recon[T_*D_];
__device__ double g_lossPartial[256];

// ---------------------------------------------------------------------------
// Helpers
// ---------------------------------------------------------------------------
__device__ __forceinline__ float gelu_exact(float x) {
    return 0.5f * x * (1.0f + erff(x * 0.70710678118654752f));
}

__device__ __forceinline__ void cp_async16(void* s, const void* g) {
    unsigned sa = (unsigned)__cvta_generic_to_shared(s);
    asm volatile("cp.async.cg.shared.global [%0], [%1], 16;\n" :: "r"(sa), "l"(g));
}
__device__ __forceinline__ void cp_commit() {
    asm volatile("cp.async.commit_group;\n");
}
template<int N>
__device__ __forceinline__ void cp_wait() {
    asm volatile("cp.async.wait_group %0;\n" :: "n"(N));
}

__device__ __forceinline__ void mma_tf32(float* c, const unsigned* a, const unsigned* b) {
    asm volatile(
        "mma.sync.aligned.m16n8k8.row.col.f32.tf32.tf32.f32 "
        "{%0,%1,%2,%3}, {%4,%5,%6,%7}, {%8,%9}, {%0,%1,%2,%3};\n"
        : "+f"(c[0]), "+f"(c[1]), "+f"(c[2]), "+f"(c[3])
        : "r"(a[0]), "r"(a[1]), "r"(a[2]), "r"(a[3]), "r"(b[0]), "r"(b[1]));
}

// ---------------------------------------------------------------------------
// Tensor-core NT GEMM (tf32 mma.sync m16n8k8), cp.async 2-stage pipeline.
//   C[m,n] = alpha * sum_k A[m,k]*B[n,k]   (+bias, +gelu) ; batched over z
// ---------------------------------------------------------------------------
template<int BM, int BN, int BK, int WM, int WN, int THREADS>
__global__ void __launch_bounds__(THREADS)
gemm_tc(const float* __restrict__ A, const float* __restrict__ B,
        float* __restrict__ C, const float* __restrict__ bias,
        int K, int lda, int ldb, int ldc,
        long long sA, long long sB, long long sC, long long sBias,
        float alpha, int mode, int causal, int kcap, int swapxy)
{
    constexpr int NWN = BN / WN;          // warps along N
    constexpr int TM  = WM / 16;          // mma tiles per warp along M
    constexpr int TN  = WN / 8;           // mma tiles per warp along N
    constexpr int LK  = BK + 4;           // smem row stride (words) -> conflict-free
    constexpr int LA  = BM * (BK/4) / THREADS;
    constexpr int LB  = BN * (BK/4) / THREADS;

    const int bx = blockIdx.x, by = blockIdx.y;
    const int m0 = (swapxy ? bx : by) * BM;
    const int n0 = (swapxy ? by : bx) * BN;
    if (causal && n0 > m0 + BM - 1) return;

    __shared__ __align__(16) float As[2][BM][LK];
    __shared__ __align__(16) float Bs[2][BN][LK];

    const int bz = blockIdx.z;
    A += bz * sA;  B += bz * sB;  C += bz * sC;
    if (mode >= 1) bias += bz * sBias;

    const int tid  = threadIdx.x;
    const int lane = tid & 31;
    const int warp = tid >> 5;
    const int gid  = lane >> 2;
    const int t4   = lane & 3;
    const int wm   = warp / NWN;
    const int wn   = warp % NWN;

    float acc[TM][TN][4];
    #pragma unroll
    for (int i = 0; i < TM; i++)
        #pragma unroll
        for (int j = 0; j < TN; j++) {
            acc[i][j][0] = 0.f; acc[i][j][1] = 0.f;
            acc[i][j][2] = 0.f; acc[i][j][3] = 0.f;
        }

    int Keff = K;
    if (kcap) { int ke = m0 + BM; if (ke < K) Keff = ke; }
    const int niter = Keff / BK;

    auto load_stage = [&](int st, int k0) {
        #pragma unroll
        for (int i = 0; i < LA; i++) {
            int l = tid + i * THREADS;
            int r = l / (BK/4), q = (l % (BK/4)) * 4;
            cp_async16(&As[st][r][q], A + (long long)(m0 + r) * lda + k0 + q);
        }
        #pragma unroll
        for (int i = 0; i < LB; i++) {
            int l = tid + i * THREADS;
            int r = l / (BK/4), q = (l % (BK/4)) * 4;
            cp_async16(&Bs[st][r][q], B + (long long)(n0 + r) * ldb + k0 + q);
        }
    };

    load_stage(0, 0);
    cp_commit();
    if (niter > 1) load_stage(1, BK);
    cp_commit();

    for (int it = 0; it < niter; it++) {
        cp_wait<1>();
        __syncthreads();

        const int st = it & 1;
        #pragma unroll
        for (int kk = 0; kk < BK; kk += 8) {
            unsigned a[TM][4], b[TN][2];
            #pragma unroll
            for (int i = 0; i < TM; i++) {
                int r = wm * WM + i * 16 + gid;
                a[i][0] = __float_as_uint(As[st][r    ][kk + t4]);
                a[i][1] = __float_as_uint(As[st][r + 8][kk + t4]);
                a[i][2] = __float_as_uint(As[st][r    ][kk + t4 + 4]);
                a[i][3] = __float_as_uint(As[st][r + 8][kk + t4 + 4]);
            }
            #pragma unroll
            for (int j = 0; j < TN; j++) {
                int c = wn * WN + j * 8 + gid;
                b[j][0] = __float_as_uint(Bs[st][c][kk + t4]);
                b[j][1] = __float_as_uint(Bs[st][c][kk + t4 + 4]);
            }
            #pragma unroll
            for (int i = 0; i < TM; i++)
                #pragma unroll
                for (int j = 0; j < TN; j++)
                    mma_tf32(acc[i][j], a[i], b[j]);
        }
        __syncthreads();

        if (it + 2 < niter) load_stage(st, (it + 2) * BK);
        cp_commit();
    }

    #pragma unroll
    for (int i = 0; i < TM; i++) {
        const int m = m0 + wm * WM + i * 16 + gid;
        #pragma unroll
        for (int j = 0; j < TN; j++) {
            const int n = n0 + wn * WN + j * 8 + t4 * 2;
            float c0 = acc[i][j][0] * alpha, c1 = acc[i][j][1] * alpha;
            float c2 = acc[i][j][2] * alpha, c3 = acc[i][j][3] * alpha;
            if (mode >= 1) {
                float b0 = bias[n], b1 = bias[n + 1];
                c0 += b0; c1 += b1; c2 += b0; c3 += b1;
            }
            if (mode == 2) {
                c0 = gelu_exact(c0); c1 = gelu_exact(c1);
                c2 = gelu_exact(c2); c3 = gelu_exact(c3);
            }
            *reinterpret_cast<float2*>(C + (long long)m       * ldc + n) = make_float2(c0, c1);
            *reinterpret_cast<float2*>(C + (long long)(m + 8) * ldc + n) = make_float2(c2, c3);
        }
    }
}

// ---------------------------------------------------------------------------
// Fused dict chain: logits -> softmax -> weights-out + recon, per (t-tile, head).
// Block: 64 t-rows x 1 head, 256 threads (8 warps: wm=warp>>1 rows, wn=warp&1).
// Pass 1: stream emb in 32-row chunks, logits via tf32 mma, accumulate sum(exp(l)).
//   (max-free: |logit| <~ 2 given LN'd x_hat and 0.02-scaled emb -> no overflow)
// Pass 2: recompute identical logits, w = exp(l)/S -> gmem + smem; recon += W @ emb
//   with emb B-operand read TRANSPOSED from the same smem tile.
// ---------------------------------------------------------------------------
#define DF_RB 64
#define DF_VC 32
#define DF_NC (V_ / DF_VC)   // 256 chunks

__global__ void __launch_bounds__(256)
dict_fused_kernel(const float* __restrict__ xhat,   // [T][D]
                  const float* __restrict__ emb,    // [H][V][64]
                  float* __restrict__ wout,         // [H][T][V]
                  float* __restrict__ recon)        // [T][D]
{
    const int h  = blockIdx.y;
    const int t0 = blockIdx.x * DF_RB;

    __shared__ __align__(16) float sA[DF_RB][68];        // x_hat tile, reused as W tile
    __shared__ __align__(16) float sE[2][DF_VC][68];     // emb chunk (double buffer)
    __shared__ float sS[DF_RB];
    __shared__ float sInv[DF_RB];

    const int tid  = threadIdx.x;
    const int lane = tid & 31;
    const int warp = tid >> 5;
    const int gid  = lane >> 2;
    const int t4   = lane & 3;
    const int wm   = warp >> 1;           // 0..3 -> rows wm*16..+16
    const int wn   = warp & 1;            // 0..1

    // load x_hat tile [64 x 64]
    #pragma unroll
    for (int i = 0; i < 4; i++) {
        int l = tid + i * 256;            // 64 rows * 16 float4
        int r = l >> 4, q = (l & 15) * 4;
        *reinterpret_cast<float4*>(&sA[r][q]) =
            *reinterpret_cast<const float4*>(xhat + (long long)(t0 + r) * D_ + h * HD_ + q);
    }
    if (tid < DF_RB) sS[tid] = 0.f;
    __syncthreads();

    // preload A fragments (rows wm*16+gid, +8), K=64 -> 8 ksteps
    unsigned afr[8][4];
    const int r0 = wm * 16 + gid;
    #pragma unroll
    for (int ks = 0; ks < 8; ks++) {
        int kk = ks * 8;
        afr[ks][0] = __float_as_uint(sA[r0    ][kk + t4]);
        afr[ks][1] = __float_as_uint(sA[r0 + 8][kk + t4]);
        afr[ks][2] = __float_as_uint(sA[r0    ][kk + t4 + 4]);
        afr[ks][3] = __float_as_uint(sA[r0 + 8][kk + t4 + 4]);
    }
    __syncthreads();   // all warps done reading sA (reused as W later)

    const float* Eh = emb + (long long)h * V_ * HD_;
    auto loadE = [&](int st, int v0) {
        #pragma unroll
        for (int i = 0; i < 2; i++) {     // 32 rows * 16 float4 = 512 -> 2/thread
            int l = tid + i * 256;
            int r = l >> 4, q = (l & 15) * 4;
            cp_async16(&sE[st][r][q], Eh + (long long)(v0 + r) * HD_ + q);
        }
    };

    // ================= pass 1: exp-sums =================
    float se0 = 0.f, se1 = 0.f;
    loadE(0, 0);
    cp_commit();
    for (int c = 0; c < DF_NC; c++) {
        if (c + 1 < DF_NC) loadE((c + 1) & 1, (c + 1) * DF_VC);
        cp_commit();
        cp_wait<1>();
        __syncthreads();
        const int st = c & 1;

        float acc[2][4] = {{0.f,0.f,0.f,0.f},{0.f,0.f,0.f,0.f}};
        #pragma unroll
        for (int ks = 0; ks < 8; ks++) {
            int kk = ks * 8;
            unsigned b[2][2];
            #pragma unroll
            for (int j = 0; j < 2; j++) {
                int v = wn * 16 + j * 8 + gid;
                b[j][0] = __float_as_uint(sE[st][v][kk + t4]);
                b[j][1] = __float_as_uint(sE[st][v][kk + t4 + 4]);
            }
            mma_tf32(acc[0], afr[ks], b[0]);
            mma_tf32(acc[1], afr[ks], b[1]);
        }
        #pragma unroll
        for (int j = 0; j < 2; j++) {
            se0 += __expf(acc[j][0]) + __expf(acc[j][1]);
            se1 += __expf(acc[j][2]) + __expf(acc[j][3]);
        }
        __syncthreads();
    }
    // reduce across t4 lanes, then across wn warps
    se0 += __shfl_xor_sync(0xffffffffu, se0, 1);
    se0 += __shfl_xor_sync(0xffffffffu, se0, 2);
    se1 += __shfl_xor_sync(0xffffffffu, se1, 1);
    se1 += __shfl_xor_sync(0xffffffffu, se1, 2);
    if (t4 == 0) {
        atomicAdd(&sS[r0], se0);
        atomicAdd(&sS[r0 + 8], se1);
    }
    __syncthreads();
    if (tid < DF_RB) sInv[tid] = 1.f / sS[tid];
    __syncthreads();
    const float inv0 = sInv[r0], inv1 = sInv[r0 + 8];

    // ================= pass 2: weights out + recon =================
    float racc[4][4];
    #pragma unroll
    for (int j = 0; j < 4; j++) {
        racc[j][0] = 0.f; racc[j][1] = 0.f; racc[j][2] = 0.f; racc[j][3] = 0.f;
    }

    loadE(0, 0);
    cp_commit();
    for (int c = 0; c < DF_NC; c++) {
        if (c + 1 < DF_NC) loadE((c + 1) & 1, (c + 1) * DF_VC);
        cp_commit();
        cp_wait<1>();
        __syncthreads();
        const int st = c & 1;

        // logits (identical replay of pass 1)
        float acc[2][4] = {{0.f,0.f,0.f,0.f},{0.f,0.f,0.f,0.f}};
        #pragma unroll
        for (int ks = 0; ks < 8; ks++) {
            int kk = ks * 8;
            unsigned b[2][2];
            #pragma unroll
            for (int j = 0; j < 2; j++) {
                int v = wn * 16 + j * 8 + gid;
                b[j][0] = __float_as_uint(sE[st][v][kk + t4]);
                b[j][1] = __float_as_uint(sE[st][v][kk + t4 + 4]);
            }
            mma_tf32(acc[0], afr[ks], b[0]);
            mma_tf32(acc[1], afr[ks], b[1]);
        }

        // weights: write to gmem output + stage in smem (sA reused as W tile)
        #pragma unroll
        for (int j = 0; j < 2; j++) {
            int vl = wn * 16 + j * 8 + t4 * 2;
            float w0 = __expf(acc[j][0]) * inv0;
            float w1 = __expf(acc[j][1]) * inv0;
            float w2 = __expf(acc[j][2]) * inv1;
            float w3 = __expf(acc[j][3]) * inv1;
            long long vg = (long long)c * DF_VC + vl;
            *reinterpret_cast<float2*>(wout + ((long long)(h*T_ + t0 + r0    ))*V_ + vg) = make_float2(w0, w1);
            *reinterpret_cast<float2*>(wout + ((long long)(h*T_ + t0 + r0 + 8))*V_ + vg) = make_float2(w2, w3);
            sA[r0    ][vl] = w0;  sA[r0    ][vl + 1] = w1;
            sA[r0 + 8][vl] = w2;  sA[r0 + 8][vl + 1] = w3;
        }
        __syncthreads();

        // recon += W[64 x 32] @ emb_chunk[32 x 64]  (B read transposed from sE)
        #pragma unroll
        for (int ks = 0; ks < 4; ks++) {
            int kk = ks * 8;
            unsigned aw[4], b[4][2];
            aw[0] = __float_as_uint(sA[r0    ][kk + t4]);
            aw[1] = __float_as_uint(sA[r0 + 8][kk + t4]);
            aw[2] = __float_as_uint(sA[r0    ][kk + t4 + 4]);
            aw[3] = __float_as_uint(sA[r0 + 8][kk + t4 + 4]);
            #pragma unroll
            for (int j = 0; j < 4; j++) {
                int e = wn * 32 + j * 8 + gid;
                b[j][0] = __float_as_uint(sE[st][kk + t4    ][e]);
                b[j][1] = __float_as_uint(sE[st][kk + t4 + 4][e]);
            }
            #pragma unroll
            for (int j = 0; j < 4; j++)
                mma_tf32(racc[j], aw, b[j]);
        }
        __syncthreads();
    }

    // write recon tile: [t0+r][h*64 + e]
    #pragma unroll
    for (int j = 0; j < 4; j++) {
        int e = h * HD_ + wn * 32 + j * 8 + t4 * 2;
        *reinterpret_cast<float2*>(recon + (long long)(t0 + r0    ) * D_ + e) =
            make_float2(racc[j][0], racc[j][1]);
        *reinterpret_cast<float2*>(recon + (long long)(t0 + r0 + 8) * D_ + e) =
            make_float2(racc[j][2], racc[j][3]);
    }
}

// ---------------------------------------------------------------------------
// LayerNorm over D=768 of (a + b)
// ---------------------------------------------------------------------------
__global__ void ln2in_kernel(const float* __restrict__ a, const float* __restrict__ b,
                             const float* __restrict__ w, const float* __restrict__ bb,
                             float* __restrict__ out)
{
    const int t = blockIdx.x;
    const int tid = threadIdx.x;
    const float* pa = a + (long long)t * D_;
    const float* pb = b + (long long)t * D_;
    float x[3];
    float s = 0.f, ss = 0.f;
    #pragma unroll
    for (int i = 0; i < 3; i++) {
        int d = tid + i*256;
        float v = pa[d] + pb[d];
        x[i] = v; s += v; ss += v*v;
    }
    #pragma unroll
    for (int o = 16; o; o >>= 1) {
        s  += __shfl_xor_sync(0xffffffffu, s, o);
        ss += __shfl_xor_sync(0xffffffffu, ss, o);
    }
    __shared__ float rs[8], rss[8];
    __shared__ float s_mu, s_inv;
    if ((tid & 31) == 0) { rs[tid >> 5] = s; rss[tid >> 5] = ss; }
    __syncthreads();
    if (tid == 0) {
        float S = 0.f, SS = 0.f;
        #pragma unroll
        for (int i = 0; i < 8; i++) { S += rs[i]; SS += rss[i]; }
        float mu  = S * (1.f / D_);
        float var = SS * (1.f / D_) - mu*mu;
        s_mu = mu;
        s_inv = rsqrtf(var + 1e-5f);
    }
    __syncthreads();
    float mu = s_mu, inv = s_inv;
    #pragma unroll
    for (int i = 0; i < 3; i++) {
        int d = tid + i*256;
        out[(long long)t*D_ + d] = (x[i] - mu) * inv * w[d] + bb[d];
    }
}

// v[h,t,d] = sum_j v_fact[h,j] * xt[t, j*64+d]
__global__ void vmix_kernel(const float* __restrict__ xt, const float* __restrict__ vf,
                            float* __restrict__ v)
{
    int idx = blockIdx.x * 256 + threadIdx.x;
    int d = idx & (HD_-1);
    int t = (idx >> 6) & (T_-1);
    int h = idx >> 16;
    float s = 0.f;
    #pragma unroll
    for (int j = 0; j < H_; j++)
        s += vf[h*H_ + j] * xt[(long long)t*D_ + j*HD_ + d];
    v[idx] = s;
}

// batched transpose in[b][R][C] -> out[b][C][R]
__global__ void transpose_kernel(const float* __restrict__ in, float* __restrict__ out,
                                 int R, int Cc)
{
    __shared__ float tile[32][33];
    const long long boff = (long long)blockIdx.z * R * Cc;
    in += boff; out += boff;
    int c0 = blockIdx.x * 32, r0 = blockIdx.y * 32;
    int x = threadIdx.x, y = threadIdx.y;
    #pragma unroll
    for (int i = 0; i < 32; i += 8)
        tile[y+i][x] = in[(long long)(r0 + y + i) * Cc + c0 + x];
    __syncthreads();
    #pragma unroll
    for (int i = 0; i < 32; i += 8)
        out[(long long)(c0 + y + i) * R + r0 + x] = tile[x][y+i];
}

// causal ALiBi softmax, in place on scores[h][i][:]
__global__ void attn_softmax_kernel(float* __restrict__ sc)
{
    const int bx = blockIdx.x;
    const int i = bx & (T_-1);
    const int h = bx >> 10;
    const float slope = (h < 8) ? exp2f(-(float)(h+1)) : exp2f(-0.5f * (float)(h-7));
    float* row = sc + ((long long)h*T_ + i) * T_;
    const int n = i + 1;
    const int tid = threadIdx.x;
    __shared__ float sh[8];

    float m = -3.4e38f;
    for (int j = tid; j < n; j += 256)
        m = fmaxf(m, row[j] + slope * (float)(j - i));
    #pragma unroll
    for (int o = 16; o; o >>= 1) m = fmaxf(m, __shfl_xor_sync(0xffffffffu, m, o));
    if ((tid & 31) == 0) sh[tid >> 5] = m;
    __syncthreads();
    float M = sh[0];
    #pragma unroll
    for (int w = 1; w < 8; w++) M = fmaxf(M, sh[w]);
    __syncthreads();

    float s = 0.f;
    for (int j = tid; j < n; j += 256) {
        float e = expf(row[j] + slope * (float)(j - i) - M);
        row[j] = e; s += e;
    }
    #pragma unroll
    for (int o = 16; o; o >>= 1) s += __shfl_xor_sync(0xffffffffu, s, o);
    if ((tid & 31) == 0) sh[tid >> 5] = s;
    __syncthreads();
    float S = 0.f;
    #pragma unroll
    for (int w = 0; w < 8; w++) S += sh[w];
    float inv = 1.f / S;
    for (int j = tid; j < n; j += 256) row[j] *= inv;
    for (int j = n + tid; j < T_; j += 256) row[j] = 0.f;
}

// xt_new[t, i*64+d] = xt + sum_j out_fact[i,j] * y[t, j*64+d]
__global__ void outmix_kernel(const float* __restrict__ xt, const float* __restrict__ of,
                              const float* __restrict__ y, float* __restrict__ o)
{
    int idx = blockIdx.x * 256 + threadIdx.x;
    int d = idx & (HD_-1);
    int i = (idx >> 6) % H_;
    int t = idx / D_;
    float s = 0.f;
    #pragma unroll
    for (int j = 0; j < H_; j++)
        s += of[i*H_ + j] * y[(long long)t*D_ + j*HD_ + d];
    o[idx] = xt[idx] + s;
}

// per-(h,t) LayerNorm over HD=64 (one warp per row)
__global__ void dln_kernel(const float* __restrict__ xp, const float* __restrict__ w,
                           const float* __restrict__ b, float* __restrict__ xh)
{
    int bx = blockIdx.x;
    int t = bx & (T_-1);
    int h = bx >> 10;
    int lane = threadIdx.x;
    const float* p = xp + (long long)t*D_ + h*HD_;
    float v0 = p[lane], v1 = p[lane + 32];
    float s = v0 + v1, ss = v0*v0 + v1*v1;
    #pragma unroll
    for (int o = 16; o; o >>= 1) {
        s  += __shfl_xor_sync(0xffffffffu, s, o);
        ss += __shfl_xor_sync(0xffffffffu, ss, o);
    }
    float mu  = s * (1.f / HD_);
    float var = ss * (1.f / HD_) - mu*mu;
    float inv = rsqrtf(var + 1e-5f);
    float* q = xh + (long long)t*D_ + h*HD_;
    q[lane]      = (v0 - mu) * inv * w[h*HD_ + lane]      + b[h*HD_ + lane];
    q[lane + 32] = (v1 - mu) * inv * w[h*HD_ + lane + 32] + b[h*HD_ + lane + 32];
}

__global__ void add_kernel(const float* __restrict__ a, const float* __restrict__ b,
                           float* __restrict__ o)
{
    int idx = blockIdx.x * 256 + threadIdx.x;
    o[idx] = a[idx] + b[idx];
}

__global__ void loss_partial_kernel(const float* __restrict__ a, const float* __restrict__ b)
{
    double s = 0.0;
    for (int idx = blockIdx.x*256 + threadIdx.x; idx < T_*D_; idx += 256*256) {
        float d = a[idx] - b[idx];
        s += (double)d * (double)d;
    }
    __shared__ double sh[256];
    sh[threadIdx.x] = s;
    __syncthreads();
    for (int o = 128; o; o >>= 1) {
        if (threadIdx.x < o) sh[threadIdx.x] += sh[threadIdx.x + o];
        __syncthreads();
    }
    if (threadIdx.x == 0) g_lossPartial[blockIdx.x] = sh[0];
}

__global__ void loss_final_kernel(float* __restrict__ out)
{
    __shared__ double sh[256];
    sh[threadIdx.x] = g_lossPartial[threadIdx.x];
    __syncthreads();
    for (int o = 128; o; o >>= 1) {
        if (threadIdx.x < o) sh[threadIdx.x] += sh[threadIdx.x + o];
        __syncthreads();
    }
    if (threadIdx.x == 0) out[0] = (float)(sh[0] / (double)(T_*D_));
}

// ---------------------------------------------------------------------------
// Host launcher
// ---------------------------------------------------------------------------
extern "C" void kernel_launch(void* const* d_in, const int* in_sizes, int n_in,
                              void* d_out, int out_size)
{
    (void)in_sizes; (void)n_in; (void)out_size;
    const float* xt       = (const float*)d_in[0];
    const float* xe       = (const float*)d_in[1];
    const float* ln1_w    = (const float*)d_in[2];
    const float* ln1_b    = (const float*)d_in[3];
    const float* qk_w     = (const float*)d_in[4];
    const float* qk_b     = (const float*)d_in[5];
    const float* v_fact   = (const float*)d_in[6];
    const float* out_fact = (const float*)d_in[7];
    const float* ln2_w    = (const float*)d_in[8];
    const float* ln2_b    = (const float*)d_in[9];
    const float* fc_w     = (const float*)d_in[10];
    const float* fc_b     = (const float*)d_in[11];
    const float* proj_w   = (const float*)d_in[12];
    const float* proj_b   = (const float*)d_in[13];
    const float* dln_w    = (const float*)d_in[14];
    const float* dln_b    = (const float*)d_in[15];
    const float* dict_emb = (const float*)d_in[16];

    float* out    = (float*)d_out;
    float* o_xt   = out;
    float* o_xe   = out + OFF_XE;
    float* o_w    = out + OFF_W;
    float* o_loss = out + OFF_LOSS;

    float *p_xnorm, *p_qk, *p_v, *p_vT, *p_sc, *p_y, *p_x2, *p_h,
          *p_xpre, *p_xhat, *p_recon;
    cudaGetSymbolAddress((void**)&p_xnorm, g_xnorm);
    cudaGetSymbolAddress((void**)&p_qk,    g_qk);
    cudaGetSymbolAddress((void**)&p_v,     g_v);
    cudaGetSymbolAddress((void**)&p_vT,    g_vT);
    cudaGetSymbolAddress((void**)&p_sc,    g_scores);
    cudaGetSymbolAddress((void**)&p_y,     g_y);
    cudaGetSymbolAddress((void**)&p_x2,    g_x2);
    cudaGetSymbolAddress((void**)&p_h,     g_h);
    cudaGetSymbolAddress((void**)&p_xpre,  g_xpre);
    cudaGetSymbolAddress((void**)&p_xhat,  g_xhat);
    cudaGetSymbolAddress((void**)&p_recon, g_recon);

    // 1) x_norm = LN(xt + xe)
    ln2in_kernel<<<T_, 256>>>(xt, xe, ln1_w, ln1_b, p_xnorm);

    // 2) qk = x_norm @ qk_w^T + qk_b       [T, 1536]
    gemm_tc<128,128,16,64,32,256><<<dim3(2*D_/128, T_/128, 1), 256>>>(
        p_xnorm, qk_w, p_qk, qk_b, D_, D_, D_, 2*D_, 0,0,0,0, 1.f, 1, 0, 0, 0);

    // 3) v[h,t,d] then vT[h,d,t]
    vmix_kernel<<<H_*T_*HD_/256, 256>>>(xt, v_fact, p_v);
    transpose_kernel<<<dim3(HD_/32, T_/32, H_), dim3(32,8)>>>(p_v, p_vT, T_, HD_);

    // 4) scores[h] = 0.125 * q[h] @ k[h]^T   (causal blocks only)
    gemm_tc<128,128,16,64,32,256><<<dim3(T_/128, T_/128, H_), 256>>>(
        p_qk, p_qk + D_, p_sc, nullptr, HD_, 2*D_, 2*D_, T_,
        64, 64, (long long)T_*T_, 0, 0.125f, 0, 1, 0, 0);

    // 5) causal ALiBi softmax in place
    attn_softmax_kernel<<<H_*T_, 256>>>(p_sc);

    // 6) y[h] = probs[h] @ v[h]  -> g_y[t, h*64+d]   (K capped at diagonal)
    gemm_tc<64,64,16,32,32,128><<<dim3(HD_/64, T_/64, H_), 128>>>(
        p_sc, p_vT, p_y, nullptr, T_, T_, T_, D_,
        (long long)T_*T_, (long long)HD_*T_, 64, 0, 1.f, 0, 0, 1, 0);

    // 7) xt_new = xt + out_fact-mix(y)
    outmix_kernel<<<T_*D_/256, 256>>>(xt, out_fact, p_y, o_xt);

    // 8) x2 = LN(xt_new + xe)
    ln2in_kernel<<<T_, 256>>>(o_xt, xe, ln2_w, ln2_b, p_x2);

    // 9) h = gelu(x2 @ fc_w^T + fc_b)   [T, 36864]   -- dominant GEMM
    gemm_tc<128,128,16,64,32,256><<<dim3(T_/128, H_*FF_/128, 1), 256>>>(
        p_x2, fc_w, p_h, fc_b, D_, D_, D_, H_*FF_, 0,0,0,0, 1.f, 2, 0, 0, 1);

    // 10) xpre[h] = h[h] @ proj_w[h]^T + proj_b[h]
    gemm_tc<64,64,16,32,32,128><<<dim3(HD_/64, T_/64, H_), 128>>>(
        p_h, proj_w, p_xpre, proj_b, FF_, H_*FF_, FF_, D_,
        FF_, (long long)HD_*FF_, 64, HD_, 1.f, 1, 0, 0, 0);

    // 11) x_hat = per-head LN(xpre)
    dln_kernel<<<H_*T_, 32>>>(p_xpre, dln_w, dln_b, p_xhat);

    // 12) fused dict chain: logits -> softmax -> weights + recon
    dict_fused_kernel<<<dim3(T_/DF_RB, H_), 256>>>(p_xhat, dict_emb, o_w, p_recon);

    // 13) xe_new = xe + x_recon
    add_kernel<<<T_*D_/256, 256>>>(xe, p_recon, o_xe);

    // 14) dict_loss = mean((x_hat - x_recon)^2)
    loss_partial_kernel<<<256, 256>>>(p_xhat, p_recon);
    loss_final_kernel<<<1, 256>>>(o_loss);
}

// round 13
// speedup vs baseline: 1.0806x; 1.0806x over previous
#include <cuda_runtime.h>
#include <math.h>

// ---------------------------------------------------------------------------
// Problem constants
// ---------------------------------------------------------------------------
#define T_  1024
#define D_  768
#define H_  12
#define FF_ 3072
#define V_  8192
#define HD_ 64

// output layout: xt_new [T*D] | xe_new [T*D] | dict_weights [H*T*V] | loss [1]
#define OFF_XE   (T_*D_)
#define OFF_W    (2*T_*D_)
#define OFF_LOSS (2*T_*D_ + H_*T_*V_)

// ---------------------------------------------------------------------------
// Device scratch (allocation-free: __device__ globals)
// ---------------------------------------------------------------------------
__device__ __align__(16) float g_xnorm[T_*D_];
__device__ __align__(16) float g_qk[T_*2*D_];
__device__ __align__(16) float g_v[H_*T_*HD_];
__device__ __align__(16) float g_vT[H_*HD_*T_];
__device__ __align__(16) float g_scores[H_*T_*T_];          // 50 MB
__device__ __align__(16) float g_y[T_*D_];
__device__ __align__(16) float g_x2[T_*D_];
__device__ __align__(16) float g_h[T_*H_*FF_];              // 151 MB
__device__ __align__(16) float g_xpre[T_*D_];
__device__ __align__(16) float g_xhat[T_*D_];
__device__ __align__(16) float g_recon[T_*D_];
__device__ double g_lossPartial[256];

// ---------------------------------------------------------------------------
// Helpers
// ---------------------------------------------------------------------------
__device__ __forceinline__ float gelu_exact(float x) {
    return 0.5f * x * (1.0f + erff(x * 0.70710678118654752f));
}

__device__ __forceinline__ void cp_async16(void* s, const void* g) {
    unsigned sa = (unsigned)__cvta_generic_to_shared(s);
    asm volatile("cp.async.cg.shared.global [%0], [%1], 16;\n" :: "r"(sa), "l"(g));
}
__device__ __forceinline__ void cp_commit() {
    asm volatile("cp.async.commit_group;\n");
}
template<int N>
__device__ __forceinline__ void cp_wait() {
    asm volatile("cp.async.wait_group %0;\n" :: "n"(N));
}

__device__ __forceinline__ void mma_tf32(float* c, const unsigned* a, const unsigned* b) {
    asm volatile(
        "mma.sync.aligned.m16n8k8.row.col.f32.tf32.tf32.f32 "
        "{%0,%1,%2,%3}, {%4,%5,%6,%7}, {%8,%9}, {%0,%1,%2,%3};\n"
        : "+f"(c[0]), "+f"(c[1]), "+f"(c[2]), "+f"(c[3])
        : "r"(a[0]), "r"(a[1]), "r"(a[2]), "r"(a[3]), "r"(b[0]), "r"(b[1]));
}

// ---------------------------------------------------------------------------
// Tensor-core NT GEMM (tf32 mma.sync m16n8k8), cp.async 2-stage pipeline.
//   C[m,n] = alpha * sum_k A[m,k]*B[n,k]   (+bias, +gelu) ; batched over z
// ---------------------------------------------------------------------------
template<int BM, int BN, int BK, int WM, int WN, int THREADS>
__global__ void __launch_bounds__(THREADS)
gemm_tc(const float* __restrict__ A, const float* __restrict__ B,
        float* __restrict__ C, const float* __restrict__ bias,
        int K, int lda, int ldb, int ldc,
        long long sA, long long sB, long long sC, long long sBias,
        float alpha, int mode, int causal, int kcap, int swapxy)
{
    constexpr int NWN = BN / WN;          // warps along N
    constexpr int TM  = WM / 16;          // mma tiles per warp along M
    constexpr int TN  = WN / 8;           // mma tiles per warp along N
    constexpr int LK  = BK + 4;           // smem row stride (words) -> conflict-free
    constexpr int LA  = BM * (BK/4) / THREADS;
    constexpr int LB  = BN * (BK/4) / THREADS;

    const int bx = blockIdx.x, by = blockIdx.y;
    const int m0 = (swapxy ? bx : by) * BM;
    const int n0 = (swapxy ? by : bx) * BN;
    if (causal && n0 > m0 + BM - 1) return;

    __shared__ __align__(16) float As[2][BM][LK];
    __shared__ __align__(16) float Bs[2][BN][LK];

    const int bz = blockIdx.z;
    A += bz * sA;  B += bz * sB;  C += bz * sC;
    if (mode >= 1) bias += bz * sBias;

    const int tid  = threadIdx.x;
    const int lane = tid & 31;
    const int warp = tid >> 5;
    const int gid  = lane >> 2;
    const int t4   = lane & 3;
    const int wm   = warp / NWN;
    const int wn   = warp % NWN;

    float acc[TM][TN][4];
    #pragma unroll
    for (int i = 0; i < TM; i++)
        #pragma unroll
        for (int j = 0; j < TN; j++) {
            acc[i][j][0] = 0.f; acc[i][j][1] = 0.f;
            acc[i][j][2] = 0.f; acc[i][j][3] = 0.f;
        }

    int Keff = K;
    if (kcap) { int ke = m0 + BM; if (ke < K) Keff = ke; }
    const int niter = Keff / BK;

    auto load_stage = [&](int st, int k0) {
        #pragma unroll
        for (int i = 0; i < LA; i++) {
            int l = tid + i * THREADS;
            int r = l / (BK/4), q = (l % (BK/4)) * 4;
            cp_async16(&As[st][r][q], A + (long long)(m0 + r) * lda + k0 + q);
        }
        #pragma unroll
        for (int i = 0; i < LB; i++) {
            int l = tid + i * THREADS;
            int r = l / (BK/4), q = (l % (BK/4)) * 4;
            cp_async16(&Bs[st][r][q], B + (long long)(n0 + r) * ldb + k0 + q);
        }
    };

    load_stage(0, 0);
    cp_commit();
    if (niter > 1) load_stage(1, BK);
    cp_commit();

    for (int it = 0; it < niter; it++) {
        cp_wait<1>();
        __syncthreads();

        const int st = it & 1;
        #pragma unroll
        for (int kk = 0; kk < BK; kk += 8) {
            unsigned a[TM][4], b[TN][2];
            #pragma unroll
            for (int i = 0; i < TM; i++) {
                int r = wm * WM + i * 16 + gid;
                a[i][0] = __float_as_uint(As[st][r    ][kk + t4]);
                a[i][1] = __float_as_uint(As[st][r + 8][kk + t4]);
                a[i][2] = __float_as_uint(As[st][r    ][kk + t4 + 4]);
                a[i][3] = __float_as_uint(As[st][r + 8][kk + t4 + 4]);
            }
            #pragma unroll
            for (int j = 0; j < TN; j++) {
                int c = wn * WN + j * 8 + gid;
                b[j][0] = __float_as_uint(Bs[st][c][kk + t4]);
                b[j][1] = __float_as_uint(Bs[st][c][kk + t4 + 4]);
            }
            #pragma unroll
            for (int i = 0; i < TM; i++)
                #pragma unroll
                for (int j = 0; j < TN; j++)
                    mma_tf32(acc[i][j], a[i], b[j]);
        }
        __syncthreads();

        if (it + 2 < niter) load_stage(st, (it + 2) * BK);
        cp_commit();
    }

    #pragma unroll
    for (int i = 0; i < TM; i++) {
        const int m = m0 + wm * WM + i * 16 + gid;
        #pragma unroll
        for (int j = 0; j < TN; j++) {
            const int n = n0 + wn * WN + j * 8 + t4 * 2;
            float c0 = acc[i][j][0] * alpha, c1 = acc[i][j][1] * alpha;
            float c2 = acc[i][j][2] * alpha, c3 = acc[i][j][3] * alpha;
            if (mode >= 1) {
                float b0 = bias[n], b1 = bias[n + 1];
                c0 += b0; c1 += b1; c2 += b0; c3 += b1;
            }
            if (mode == 2) {
                c0 = gelu_exact(c0); c1 = gelu_exact(c1);
                c2 = gelu_exact(c2); c3 = gelu_exact(c3);
            }
            *reinterpret_cast<float2*>(C + (long long)m       * ldc + n) = make_float2(c0, c1);
            *reinterpret_cast<float2*>(C + (long long)(m + 8) * ldc + n) = make_float2(c2, c3);
        }
    }
}

// ---------------------------------------------------------------------------
// Fused dict chain v2: logits -> softmax -> weights-out + recon.
// Block: 32 t-rows x 1 head, 128 threads (4 warps), grid 32 x 12 = 384 CTAs.
// smem ~52 KB -> 4 CTAs/SM so barrier/L2 latency is overlapped.
// V streamed in 64-row chunks (128 chunks), cp.async double-buffered.
// Max-free softmax: |logit| small (LN'd x_hat . 0.02-scale emb).
// ---------------------------------------------------------------------------
#define DF_RB 32
#define DF_VC 64
#define DF_NC (V_ / DF_VC)   // 128 chunks

__global__ void __launch_bounds__(128)
dict_fused_kernel(const float* __restrict__ xhat,   // [T][D]
                  const float* __restrict__ emb,    // [H][V][64]
                  float* __restrict__ wout,         // [H][T][V]
                  float* __restrict__ recon)        // [T][D]
{
    const int h  = blockIdx.y;
    const int t0 = blockIdx.x * DF_RB;

    __shared__ __align__(16) float sA[DF_RB][68];        // x_hat tile
    __shared__ __align__(16) float sW[DF_RB][68];        // weights chunk (pass 2)
    __shared__ __align__(16) float sE[2][DF_VC][68];     // emb chunk (double buffer)
    __shared__ float sS[DF_RB];
    __shared__ float sInv[DF_RB];

    const int tid  = threadIdx.x;
    const int lane = tid & 31;
    const int warp = tid >> 5;
    const int gid  = lane >> 2;
    const int t4   = lane & 3;
    const int wm   = warp >> 1;           // 0..1 -> rows wm*16..+16
    const int wn   = warp & 1;            // 0..1 -> v/e columns wn*32..+32

    // load x_hat tile [32 x 64]
    #pragma unroll
    for (int i = 0; i < 4; i++) {
        int l = tid + i * 128;            // 32 rows * 16 float4
        int r = l >> 4, q = (l & 15) * 4;
        *reinterpret_cast<float4*>(&sA[r][q]) =
            *reinterpret_cast<const float4*>(xhat + (long long)(t0 + r) * D_ + h * HD_ + q);
    }
    if (tid < DF_RB) sS[tid] = 0.f;
    __syncthreads();

    // preload A fragments (rows r0, r0+8), K=64 -> 8 ksteps
    const int r0 = wm * 16 + gid;
    unsigned afr[8][4];
    #pragma unroll
    for (int ks = 0; ks < 8; ks++) {
        int kk = ks * 8;
        afr[ks][0] = __float_as_uint(sA[r0    ][kk + t4]);
        afr[ks][1] = __float_as_uint(sA[r0 + 8][kk + t4]);
        afr[ks][2] = __float_as_uint(sA[r0    ][kk + t4 + 4]);
        afr[ks][3] = __float_as_uint(sA[r0 + 8][kk + t4 + 4]);
    }

    const float* Eh = emb + (long long)h * V_ * HD_;
    auto loadE = [&](int st, int v0) {
        #pragma unroll
        for (int i = 0; i < 8; i++) {     // 64 rows * 16 float4 = 1024 -> 8/thread
            int l = tid + i * 128;
            int r = l >> 4, q = (l & 15) * 4;
            cp_async16(&sE[st][r][q], Eh + (long long)(v0 + r) * HD_ + q);
        }
    };

    // ================= pass 1: exp-sums =================
    float se0 = 0.f, se1 = 0.f;
    loadE(0, 0);
    cp_commit();
    for (int c = 0; c < DF_NC; c++) {
        if (c + 1 < DF_NC) loadE((c + 1) & 1, (c + 1) * DF_VC);
        cp_commit();
        cp_wait<1>();
        __syncthreads();
        const int st = c & 1;

        #pragma unroll
        for (int j = 0; j < 4; j++) {
            float acc[4] = {0.f, 0.f, 0.f, 0.f};
            #pragma unroll
            for (int ks = 0; ks < 8; ks++) {
                int kk = ks * 8;
                int v = wn * 32 + j * 8 + gid;
                unsigned b[2];
                b[0] = __float_as_uint(sE[st][v][kk + t4]);
                b[1] = __float_as_uint(sE[st][v][kk + t4 + 4]);
                mma_tf32(acc, afr[ks], b);
            }
            se0 += __expf(acc[0]) + __expf(acc[1]);
            se1 += __expf(acc[2]) + __expf(acc[3]);
        }
        __syncthreads();
    }
    // reduce across t4 lanes (cols), then across wn warps via smem atomics
    se0 += __shfl_xor_sync(0xffffffffu, se0, 1);
    se0 += __shfl_xor_sync(0xffffffffu, se0, 2);
    se1 += __shfl_xor_sync(0xffffffffu, se1, 1);
    se1 += __shfl_xor_sync(0xffffffffu, se1, 2);
    if (t4 == 0) {
        atomicAdd(&sS[r0], se0);
        atomicAdd(&sS[r0 + 8], se1);
    }
    __syncthreads();
    if (tid < DF_RB) sInv[tid] = 1.f / sS[tid];
    __syncthreads();
    const float inv0 = sInv[r0], inv1 = sInv[r0 + 8];

    // ================= pass 2: weights out + recon =================
    float racc[4][4];
    #pragma unroll
    for (int j = 0; j < 4; j++) {
        racc[j][0] = 0.f; racc[j][1] = 0.f; racc[j][2] = 0.f; racc[j][3] = 0.f;
    }

    loadE(0, 0);
    cp_commit();
    for (int c = 0; c < DF_NC; c++) {
        if (c + 1 < DF_NC) loadE((c + 1) & 1, (c + 1) * DF_VC);
        cp_commit();
        cp_wait<1>();
        __syncthreads();
        const int st = c & 1;

        // logits (identical replay of pass 1), weights -> gmem + sW
        #pragma unroll
        for (int j = 0; j < 4; j++) {
            float acc[4] = {0.f, 0.f, 0.f, 0.f};
            #pragma unroll
            for (int ks = 0; ks < 8; ks++) {
                int kk = ks * 8;
                int v = wn * 32 + j * 8 + gid;
                unsigned b[2];
                b[0] = __float_as_uint(sE[st][v][kk + t4]);
                b[1] = __float_as_uint(sE[st][v][kk + t4 + 4]);
                mma_tf32(acc, afr[ks], b);
            }
            int vl = wn * 32 + j * 8 + t4 * 2;
            float w0 = __expf(acc[0]) * inv0;
            float w1 = __expf(acc[1]) * inv0;
            float w2 = __expf(acc[2]) * inv1;
            float w3 = __expf(acc[3]) * inv1;
            long long vg = (long long)c * DF_VC + vl;
            *reinterpret_cast<float2*>(wout + ((long long)(h*T_ + t0 + r0    ))*V_ + vg) = make_float2(w0, w1);
            *reinterpret_cast<float2*>(wout + ((long long)(h*T_ + t0 + r0 + 8))*V_ + vg) = make_float2(w2, w3);
            sW[r0    ][vl] = w0;  sW[r0    ][vl + 1] = w1;
            sW[r0 + 8][vl] = w2;  sW[r0 + 8][vl + 1] = w3;
        }
        __syncthreads();

        // recon += W[32 x 64] @ emb_chunk[64 x 64]^T-read-from-sE
        #pragma unroll
        for (int ks = 0; ks < 8; ks++) {
            int kk = ks * 8;
            unsigned aw[4];
            aw[0] = __float_as_uint(sW[r0    ][kk + t4]);
            aw[1] = __float_as_uint(sW[r0 + 8][kk + t4]);
            aw[2] = __float_as_uint(sW[r0    ][kk + t4 + 4]);
            aw[3] = __float_as_uint(sW[r0 + 8][kk + t4 + 4]);
            #pragma unroll
            for (int j = 0; j < 4; j++) {
                int e = wn * 32 + j * 8 + gid;
                unsigned b[2];
                b[0] = __float_as_uint(sE[st][kk + t4    ][e]);
                b[1] = __float_as_uint(sE[st][kk + t4 + 4][e]);
                mma_tf32(racc[j], aw, b);
            }
        }
        __syncthreads();
    }

    // write recon tile: [t0+r][h*64 + e]
    #pragma unroll
    for (int j = 0; j < 4; j++) {
        int e = h * HD_ + wn * 32 + j * 8 + t4 * 2;
        *reinterpret_cast<float2*>(recon + (long long)(t0 + r0    ) * D_ + e) =
            make_float2(racc[j][0], racc[j][1]);
        *reinterpret_cast<float2*>(recon + (long long)(t0 + r0 + 8) * D_ + e) =
            make_float2(racc[j][2], racc[j][3]);
    }
}

// ---------------------------------------------------------------------------
// LayerNorm over D=768 of (a + b)
// ---------------------------------------------------------------------------
__global__ void ln2in_kernel(const float* __restrict__ a, const float* __restrict__ b,
                             const float* __restrict__ w, const float* __restrict__ bb,
                             float* __restrict__ out)
{
    const int t = blockIdx.x;
    const int tid = threadIdx.x;
    const float* pa = a + (long long)t * D_;
    const float* pb = b + (long long)t * D_;
    float x[3];
    float s = 0.f, ss = 0.f;
    #pragma unroll
    for (int i = 0; i < 3; i++) {
        int d = tid + i*256;
        float v = pa[d] + pb[d];
        x[i] = v; s += v; ss += v*v;
    }
    #pragma unroll
    for (int o = 16; o; o >>= 1) {
        s  += __shfl_xor_sync(0xffffffffu, s, o);
        ss += __shfl_xor_sync(0xffffffffu, ss, o);
    }
    __shared__ float rs[8], rss[8];
    __shared__ float s_mu, s_inv;
    if ((tid & 31) == 0) { rs[tid >> 5] = s; rss[tid >> 5] = ss; }
    __syncthreads();
    if (tid == 0) {
        float S = 0.f, SS = 0.f;
        #pragma unroll
        for (int i = 0; i < 8; i++) { S += rs[i]; SS += rss[i]; }
        float mu  = S * (1.f / D_);
        float var = SS * (1.f / D_) - mu*mu;
        s_mu = mu;
        s_inv = rsqrtf(var + 1e-5f);
    }
    __syncthreads();
    float mu = s_mu, inv = s_inv;
    #pragma unroll
    for (int i = 0; i < 3; i++) {
        int d = tid + i*256;
        out[(long long)t*D_ + d] = (x[i] - mu) * inv * w[d] + bb[d];
    }
}

// v[h,t,d] = sum_j v_fact[h,j] * xt[t, j*64+d]
__global__ void vmix_kernel(const float* __restrict__ xt, const float* __restrict__ vf,
                            float* __restrict__ v)
{
    int idx = blockIdx.x * 256 + threadIdx.x;
    int d = idx & (HD_-1);
    int t = (idx >> 6) & (T_-1);
    int h = idx >> 16;
    float s = 0.f;
    #pragma unroll
    for (int j = 0; j < H_; j++)
        s += vf[h*H_ + j] * xt[(long long)t*D_ + j*HD_ + d];
    v[idx] = s;
}

// batched transpose in[b][R][C] -> out[b][C][R]
__global__ void transpose_kernel(const float* __restrict__ in, float* __restrict__ out,
                                 int R, int Cc)
{
    __shared__ float tile[32][33];
    const long long boff = (long long)blockIdx.z * R * Cc;
    in += boff; out += boff;
    int c0 = blockIdx.x * 32, r0 = blockIdx.y * 32;
    int x = threadIdx.x, y = threadIdx.y;
    #pragma unroll
    for (int i = 0; i < 32; i += 8)
        tile[y+i][x] = in[(long long)(r0 + y + i) * Cc + c0 + x];
    __syncthreads();
    #pragma unroll
    for (int i = 0; i < 32; i += 8)
        out[(long long)(c0 + y + i) * R + r0 + x] = tile[x][y+i];
}

// causal ALiBi softmax, in place on scores[h][i][:]
__global__ void attn_softmax_kernel(float* __restrict__ sc)
{
    const int bx = blockIdx.x;
    const int i = bx & (T_-1);
    const int h = bx >> 10;
    const float slope = (h < 8) ? exp2f(-(float)(h+1)) : exp2f(-0.5f * (float)(h-7));
    float* row = sc + ((long long)h*T_ + i) * T_;
    const int n = i + 1;
    const int tid = threadIdx.x;
    __shared__ float sh[8];

    float m = -3.4e38f;
    for (int j = tid; j < n; j += 256)
        m = fmaxf(m, row[j] + slope * (float)(j - i));
    #pragma unroll
    for (int o = 16; o; o >>= 1) m = fmaxf(m, __shfl_xor_sync(0xffffffffu, m, o));
    if ((tid & 31) == 0) sh[tid >> 5] = m;
    __syncthreads();
    float M = sh[0];
    #pragma unroll
    for (int w = 1; w < 8; w++) M = fmaxf(M, sh[w]);
    __syncthreads();

    float s = 0.f;
    for (int j = tid; j < n; j += 256) {
        float e = expf(row[j] + slope * (float)(j - i) - M);
        row[j] = e; s += e;
    }
    #pragma unroll
    for (int o = 16; o; o >>= 1) s += __shfl_xor_sync(0xffffffffu, s, o);
    if ((tid & 31) == 0) sh[tid >> 5] = s;
    __syncthreads();
    float S = 0.f;
    #pragma unroll
    for (int w = 0; w < 8; w++) S += sh[w];
    float inv = 1.f / S;
    for (int j = tid; j < n; j += 256) row[j] *= inv;
    for (int j = n + tid; j < T_; j += 256) row[j] = 0.f;
}

// xt_new[t, i*64+d] = xt + sum_j out_fact[i,j] * y[t, j*64+d]
__global__ void outmix_kernel(const float* __restrict__ xt, const float* __restrict__ of,
                              const float* __restrict__ y, float* __restrict__ o)
{
    int idx = blockIdx.x * 256 + threadIdx.x;
    int d = idx & (HD_-1);
    int i = (idx >> 6) % H_;
    int t = idx / D_;
    float s = 0.f;
    #pragma unroll
    for (int j = 0; j < H_; j++)
        s += of[i*H_ + j] * y[(long long)t*D_ + j*HD_ + d];
    o[idx] = xt[idx] + s;
}

// per-(h,t) LayerNorm over HD=64 (one warp per row)
__global__ void dln_kernel(const float* __restrict__ xp, const float* __restrict__ w,
                           const float* __restrict__ b, float* __restrict__ xh)
{
    int bx = blockIdx.x;
    int t = bx & (T_-1);
    int h = bx >> 10;
    int lane = threadIdx.x;
    const float* p = xp + (long long)t*D_ + h*HD_;
    float v0 = p[lane], v1 = p[lane + 32];
    float s = v0 + v1, ss = v0*v0 + v1*v1;
    #pragma unroll
    for (int o = 16; o; o >>= 1) {
        s  += __shfl_xor_sync(0xffffffffu, s, o);
        ss += __shfl_xor_sync(0xffffffffu, ss, o);
    }
    float mu  = s * (1.f / HD_);
    float var = ss * (1.f / HD_) - mu*mu;
    float inv = rsqrtf(var + 1e-5f);
    float* q = xh + (long long)t*D_ + h*HD_;
    q[lane]      = (v0 - mu) * inv * w[h*HD_ + lane]      + b[h*HD_ + lane];
    q[lane + 32] = (v1 - mu) * inv * w[h*HD_ + lane + 32] + b[h*HD_ + lane + 32];
}

__global__ void add_kernel(const float* __restrict__ a, const float* __restrict__ b,
                           float* __restrict__ o)
{
    int idx = blockIdx.x * 256 + threadIdx.x;
    o[idx] = a[idx] + b[idx];
}

__global__ void loss_partial_kernel(const float* __restrict__ a, const float* __restrict__ b)
{
    double s = 0.0;
    for (int idx = blockIdx.x*256 + threadIdx.x; idx < T_*D_; idx += 256*256) {
        float d = a[idx] - b[idx];
        s += (double)d * (double)d;
    }
    __shared__ double sh[256];
    sh[threadIdx.x] = s;
    __syncthreads();
    for (int o = 128; o; o >>= 1) {
        if (threadIdx.x < o) sh[threadIdx.x] += sh[threadIdx.x + o];
        __syncthreads();
    }
    if (threadIdx.x == 0) g_lossPartial[blockIdx.x] = sh[0];
}

__global__ void loss_final_kernel(float* __restrict__ out)
{
    __shared__ double sh[256];
    sh[threadIdx.x] = g_lossPartial[threadIdx.x];
    __syncthreads();
    for (int o = 128; o; o >>= 1) {
        if (threadIdx.x < o) sh[threadIdx.x] += sh[threadIdx.x + o];
        __syncthreads();
    }
    if (threadIdx.x == 0) out[0] = (float)(sh[0] / (double)(T_*D_));
}

// ---------------------------------------------------------------------------
// Host launcher
// ---------------------------------------------------------------------------
extern "C" void kernel_launch(void* const* d_in, const int* in_sizes, int n_in,
                              void* d_out, int out_size)
{
    (void)in_sizes; (void)n_in; (void)out_size;
    const float* xt       = (const float*)d_in[0];
    const float* xe       = (const float*)d_in[1];
    const float* ln1_w    = (const float*)d_in[2];
    const float* ln1_b    = (const float*)d_in[3];
    const float* qk_w     = (const float*)d_in[4];
    const float* qk_b     = (const float*)d_in[5];
    const float* v_fact   = (const float*)d_in[6];
    const float* out_fact = (const float*)d_in[7];
    const float* ln2_w    = (const float*)d_in[8];
    const float* ln2_b    = (const float*)d_in[9];
    const float* fc_w     = (const float*)d_in[10];
    const float* fc_b     = (const float*)d_in[11];
    const float* proj_w   = (const float*)d_in[12];
    const float* proj_b   = (const float*)d_in[13];
    const float* dln_w    = (const float*)d_in[14];
    const float* dln_b    = (const float*)d_in[15];
    const float* dict_emb = (const float*)d_in[16];

    float* out    = (float*)d_out;
    float* o_xt   = out;
    float* o_xe   = out + OFF_XE;
    float* o_w    = out + OFF_W;
    float* o_loss = out + OFF_LOSS;

    float *p_xnorm, *p_qk, *p_v, *p_vT, *p_sc, *p_y, *p_x2, *p_h,
          *p_xpre, *p_xhat, *p_recon;
    cudaGetSymbolAddress((void**)&p_xnorm, g_xnorm);
    cudaGetSymbolAddress((void**)&p_qk,    g_qk);
    cudaGetSymbolAddress((void**)&p_v,     g_v);
    cudaGetSymbolAddress((void**)&p_vT,    g_vT);
    cudaGetSymbolAddress((void**)&p_sc,    g_scores);
    cudaGetSymbolAddress((void**)&p_y,     g_y);
    cudaGetSymbolAddress((void**)&p_x2,    g_x2);
    cudaGetSymbolAddress((void**)&p_h,     g_h);
    cudaGetSymbolAddress((void**)&p_xpre,  g_xpre);
    cudaGetSymbolAddress((void**)&p_xhat,  g_xhat);
    cudaGetSymbolAddress((void**)&p_recon, g_recon);

    // 1) x_norm = LN(xt + xe)
    ln2in_kernel<<<T_, 256>>>(xt, xe, ln1_w, ln1_b, p_xnorm);

    // 2) qk = x_norm @ qk_w^T + qk_b       [T, 1536]
    gemm_tc<128,128,16,64,32,256><<<dim3(2*D_/128, T_/128, 1), 256>>>(
        p_xnorm, qk_w, p_qk, qk_b, D_, D_, D_, 2*D_, 0,0,0,0, 1.f, 1, 0, 0, 0);

    // 3) v[h,t,d] then vT[h,d,t]
    vmix_kernel<<<H_*T_*HD_/256, 256>>>(xt, v_fact, p_v);
    transpose_kernel<<<dim3(HD_/32, T_/32, H_), dim3(32,8)>>>(p_v, p_vT, T_, HD_);

    // 4) scores[h] = 0.125 * q[h] @ k[h]^T   (causal blocks only)
    gemm_tc<128,128,16,64,32,256><<<dim3(T_/128, T_/128, H_), 256>>>(
        p_qk, p_qk + D_, p_sc, nullptr, HD_, 2*D_, 2*D_, T_,
        64, 64, (long long)T_*T_, 0, 0.125f, 0, 1, 0, 0);

    // 5) causal ALiBi softmax in place
    attn_softmax_kernel<<<H_*T_, 256>>>(p_sc);

    // 6) y[h] = probs[h] @ v[h]  -> g_y[t, h*64+d]   (K capped at diagonal)
    gemm_tc<64,64,16,32,32,128><<<dim3(HD_/64, T_/64, H_), 128>>>(
        p_sc, p_vT, p_y, nullptr, T_, T_, T_, D_,
        (long long)T_*T_, (long long)HD_*T_, 64, 0, 1.f, 0, 0, 1, 0);

    // 7) xt_new = xt + out_fact-mix(y)
    outmix_kernel<<<T_*D_/256, 256>>>(xt, out_fact, p_y, o_xt);

    // 8) x2 = LN(xt_new + xe)
    ln2in_kernel<<<T_, 256>>>(o_xt, xe, ln2_w, ln2_b, p_x2);

    // 9) h = gelu(x2 @ fc_w^T + fc_b)   [T, 36864]   -- dominant GEMM
    gemm_tc<128,128,16,64,32,256><<<dim3(T_/128, H_*FF_/128, 1), 256>>>(
        p_x2, fc_w, p_h, fc_b, D_, D_, D_, H_*FF_, 0,0,0,0, 1.f, 2, 0, 0, 1);

    // 10) xpre[h] = h[h] @ proj_w[h]^T + proj_b[h]
    gemm_tc<64,64,16,32,32,128><<<dim3(HD_/64, T_/64, H_), 128>>>(
        p_h, proj_w, p_xpre, proj_b, FF_, H_*FF_, FF_, D_,
        FF_, (long long)HD_*FF_, 64, HD_, 1.f, 1, 0, 0, 0);

    // 11) x_hat = per-head LN(xpre)
    dln_kernel<<<H_*T_, 32>>>(p_xpre, dln_w, dln_b, p_xhat);

    // 12) fused dict chain: logits -> softmax -> weights + recon
    dict_fused_kernel<<<dim3(T_/DF_RB, H_), 128>>>(p_xhat, dict_emb, o_w, p_recon);

    // 13) xe_new = xe + x_recon
    add_kernel<<<T_*D_/256, 256>>>(xe, p_recon, o_xe);

    // 14) dict_loss = mean((x_hat - x_recon)^2)
    loss_partial_kernel<<<256, 256>>>(p_xhat, p_recon);
    loss_final_kernel<<<1, 256>>>(o_loss);
}

// round 14
// speedup vs baseline: 1.1276x; 1.0436x over previous
#include <cuda_runtime.h>
#include <math.h>

// ---------------------------------------------------------------------------
// Problem constants
// ---------------------------------------------------------------------------
#define T_  1024
#define D_  768
#define H_  12
#define FF_ 3072
#define V_  8192
#define HD_ 64

// output layout: xt_new [T*D] | xe_new [T*D] | dict_weights [H*T*V] | loss [1]
#define OFF_XE   (T_*D_)
#define OFF_W    (2*T_*D_)
#define OFF_LOSS (2*T_*D_ + H_*T_*V_)

// ---------------------------------------------------------------------------
// Device scratch (allocation-free: __device__ globals)
// ---------------------------------------------------------------------------
__device__ __align__(16) float g_xnorm[T_*D_];
__device__ __align__(16) float g_qk[T_*2*D_];
__device__ __align__(16) float g_v[H_*T_*HD_];
__device__ __align__(16) float g_vT[H_*HD_*T_];
__device__ __align__(16) float g_scores[H_*T_*T_];          // 50 MB
__device__ __align__(16) float g_y[T_*D_];
__device__ __align__(16) float g_x2[T_*D_];
__device__ __align__(16) float g_h[T_*H_*FF_];              // 151 MB
__device__ __align__(16) float g_xpreP[4*T_*D_];            // proj split-K partials
__device__ __align__(16) float g_xhat[T_*D_];
__device__ __align__(16) float g_dsum[H_*T_*4];             // dict exp-sum partials
__device__ __align__(16) float g_reconP[2*T_*D_];           // recon v-split partials
__device__ __align__(16) float g_recon[T_*D_];
__device__ double g_lossPartial[256];

// ---------------------------------------------------------------------------
// Helpers
// ---------------------------------------------------------------------------
__device__ __forceinline__ float gelu_exact(float x) {
    return 0.5f * x * (1.0f + erff(x * 0.70710678118654752f));
}

__device__ __forceinline__ void cp_async16(void* s, const void* g) {
    unsigned sa = (unsigned)__cvta_generic_to_shared(s);
    asm volatile("cp.async.cg.shared.global [%0], [%1], 16;\n" :: "r"(sa), "l"(g));
}
__device__ __forceinline__ void cp_commit() {
    asm volatile("cp.async.commit_group;\n");
}
template<int N>
__device__ __forceinline__ void cp_wait() {
    asm volatile("cp.async.wait_group %0;\n" :: "n"(N));
}

__device__ __forceinline__ void mma_tf32(float* c, const unsigned* a, const unsigned* b) {
    asm volatile(
        "mma.sync.aligned.m16n8k8.row.col.f32.tf32.tf32.f32 "
        "{%0,%1,%2,%3}, {%4,%5,%6,%7}, {%8,%9}, {%0,%1,%2,%3};\n"
        : "+f"(c[0]), "+f"(c[1]), "+f"(c[2]), "+f"(c[3])
        : "r"(a[0]), "r"(a[1]), "r"(a[2]), "r"(a[3]), "r"(b[0]), "r"(b[1]));
}

// ---------------------------------------------------------------------------
// Tensor-core NT GEMM (tf32 mma.sync m16n8k8), cp.async 2-stage pipeline.
//   C[m,n] = alpha * sum_k A[m,k]*B[n,k]   (+bias, +gelu) ; batched over z
// nsplit>1: split-K — blockIdx.z = zb*nsplit+zs, K range [zs*klen,(zs+1)*klen),
//           C += zs*sCsplit (partial buffers, mode must be 0).
// ---------------------------------------------------------------------------
template<int BM, int BN, int BK, int WM, int WN, int THREADS>
__global__ void __launch_bounds__(THREADS)
gemm_tc(const float* __restrict__ A, const float* __restrict__ B,
        float* __restrict__ C, const float* __restrict__ bias,
        int K, int lda, int ldb, int ldc,
        long long sA, long long sB, long long sC, long long sBias,
        float alpha, int mode, int causal, int kcap, int swapxy,
        int nsplit, int klen, long long sCsplit)
{
    constexpr int NWN = BN / WN;          // warps along N
    constexpr int TM  = WM / 16;          // mma tiles per warp along M
    constexpr int TN  = WN / 8;           // mma tiles per warp along N
    constexpr int LK  = BK + 4;           // smem row stride (words) -> conflict-free
    constexpr int LA  = BM * (BK/4) / THREADS;
    constexpr int LB  = BN * (BK/4) / THREADS;

    const int bx = blockIdx.x, by = blockIdx.y;
    const int m0 = (swapxy ? bx : by) * BM;
    const int n0 = (swapxy ? by : bx) * BN;
    if (causal && n0 > m0 + BM - 1) return;

    __shared__ __align__(16) float As[2][BM][LK];
    __shared__ __align__(16) float Bs[2][BN][LK];

    int zb = blockIdx.z, koff = 0;
    if (nsplit > 1) {
        int zs = zb % nsplit;
        zb = zb / nsplit;
        koff = zs * klen;
        C += zs * sCsplit;
        K = klen;
    }
    A += zb * sA + koff;  B += zb * sB + koff;  C += zb * sC;
    if (mode >= 1) bias += zb * sBias;

    const int tid  = threadIdx.x;
    const int lane = tid & 31;
    const int warp = tid >> 5;
    const int gid  = lane >> 2;
    const int t4   = lane & 3;
    const int wm   = warp / NWN;
    const int wn   = warp % NWN;

    float acc[TM][TN][4];
    #pragma unroll
    for (int i = 0; i < TM; i++)
        #pragma unroll
        for (int j = 0; j < TN; j++) {
            acc[i][j][0] = 0.f; acc[i][j][1] = 0.f;
            acc[i][j][2] = 0.f; acc[i][j][3] = 0.f;
        }

    int Keff = K;
    if (kcap) { int ke = m0 + BM; if (ke < K) Keff = ke; }
    const int niter = Keff / BK;

    auto load_stage = [&](int st, int k0) {
        #pragma unroll
        for (int i = 0; i < LA; i++) {
            int l = tid + i * THREADS;
            int r = l / (BK/4), q = (l % (BK/4)) * 4;
            cp_async16(&As[st][r][q], A + (long long)(m0 + r) * lda + k0 + q);
        }
        #pragma unroll
        for (int i = 0; i < LB; i++) {
            int l = tid + i * THREADS;
            int r = l / (BK/4), q = (l % (BK/4)) * 4;
            cp_async16(&Bs[st][r][q], B + (long long)(n0 + r) * ldb + k0 + q);
        }
    };

    load_stage(0, 0);
    cp_commit();
    if (niter > 1) load_stage(1, BK);
    cp_commit();

    for (int it = 0; it < niter; it++) {
        cp_wait<1>();
        __syncthreads();

        const int st = it & 1;
        #pragma unroll
        for (int kk = 0; kk < BK; kk += 8) {
            unsigned a[TM][4], b[TN][2];
            #pragma unroll
            for (int i = 0; i < TM; i++) {
                int r = wm * WM + i * 16 + gid;
                a[i][0] = __float_as_uint(As[st][r    ][kk + t4]);
                a[i][1] = __float_as_uint(As[st][r + 8][kk + t4]);
                a[i][2] = __float_as_uint(As[st][r    ][kk + t4 + 4]);
                a[i][3] = __float_as_uint(As[st][r + 8][kk + t4 + 4]);
            }
            #pragma unroll
            for (int j = 0; j < TN; j++) {
                int c = wn * WN + j * 8 + gid;
                b[j][0] = __float_as_uint(Bs[st][c][kk + t4]);
                b[j][1] = __float_as_uint(Bs[st][c][kk + t4 + 4]);
            }
            #pragma unroll
            for (int i = 0; i < TM; i++)
                #pragma unroll
                for (int j = 0; j < TN; j++)
                    mma_tf32(acc[i][j], a[i], b[j]);
        }
        __syncthreads();

        if (it + 2 < niter) load_stage(st, (it + 2) * BK);
        cp_commit();
    }

    #pragma unroll
    for (int i = 0; i < TM; i++) {
        const int m = m0 + wm * WM + i * 16 + gid;
        #pragma unroll
        for (int j = 0; j < TN; j++) {
            const int n = n0 + wn * WN + j * 8 + t4 * 2;
            float c0 = acc[i][j][0] * alpha, c1 = acc[i][j][1] * alpha;
            float c2 = acc[i][j][2] * alpha, c3 = acc[i][j][3] * alpha;
            if (mode >= 1) {
                float b0 = bias[n], b1 = bias[n + 1];
                c0 += b0; c1 += b1; c2 += b0; c3 += b1;
            }
            if (mode == 2) {
                c0 = gelu_exact(c0); c1 = gelu_exact(c1);
                c2 = gelu_exact(c2); c3 = gelu_exact(c3);
            }
            *reinterpret_cast<float2*>(C + (long long)m       * ldc + n) = make_float2(c0, c1);
            *reinterpret_cast<float2*>(C + (long long)(m + 8) * ldc + n) = make_float2(c2, c3);
        }
    }
}

// ---------------------------------------------------------------------------
// Dict chain pass 1: partial exp-sums over a quarter of V.
// grid (T/32, H, 4), 128 threads.  dsum[(h*T+t)*4 + vs] = sum_{v in quarter} exp(logit)
// ---------------------------------------------------------------------------
#define DF_RB 32
#define DF_VC 64

__global__ void __launch_bounds__(128)
dict_pass1_kernel(const float* __restrict__ xhat, const float* __restrict__ emb,
                  float* __restrict__ dsum)
{
    const int h  = blockIdx.y;
    const int t0 = blockIdx.x * DF_RB;
    const int vs = blockIdx.z;
    const int vbase = vs * (V_ / 4);
    const int NCH = (V_ / 4) / DF_VC;     // 32 chunks

    __shared__ __align__(16) float sA[DF_RB][68];
    __shared__ __align__(16) float sE[2][DF_VC][68];
    __shared__ float sS[DF_RB];

    const int tid  = threadIdx.x;
    const int lane = tid & 31;
    const int warp = tid >> 5;
    const int gid  = lane >> 2;
    const int t4   = lane & 3;
    const int wm   = warp >> 1;
    const int wn   = warp & 1;

    #pragma unroll
    for (int i = 0; i < 4; i++) {
        int l = tid + i * 128;
        int r = l >> 4, q = (l & 15) * 4;
        *reinterpret_cast<float4*>(&sA[r][q]) =
            *reinterpret_cast<const float4*>(xhat + (long long)(t0 + r) * D_ + h * HD_ + q);
    }
    if (tid < DF_RB) sS[tid] = 0.f;
    __syncthreads();

    const int r0 = wm * 16 + gid;
    unsigned afr[8][4];
    #pragma unroll
    for (int ks = 0; ks < 8; ks++) {
        int kk = ks * 8;
        afr[ks][0] = __float_as_uint(sA[r0    ][kk + t4]);
        afr[ks][1] = __float_as_uint(sA[r0 + 8][kk + t4]);
        afr[ks][2] = __float_as_uint(sA[r0    ][kk + t4 + 4]);
        afr[ks][3] = __float_as_uint(sA[r0 + 8][kk + t4 + 4]);
    }

    const float* Eh = emb + (long long)h * V_ * HD_;
    auto loadE = [&](int st, int v0) {
        #pragma unroll
        for (int i = 0; i < 8; i++) {
            int l = tid + i * 128;
            int r = l >> 4, q = (l & 15) * 4;
            cp_async16(&sE[st][r][q], Eh + (long long)(v0 + r) * HD_ + q);
        }
    };

    float se0 = 0.f, se1 = 0.f;
    loadE(0, vbase);
    cp_commit();
    for (int c = 0; c < NCH; c++) {
        if (c + 1 < NCH) loadE((c + 1) & 1, vbase + (c + 1) * DF_VC);
        cp_commit();
        cp_wait<1>();
        __syncthreads();
        const int st = c & 1;

        #pragma unroll
        for (int j = 0; j < 4; j++) {
            float acc[4] = {0.f, 0.f, 0.f, 0.f};
            #pragma unroll
            for (int ks = 0; ks < 8; ks++) {
                int kk = ks * 8;
                int v = wn * 32 + j * 8 + gid;
                unsigned b[2];
                b[0] = __float_as_uint(sE[st][v][kk + t4]);
                b[1] = __float_as_uint(sE[st][v][kk + t4 + 4]);
                mma_tf32(acc, afr[ks], b);
            }
            se0 += __expf(acc[0]) + __expf(acc[1]);
            se1 += __expf(acc[2]) + __expf(acc[3]);
        }
        __syncthreads();
    }
    se0 += __shfl_xor_sync(0xffffffffu, se0, 1);
    se0 += __shfl_xor_sync(0xffffffffu, se0, 2);
    se1 += __shfl_xor_sync(0xffffffffu, se1, 1);
    se1 += __shfl_xor_sync(0xffffffffu, se1, 2);
    if (t4 == 0) {
        atomicAdd(&sS[r0], se0);
        atomicAdd(&sS[r0 + 8], se1);
    }
    __syncthreads();
    if (tid < DF_RB)
        dsum[((long long)h * T_ + t0 + tid) * 4 + vs] = sS[tid];
}

// ---------------------------------------------------------------------------
// Dict chain pass 2: weights out + recon partial over half of V.
// grid (T/32, H, 2), 128 threads. reconP[vs][t][h*64+e]
// ---------------------------------------------------------------------------
__global__ void __launch_bounds__(128)
dict_pass2_kernel(const float* __restrict__ xhat, const float* __restrict__ emb,
                  const float* __restrict__ dsum, float* __restrict__ wout,
                  float* __restrict__ reconP)
{
    const int h  = blockIdx.y;
    const int t0 = blockIdx.x * DF_RB;
    const int vs = blockIdx.z;
    const int vbase = vs * (V_ / 2);
    const int NCH = (V_ / 2) / DF_VC;     // 64 chunks

    __shared__ __align__(16) float sA[DF_RB][68];
    __shared__ __align__(16) float sW[DF_RB][68];
    __shared__ __align__(16) float sE[2][DF_VC][68];
    __shared__ float sInv[DF_RB];

    const int tid  = threadIdx.x;
    const int lane = tid & 31;
    const int warp = tid >> 5;
    const int gid  = lane >> 2;
    const int t4   = lane & 3;
    const int wm   = warp >> 1;
    const int wn   = warp & 1;

    #pragma unroll
    for (int i = 0; i < 4; i++) {
        int l = tid + i * 128;
        int r = l >> 4, q = (l & 15) * 4;
        *reinterpret_cast<float4*>(&sA[r][q]) =
            *reinterpret_cast<const float4*>(xhat + (long long)(t0 + r) * D_ + h * HD_ + q);
    }
    if (tid < DF_RB) {
        const float* ds = dsum + ((long long)h * T_ + t0 + tid) * 4;
        sInv[tid] = 1.f / (ds[0] + ds[1] + ds[2] + ds[3]);
    }
    __syncthreads();

    const int r0 = wm * 16 + gid;
    unsigned afr[8][4];
    #pragma unroll
    for (int ks = 0; ks < 8; ks++) {
        int kk = ks * 8;
        afr[ks][0] = __float_as_uint(sA[r0    ][kk + t4]);
        afr[ks][1] = __float_as_uint(sA[r0 + 8][kk + t4]);
        afr[ks][2] = __float_as_uint(sA[r0    ][kk + t4 + 4]);
        afr[ks][3] = __float_as_uint(sA[r0 + 8][kk + t4 + 4]);
    }
    const float inv0 = sInv[r0], inv1 = sInv[r0 + 8];

    const float* Eh = emb + (long long)h * V_ * HD_;
    auto loadE = [&](int st, int v0) {
        #pragma unroll
        for (int i = 0; i < 8; i++) {
            int l = tid + i * 128;
            int r = l >> 4, q = (l & 15) * 4;
            cp_async16(&sE[st][r][q], Eh + (long long)(v0 + r) * HD_ + q);
        }
    };

    float racc[4][4];
    #pragma unroll
    for (int j = 0; j < 4; j++) {
        racc[j][0] = 0.f; racc[j][1] = 0.f; racc[j][2] = 0.f; racc[j][3] = 0.f;
    }

    loadE(0, vbase);
    cp_commit();
    for (int c = 0; c < NCH; c++) {
        if (c + 1 < NCH) loadE((c + 1) & 1, vbase + (c + 1) * DF_VC);
        cp_commit();
        cp_wait<1>();
        __syncthreads();
        const int st = c & 1;

        #pragma unroll
        for (int j = 0; j < 4; j++) {
            float acc[4] = {0.f, 0.f, 0.f, 0.f};
            #pragma unroll
            for (int ks = 0; ks < 8; ks++) {
                int kk = ks * 8;
                int v = wn * 32 + j * 8 + gid;
                unsigned b[2];
                b[0] = __float_as_uint(sE[st][v][kk + t4]);
                b[1] = __float_as_uint(sE[st][v][kk + t4 + 4]);
                mma_tf32(acc, afr[ks], b);
            }
            int vl = wn * 32 + j * 8 + t4 * 2;
            float w0 = __expf(acc[0]) * inv0;
            float w1 = __expf(acc[1]) * inv0;
            float w2 = __expf(acc[2]) * inv1;
            float w3 = __expf(acc[3]) * inv1;
            long long vg = (long long)vbase + c * DF_VC + vl;
            *reinterpret_cast<float2*>(wout + ((long long)(h*T_ + t0 + r0    ))*V_ + vg) = make_float2(w0, w1);
            *reinterpret_cast<float2*>(wout + ((long long)(h*T_ + t0 + r0 + 8))*V_ + vg) = make_float2(w2, w3);
            sW[r0    ][vl] = w0;  sW[r0    ][vl + 1] = w1;
            sW[r0 + 8][vl] = w2;  sW[r0 + 8][vl + 1] = w3;
        }
        __syncthreads();

        #pragma unroll
        for (int ks = 0; ks < 8; ks++) {
            int kk = ks * 8;
            unsigned aw[4];
            aw[0] = __float_as_uint(sW[r0    ][kk + t4]);
            aw[1] = __float_as_uint(sW[r0 + 8][kk + t4]);
            aw[2] = __float_as_uint(sW[r0    ][kk + t4 + 4]);
            aw[3] = __float_as_uint(sW[r0 + 8][kk + t4 + 4]);
            #pragma unroll
            for (int j = 0; j < 4; j++) {
                int e = wn * 32 + j * 8 + gid;
                unsigned b[2];
                b[0] = __float_as_uint(sE[st][kk + t4    ][e]);
                b[1] = __float_as_uint(sE[st][kk + t4 + 4][e]);
                mma_tf32(racc[j], aw, b);
            }
        }
        __syncthreads();
    }

    float* rp = reconP + (long long)vs * T_ * D_;
    #pragma unroll
    for (int j = 0; j < 4; j++) {
        int e = h * HD_ + wn * 32 + j * 8 + t4 * 2;
        *reinterpret_cast<float2*>(rp + (long long)(t0 + r0    ) * D_ + e) =
            make_float2(racc[j][0], racc[j][1]);
        *reinterpret_cast<float2*>(rp + (long long)(t0 + r0 + 8) * D_ + e) =
            make_float2(racc[j][2], racc[j][3]);
    }
}

// ---------------------------------------------------------------------------
// LayerNorm over D=768 of (a + b)
// ---------------------------------------------------------------------------
__global__ void ln2in_kernel(const float* __restrict__ a, const float* __restrict__ b,
                             const float* __restrict__ w, const float* __restrict__ bb,
                             float* __restrict__ out)
{
    const int t = blockIdx.x;
    const int tid = threadIdx.x;
    const float* pa = a + (long long)t * D_;
    const float* pb = b + (long long)t * D_;
    float x[3];
    float s = 0.f, ss = 0.f;
    #pragma unroll
    for (int i = 0; i < 3; i++) {
        int d = tid + i*256;
        float v = pa[d] + pb[d];
        x[i] = v; s += v; ss += v*v;
    }
    #pragma unroll
    for (int o = 16; o; o >>= 1) {
        s  += __shfl_xor_sync(0xffffffffu, s, o);
        ss += __shfl_xor_sync(0xffffffffu, ss, o);
    }
    __shared__ float rs[8], rss[8];
    __shared__ float s_mu, s_inv;
    if ((tid & 31) == 0) { rs[tid >> 5] = s; rss[tid >> 5] = ss; }
    __syncthreads();
    if (tid == 0) {
        float S = 0.f, SS = 0.f;
        #pragma unroll
        for (int i = 0; i < 8; i++) { S += rs[i]; SS += rss[i]; }
        float mu  = S * (1.f / D_);
        float var = SS * (1.f / D_) - mu*mu;
        s_mu = mu;
        s_inv = rsqrtf(var + 1e-5f);
    }
    __syncthreads();
    float mu = s_mu, inv = s_inv;
    #pragma unroll
    for (int i = 0; i < 3; i++) {
        int d = tid + i*256;
        out[(long long)t*D_ + d] = (x[i] - mu) * inv * w[d] + bb[d];
    }
}

// v[h,t,d] = sum_j v_fact[h,j] * xt[t, j*64+d]
__global__ void vmix_kernel(const float* __restrict__ xt, const float* __restrict__ vf,
                            float* __restrict__ v)
{
    int idx = blockIdx.x * 256 + threadIdx.x;
    int d = idx & (HD_-1);
    int t = (idx >> 6) & (T_-1);
    int h = idx >> 16;
    float s = 0.f;
    #pragma unroll
    for (int j = 0; j < H_; j++)
        s += vf[h*H_ + j] * xt[(long long)t*D_ + j*HD_ + d];
    v[idx] = s;
}

// batched transpose in[b][R][C] -> out[b][C][R]
__global__ void transpose_kernel(const float* __restrict__ in, float* __restrict__ out,
                                 int R, int Cc)
{
    __shared__ float tile[32][33];
    const long long boff = (long long)blockIdx.z * R * Cc;
    in += boff; out += boff;
    int c0 = blockIdx.x * 32, r0 = blockIdx.y * 32;
    int x = threadIdx.x, y = threadIdx.y;
    #pragma unroll
    for (int i = 0; i < 32; i += 8)
        tile[y+i][x] = in[(long long)(r0 + y + i) * Cc + c0 + x];
    __syncthreads();
    #pragma unroll
    for (int i = 0; i < 32; i += 8)
        out[(long long)(c0 + y + i) * R + r0 + x] = tile[x][y+i];
}

// causal ALiBi softmax, in place on scores[h][i][:]
__global__ void attn_softmax_kernel(float* __restrict__ sc)
{
    const int bx = blockIdx.x;
    const int i = bx & (T_-1);
    const int h = bx >> 10;
    const float slope = (h < 8) ? exp2f(-(float)(h+1)) : exp2f(-0.5f * (float)(h-7));
    float* row = sc + ((long long)h*T_ + i) * T_;
    const int n = i + 1;
    const int tid = threadIdx.x;
    __shared__ float sh[8];

    float m = -3.4e38f;
    for (int j = tid; j < n; j += 256)
        m = fmaxf(m, row[j] + slope * (float)(j - i));
    #pragma unroll
    for (int o = 16; o; o >>= 1) m = fmaxf(m, __shfl_xor_sync(0xffffffffu, m, o));
    if ((tid & 31) == 0) sh[tid >> 5] = m;
    __syncthreads();
    float M = sh[0];
    #pragma unroll
    for (int w = 1; w < 8; w++) M = fmaxf(M, sh[w]);
    __syncthreads();

    float s = 0.f;
    for (int j = tid; j < n; j += 256) {
        float e = expf(row[j] + slope * (float)(j - i) - M);
        row[j] = e; s += e;
    }
    #pragma unroll
    for (int o = 16; o; o >>= 1) s += __shfl_xor_sync(0xffffffffu, s, o);
    if ((tid & 31) == 0) sh[tid >> 5] = s;
    __syncthreads();
    float S = 0.f;
    #pragma unroll
    for (int w = 0; w < 8; w++) S += sh[w];
    float inv = 1.f / S;
    for (int j = tid; j < n; j += 256) row[j] *= inv;
    for (int j = n + tid; j < T_; j += 256) row[j] = 0.f;
}

// xt_new[t, i*64+d] = xt + sum_j out_fact[i,j] * y[t, j*64+d]
__global__ void outmix_kernel(const float* __restrict__ xt, const float* __restrict__ of,
                              const float* __restrict__ y, float* __restrict__ o)
{
    int idx = blockIdx.x * 256 + threadIdx.x;
    int d = idx & (HD_-1);
    int i = (idx >> 6) % H_;
    int t = idx / D_;
    float s = 0.f;
    #pragma unroll
    for (int j = 0; j < H_; j++)
        s += of[i*H_ + j] * y[(long long)t*D_ + j*HD_ + d];
    o[idx] = xt[idx] + s;
}

// per-(h,t) LayerNorm over HD=64; input = sum of 4 split-K partials + proj bias
__global__ void dln_kernel(const float* __restrict__ xpP, const float* __restrict__ pb,
                           const float* __restrict__ w, const float* __restrict__ b,
                           float* __restrict__ xh)
{
    int bx = blockIdx.x;
    int t = bx & (T_-1);
    int h = bx >> 10;
    int lane = threadIdx.x;
    const long long base = (long long)t*D_ + h*HD_;
    const long long TD = (long long)T_*D_;
    float v0 = xpP[base + lane]      + xpP[base + lane + TD]
             + xpP[base + lane + 2*TD] + xpP[base + lane + 3*TD] + pb[h*HD_ + lane];
    float v1 = xpP[base + lane + 32] + xpP[base + lane + 32 + TD]
             + xpP[base + lane + 32 + 2*TD] + xpP[base + lane + 32 + 3*TD] + pb[h*HD_ + lane + 32];
    float s = v0 + v1, ss = v0*v0 + v1*v1;
    #pragma unroll
    for (int o = 16; o; o >>= 1) {
        s  += __shfl_xor_sync(0xffffffffu, s, o);
        ss += __shfl_xor_sync(0xffffffffu, ss, o);
    }
    float mu  = s * (1.f / HD_);
    float var = ss * (1.f / HD_) - mu*mu;
    float inv = rsqrtf(var + 1e-5f);
    float* q = xh + base;
    q[lane]      = (v0 - mu) * inv * w[h*HD_ + lane]      + b[h*HD_ + lane];
    q[lane + 32] = (v1 - mu) * inv * w[h*HD_ + lane + 32] + b[h*HD_ + lane + 32];
}

// xe_new = xe + reconP0 + reconP1 ; also store combined recon for the loss
__global__ void add2_kernel(const float* __restrict__ xe, const float* __restrict__ rp,
                            float* __restrict__ oxe, float* __restrict__ recon)
{
    int idx = blockIdx.x * 256 + threadIdx.x;
    float r = rp[idx] + rp[idx + T_*D_];
    recon[idx] = r;
    oxe[idx] = xe[idx] + r;
}

__global__ void loss_partial_kernel(const float* __restrict__ a, const float* __restrict__ b)
{
    double s = 0.0;
    for (int idx = blockIdx.x*256 + threadIdx.x; idx < T_*D_; idx += 256*256) {
        float d = a[idx] - b[idx];
        s += (double)d * (double)d;
    }
    __shared__ double sh[256];
    sh[threadIdx.x] = s;
    __syncthreads();
    for (int o = 128; o; o >>= 1) {
        if (threadIdx.x < o) sh[threadIdx.x] += sh[threadIdx.x + o];
        __syncthreads();
    }
    if (threadIdx.x == 0) g_lossPartial[blockIdx.x] = sh[0];
}

__global__ void loss_final_kernel(float* __restrict__ out)
{
    __shared__ double sh[256];
    sh[threadIdx.x] = g_lossPartial[threadIdx.x];
    __syncthreads();
    for (int o = 128; o; o >>= 1) {
        if (threadIdx.x < o) sh[threadIdx.x] += sh[threadIdx.x + o];
        __syncthreads();
    }
    if (threadIdx.x == 0) out[0] = (float)(sh[0] / (double)(T_*D_));
}

// ---------------------------------------------------------------------------
// Host launcher
// ---------------------------------------------------------------------------
extern "C" void kernel_launch(void* const* d_in, const int* in_sizes, int n_in,
                              void* d_out, int out_size)
{
    (void)in_sizes; (void)n_in; (void)out_size;
    const float* xt       = (const float*)d_in[0];
    const float* xe       = (const float*)d_in[1];
    const float* ln1_w    = (const float*)d_in[2];
    const float* ln1_b    = (const float*)d_in[3];
    const float* qk_w     = (const float*)d_in[4];
    const float* qk_b     = (const float*)d_in[5];
    const float* v_fact   = (const float*)d_in[6];
    const float* out_fact = (const float*)d_in[7];
    const float* ln2_w    = (const float*)d_in[8];
    const float* ln2_b    = (const float*)d_in[9];
    const float* fc_w     = (const float*)d_in[10];
    const float* fc_b     = (const float*)d_in[11];
    const float* proj_w   = (const float*)d_in[12];
    const float* proj_b   = (const float*)d_in[13];
    const float* dln_w    = (const float*)d_in[14];
    const float* dln_b    = (const float*)d_in[15];
    const float* dict_emb = (const float*)d_in[16];

    float* out    = (float*)d_out;
    float* o_xt   = out;
    float* o_xe   = out + OFF_XE;
    float* o_w    = out + OFF_W;
    float* o_loss = out + OFF_LOSS;

    float *p_xnorm, *p_qk, *p_v, *p_vT, *p_sc, *p_y, *p_x2, *p_h,
          *p_xpreP, *p_xhat, *p_dsum, *p_reconP, *p_recon;
    cudaGetSymbolAddress((void**)&p_xnorm,  g_xnorm);
    cudaGetSymbolAddress((void**)&p_qk,     g_qk);
    cudaGetSymbolAddress((void**)&p_v,      g_v);
    cudaGetSymbolAddress((void**)&p_vT,     g_vT);
    cudaGetSymbolAddress((void**)&p_sc,     g_scores);
    cudaGetSymbolAddress((void**)&p_y,      g_y);
    cudaGetSymbolAddress((void**)&p_x2,     g_x2);
    cudaGetSymbolAddress((void**)&p_h,      g_h);
    cudaGetSymbolAddress((void**)&p_xpreP,  g_xpreP);
    cudaGetSymbolAddress((void**)&p_xhat,   g_xhat);
    cudaGetSymbolAddress((void**)&p_dsum,   g_dsum);
    cudaGetSymbolAddress((void**)&p_reconP, g_reconP);
    cudaGetSymbolAddress((void**)&p_recon,  g_recon);

    // 1) x_norm = LN(xt + xe)
    ln2in_kernel<<<T_, 256>>>(xt, xe, ln1_w, ln1_b, p_xnorm);

    // 2) qk = x_norm @ qk_w^T + qk_b       [T, 1536]
    gemm_tc<128,128,16,64,32,256><<<dim3(2*D_/128, T_/128, 1), 256>>>(
        p_xnorm, qk_w, p_qk, qk_b, D_, D_, D_, 2*D_, 0,0,0,0, 1.f, 1, 0, 0, 0, 1, 0, 0);

    // 3) v[h,t,d] then vT[h,d,t]
    vmix_kernel<<<H_*T_*HD_/256, 256>>>(xt, v_fact, p_v);
    transpose_kernel<<<dim3(HD_/32, T_/32, H_), dim3(32,8)>>>(p_v, p_vT, T_, HD_);

    // 4) scores[h] = 0.125 * q[h] @ k[h]^T   (causal blocks only)
    gemm_tc<128,128,16,64,32,256><<<dim3(T_/128, T_/128, H_), 256>>>(
        p_qk, p_qk + D_, p_sc, nullptr, HD_, 2*D_, 2*D_, T_,
        64, 64, (long long)T_*T_, 0, 0.125f, 0, 1, 0, 0, 1, 0, 0);

    // 5) causal ALiBi softmax in place
    attn_softmax_kernel<<<H_*T_, 256>>>(p_sc);

    // 6) y[h] = probs[h] @ v[h]  (K capped at diagonal), 256 threads
    gemm_tc<64,64,16,16,32,256><<<dim3(HD_/64, T_/64, H_), 256>>>(
        p_sc, p_vT, p_y, nullptr, T_, T_, T_, D_,
        (long long)T_*T_, (long long)HD_*T_, 64, 0, 1.f, 0, 0, 1, 0, 1, 0, 0);

    // 7) xt_new = xt + out_fact-mix(y)
    outmix_kernel<<<T_*D_/256, 256>>>(xt, out_fact, p_y, o_xt);

    // 8) x2 = LN(xt_new + xe)
    ln2in_kernel<<<T_, 256>>>(o_xt, xe, ln2_w, ln2_b, p_x2);

    // 9) h = gelu(x2 @ fc_w^T + fc_b)   [T, 36864]   -- dominant GEMM
    gemm_tc<128,128,16,64,32,256><<<dim3(T_/128, H_*FF_/128, 1), 256>>>(
        p_x2, fc_w, p_h, fc_b, D_, D_, D_, H_*FF_, 0,0,0,0, 1.f, 2, 0, 0, 1, 1, 0, 0);

    // 10) proj split-K=4: xpreP[ks] = h[h][k-range] @ proj_w[h][k-range]^T
    gemm_tc<64,64,16,16,32,256><<<dim3(1, T_/64, H_*4), 256>>>(
        p_h, proj_w, p_xpreP, nullptr, FF_, H_*FF_, FF_, D_,
        FF_, (long long)HD_*FF_, 64, 0, 1.f, 0, 0, 0, 0, 4, FF_/4, (long long)T_*D_);

    // 11) x_hat = per-head LN(sum of partials + proj_b)
    dln_kernel<<<H_*T_, 32>>>(p_xpreP, proj_b, dln_w, dln_b, p_xhat);

    // 12) dict pass 1: partial exp-sums (V split 4-way)
    dict_pass1_kernel<<<dim3(T_/DF_RB, H_, 4), 128>>>(p_xhat, dict_emb, p_dsum);

    // 13) dict pass 2: weights + recon partials (V split 2-way)
    dict_pass2_kernel<<<dim3(T_/DF_RB, H_, 2), 128>>>(p_xhat, dict_emb, p_dsum, o_w, p_reconP);

    // 14) xe_new = xe + recon ; store combined recon
    add2_kernel<<<T_*D_/256, 256>>>(xe, p_reconP, o_xe, p_recon);

    // 15) dict_loss = mean((x_hat - x_recon)^2)
    loss_partial_kernel<<<256, 256>>>(p_xhat, p_recon);
    loss_final_kernel<<<1, 256>>>(o_loss);
}

// round 15
// speedup vs baseline: 1.2045x; 1.0682x over previous
#include <cuda_runtime.h>
#include <math.h>

// ---------------------------------------------------------------------------
// Problem constants
// ---------------------------------------------------------------------------
#define T_  1024
#define D_  768
#define H_  12
#define FF_ 3072
#define V_  8192
#define HD_ 64

// output layout: xt_new [T*D] | xe_new [T*D] | dict_weights [H*T*V] | loss [1]
#define OFF_XE   (T_*D_)
#define OFF_W    (2*T_*D_)
#define OFF_LOSS (2*T_*D_ + H_*T_*V_)

// ---------------------------------------------------------------------------
// Device scratch (allocation-free: __device__ globals)
// ---------------------------------------------------------------------------
__device__ __align__(16) float g_xnorm[T_*D_];
__device__ __align__(16) float g_qk[T_*2*D_];
__device__ __align__(16) float g_v[H_*T_*HD_];
__device__ __align__(16) float g_y[T_*D_];
__device__ __align__(16) float g_x2[T_*D_];
__device__ __align__(16) float g_h[T_*H_*FF_];              // 151 MB
__device__ __align__(16) float g_xpreP[4*T_*D_];            // proj split-K partials
__device__ __align__(16) float g_xhat[T_*D_];
__device__ __align__(16) float g_dsum[H_*T_*4];             // dict exp-sum partials
__device__ __align__(16) float g_reconP[2*T_*D_];           // recon v-split partials
__device__ __align__(16) float g_recon[T_*D_];
__device__ double g_lossPartial[256];

// ---------------------------------------------------------------------------
// Helpers
// ---------------------------------------------------------------------------
__device__ __forceinline__ float gelu_exact(float x) {
    return 0.5f * x * (1.0f + erff(x * 0.70710678118654752f));
}

__device__ __forceinline__ void cp_async16(void* s, const void* g) {
    unsigned sa = (unsigned)__cvta_generic_to_shared(s);
    asm volatile("cp.async.cg.shared.global [%0], [%1], 16;\n" :: "r"(sa), "l"(g));
}
__device__ __forceinline__ void cp_commit() {
    asm volatile("cp.async.commit_group;\n");
}
template<int N>
__device__ __forceinline__ void cp_wait() {
    asm volatile("cp.async.wait_group %0;\n" :: "n"(N));
}

__device__ __forceinline__ void mma_tf32(float* c, const unsigned* a, const unsigned* b) {
    asm volatile(
        "mma.sync.aligned.m16n8k8.row.col.f32.tf32.tf32.f32 "
        "{%0,%1,%2,%3}, {%4,%5,%6,%7}, {%8,%9}, {%0,%1,%2,%3};\n"
        : "+f"(c[0]), "+f"(c[1]), "+f"(c[2]), "+f"(c[3])
        : "r"(a[0]), "r"(a[1]), "r"(a[2]), "r"(a[3]), "r"(b[0]), "r"(b[1]));
}

// ---------------------------------------------------------------------------
// Tensor-core NT GEMM (tf32 mma.sync m16n8k8), cp.async 2-stage pipeline.
//   C[m,n] = alpha * sum_k A[m,k]*B[n,k]   (+bias, +gelu) ; batched over z
// nsplit>1: split-K — blockIdx.z = zb*nsplit+zs, K range [zs*klen,(zs+1)*klen),
//           C += zs*sCsplit (partial buffers, mode must be 0).
// ---------------------------------------------------------------------------
template<int BM, int BN, int BK, int WM, int WN, int THREADS>
__global__ void __launch_bounds__(THREADS)
gemm_tc(const float* __restrict__ A, const float* __restrict__ B,
        float* __restrict__ C, const float* __restrict__ bias,
        int K, int lda, int ldb, int ldc,
        long long sA, long long sB, long long sC, long long sBias,
        float alpha, int mode, int causal, int kcap, int swapxy,
        int nsplit, int klen, long long sCsplit)
{
    constexpr int NWN = BN / WN;          // warps along N
    constexpr int TM  = WM / 16;          // mma tiles per warp along M
    constexpr int TN  = WN / 8;           // mma tiles per warp along N
    constexpr int LK  = BK + 4;           // smem row stride (words) -> conflict-free
    constexpr int LA  = BM * (BK/4) / THREADS;
    constexpr int LB  = BN * (BK/4) / THREADS;

    const int bx = blockIdx.x, by = blockIdx.y;
    const int m0 = (swapxy ? bx : by) * BM;
    const int n0 = (swapxy ? by : bx) * BN;
    if (causal && n0 > m0 + BM - 1) return;

    __shared__ __align__(16) float As[2][BM][LK];
    __shared__ __align__(16) float Bs[2][BN][LK];

    int zb = blockIdx.z, koff = 0;
    if (nsplit > 1) {
        int zs = zb % nsplit;
        zb = zb / nsplit;
        koff = zs * klen;
        C += zs * sCsplit;
        K = klen;
    }
    A += zb * sA + koff;  B += zb * sB + koff;  C += zb * sC;
    if (mode >= 1) bias += zb * sBias;

    const int tid  = threadIdx.x;
    const int lane = tid & 31;
    const int warp = tid >> 5;
    const int gid  = lane >> 2;
    const int t4   = lane & 3;
    const int wm   = warp / NWN;
    const int wn   = warp % NWN;

    float acc[TM][TN][4];
    #pragma unroll
    for (int i = 0; i < TM; i++)
        #pragma unroll
        for (int j = 0; j < TN; j++) {
            acc[i][j][0] = 0.f; acc[i][j][1] = 0.f;
            acc[i][j][2] = 0.f; acc[i][j][3] = 0.f;
        }

    int Keff = K;
    if (kcap) { int ke = m0 + BM; if (ke < K) Keff = ke; }
    const int niter = Keff / BK;

    auto load_stage = [&](int st, int k0) {
        #pragma unroll
        for (int i = 0; i < LA; i++) {
            int l = tid + i * THREADS;
            int r = l / (BK/4), q = (l % (BK/4)) * 4;
            cp_async16(&As[st][r][q], A + (long long)(m0 + r) * lda + k0 + q);
        }
        #pragma unroll
        for (int i = 0; i < LB; i++) {
            int l = tid + i * THREADS;
            int r = l / (BK/4), q = (l % (BK/4)) * 4;
            cp_async16(&Bs[st][r][q], B + (long long)(n0 + r) * ldb + k0 + q);
        }
    };

    load_stage(0, 0);
    cp_commit();
    if (niter > 1) load_stage(1, BK);
    cp_commit();

    for (int it = 0; it < niter; it++) {
        cp_wait<1>();
        __syncthreads();

        const int st = it & 1;
        #pragma unroll
        for (int kk = 0; kk < BK; kk += 8) {
            unsigned a[TM][4], b[TN][2];
            #pragma unroll
            for (int i = 0; i < TM; i++) {
                int r = wm * WM + i * 16 + gid;
                a[i][0] = __float_as_uint(As[st][r    ][kk + t4]);
                a[i][1] = __float_as_uint(As[st][r + 8][kk + t4]);
                a[i][2] = __float_as_uint(As[st][r    ][kk + t4 + 4]);
                a[i][3] = __float_as_uint(As[st][r + 8][kk + t4 + 4]);
            }
            #pragma unroll
            for (int j = 0; j < TN; j++) {
                int c = wn * WN + j * 8 + gid;
                b[j][0] = __float_as_uint(Bs[st][c][kk + t4]);
                b[j][1] = __float_as_uint(Bs[st][c][kk + t4 + 4]);
            }
            #pragma unroll
            for (int i = 0; i < TM; i++)
                #pragma unroll
                for (int j = 0; j < TN; j++)
                    mma_tf32(acc[i][j], a[i], b[j]);
        }
        __syncthreads();

        if (it + 2 < niter) load_stage(st, (it + 2) * BK);
        cp_commit();
    }

    #pragma unroll
    for (int i = 0; i < TM; i++) {
        const int m = m0 + wm * WM + i * 16 + gid;
        #pragma unroll
        for (int j = 0; j < TN; j++) {
            const int n = n0 + wn * WN + j * 8 + t4 * 2;
            float c0 = acc[i][j][0] * alpha, c1 = acc[i][j][1] * alpha;
            float c2 = acc[i][j][2] * alpha, c3 = acc[i][j][3] * alpha;
            if (mode >= 1) {
                float b0 = bias[n], b1 = bias[n + 1];
                c0 += b0; c1 += b1; c2 += b0; c3 += b1;
            }
            if (mode == 2) {
                c0 = gelu_exact(c0); c1 = gelu_exact(c1);
                c2 = gelu_exact(c2); c3 = gelu_exact(c3);
            }
            *reinterpret_cast<float2*>(C + (long long)m       * ldc + n) = make_float2(c0, c1);
            *reinterpret_cast<float2*>(C + (long long)(m + 8) * ldc + n) = make_float2(c2, c3);
        }
    }
}

// ---------------------------------------------------------------------------
// Fused flash attention: scores -> ALiBi-causal softmax -> @V, one kernel.
// Block: 32 q-rows x 1 head, 128 threads (4 warps: wm=warp>>1 rows, wn=warp&1).
// grid (T/32, H) = 384 CTAs, smem ~43.6KB -> 5 CTAs/SM.
// Max-free softmax: logits = 0.125*q.k (sigma~0.3) + ALiBi bias <= 0 -> exp
// never overflows; underflow -> true-zero probs.
// sQP holds Q during fragment preload, then is reused as the P tile.
// ---------------------------------------------------------------------------
#define FA_RB 32
#define FA_KC 64

__global__ void __launch_bounds__(128)
flash_attn_kernel(const float* __restrict__ qk,   // [T][2D] (q | k)
                  const float* __restrict__ v,    // [H][T][64]
                  float* __restrict__ y)          // [T][D]
{
    const int h  = blockIdx.y;
    const int t0 = blockIdx.x * FA_RB;
    const float slope = (h < 8) ? exp2f(-(float)(h+1)) : exp2f(-0.5f * (float)(h-7));

    __shared__ __align__(16) float sQP[FA_RB][68];
    __shared__ __align__(16) float sK[FA_KC][68];
    __shared__ __align__(16) float sV[FA_KC][68];
    __shared__ float sL[FA_RB];

    const int tid  = threadIdx.x;
    const int lane = tid & 31;
    const int warp = tid >> 5;
    const int gid  = lane >> 2;
    const int t4   = lane & 3;
    const int wm   = warp >> 1;
    const int wn   = warp & 1;

    // load Q tile [32 x 64]
    #pragma unroll
    for (int i = 0; i < 4; i++) {
        int l = tid + i * 128;
        int r = l >> 4, q = (l & 15) * 4;
        *reinterpret_cast<float4*>(&sQP[r][q]) =
            *reinterpret_cast<const float4*>(qk + (long long)(t0 + r) * (2*D_) + h * HD_ + q);
    }
    if (tid < FA_RB) sL[tid] = 0.f;
    __syncthreads();

    const int r0 = wm * 16 + gid;
    unsigned afr[8][4];
    #pragma unroll
    for (int ks = 0; ks < 8; ks++) {
        int kk = ks * 8;
        afr[ks][0] = __float_as_uint(sQP[r0    ][kk + t4]);
        afr[ks][1] = __float_as_uint(sQP[r0 + 8][kk + t4]);
        afr[ks][2] = __float_as_uint(sQP[r0    ][kk + t4 + 4]);
        afr[ks][3] = __float_as_uint(sQP[r0 + 8][kk + t4 + 4]);
    }
    __syncthreads();   // sQP free -> becomes P tile

    float yacc[4][4];
    #pragma unroll
    for (int j = 0; j < 4; j++) {
        yacc[j][0] = 0.f; yacc[j][1] = 0.f; yacc[j][2] = 0.f; yacc[j][3] = 0.f;
    }
    float l0 = 0.f, l1 = 0.f;
    const int i0 = t0 + r0;
    const int nch = t0 / FA_KC + 1;

    for (int c = 0; c < nch; c++) {
        // load K,V chunk [64 x 64]
        #pragma unroll
        for (int i = 0; i < 8; i++) {
            int l = tid + i * 128;
            int r = l >> 4, q = (l & 15) * 4;
            cp_async16(&sK[r][q], qk + (long long)(c*FA_KC + r) * (2*D_) + D_ + h * HD_ + q);
            cp_async16(&sV[r][q], v + ((long long)h * T_ + c*FA_KC + r) * HD_ + q);
        }
        cp_commit();
        cp_wait<0>();
        __syncthreads();

        // S = Q @ K^T, then masked exp -> P into sQP
        #pragma unroll
        for (int j = 0; j < 4; j++) {
            float acc[4] = {0.f, 0.f, 0.f, 0.f};
            #pragma unroll
            for (int ks = 0; ks < 8; ks++) {
                int kk = ks * 8;
                int vv = wn * 32 + j * 8 + gid;
                unsigned b[2];
                b[0] = __float_as_uint(sK[vv][kk + t4]);
                b[1] = __float_as_uint(sK[vv][kk + t4 + 4]);
                mma_tf32(acc, afr[ks], b);
            }
            int jl = wn * 32 + j * 8 + t4 * 2;
            int jj = c * FA_KC + jl;
            float p0 = (jj     <= i0    ) ? __expf(acc[0]*0.125f + slope*(float)(jj     - i0    )) : 0.f;
            float p1 = (jj + 1 <= i0    ) ? __expf(acc[1]*0.125f + slope*(float)(jj + 1 - i0    )) : 0.f;
            float p2 = (jj     <= i0 + 8) ? __expf(acc[2]*0.125f + slope*(float)(jj     - i0 - 8)) : 0.f;
            float p3 = (jj + 1 <= i0 + 8) ? __expf(acc[3]*0.125f + slope*(float)(jj + 1 - i0 - 8)) : 0.f;
            l0 += p0 + p1;
            l1 += p2 + p3;
            sQP[r0    ][jl] = p0;  sQP[r0    ][jl + 1] = p1;
            sQP[r0 + 8][jl] = p2;  sQP[r0 + 8][jl + 1] = p3;
        }
        __syncthreads();

        // yacc += P @ V   (V read transposed from sV)
        #pragma unroll
        for (int ks = 0; ks < 8; ks++) {
            int kk = ks * 8;
            unsigned aw[4];
            aw[0] = __float_as_uint(sQP[r0    ][kk + t4]);
            aw[1] = __float_as_uint(sQP[r0 + 8][kk + t4]);
            aw[2] = __float_as_uint(sQP[r0    ][kk + t4 + 4]);
            aw[3] = __float_as_uint(sQP[r0 + 8][kk + t4 + 4]);
            #pragma unroll
            for (int j = 0; j < 4; j++) {
                int e = wn * 32 + j * 8 + gid;
                unsigned b[2];
                b[0] = __float_as_uint(sV[kk + t4    ][e]);
                b[1] = __float_as_uint(sV[kk + t4 + 4][e]);
                mma_tf32(yacc[j], aw, b);
            }
        }
        __syncthreads();
    }

    // row sums: reduce over t4 lanes, then across wn warps (2 fp32 adds, commutative)
    l0 += __shfl_xor_sync(0xffffffffu, l0, 1);
    l0 += __shfl_xor_sync(0xffffffffu, l0, 2);
    l1 += __shfl_xor_sync(0xffffffffu, l1, 1);
    l1 += __shfl_xor_sync(0xffffffffu, l1, 2);
    if (t4 == 0) {
        atomicAdd(&sL[r0], l0);
        atomicAdd(&sL[r0 + 8], l1);
    }
    __syncthreads();
    const float inv0 = 1.f / sL[r0], inv1 = 1.f / sL[r0 + 8];

    #pragma unroll
    for (int j = 0; j < 4; j++) {
        int e = h * HD_ + wn * 32 + j * 8 + t4 * 2;
        *reinterpret_cast<float2*>(y + (long long)(t0 + r0    ) * D_ + e) =
            make_float2(yacc[j][0] * inv0, yacc[j][1] * inv0);
        *reinterpret_cast<float2*>(y + (long long)(t0 + r0 + 8) * D_ + e) =
            make_float2(yacc[j][2] * inv1, yacc[j][3] * inv1);
    }
}

// ---------------------------------------------------------------------------
// Dict chain pass 1: partial exp-sums over a quarter of V.
// ---------------------------------------------------------------------------
#define DF_RB 32
#define DF_VC 64

__global__ void __launch_bounds__(128)
dict_pass1_kernel(const float* __restrict__ xhat, const float* __restrict__ emb,
                  float* __restrict__ dsum)
{
    const int h  = blockIdx.y;
    const int t0 = blockIdx.x * DF_RB;
    const int vs = blockIdx.z;
    const int vbase = vs * (V_ / 4);
    const int NCH = (V_ / 4) / DF_VC;

    __shared__ __align__(16) float sA[DF_RB][68];
    __shared__ __align__(16) float sE[2][DF_VC][68];
    __shared__ float sS[DF_RB];

    const int tid  = threadIdx.x;
    const int lane = tid & 31;
    const int warp = tid >> 5;
    const int gid  = lane >> 2;
    const int t4   = lane & 3;
    const int wm   = warp >> 1;
    const int wn   = warp & 1;

    #pragma unroll
    for (int i = 0; i < 4; i++) {
        int l = tid + i * 128;
        int r = l >> 4, q = (l & 15) * 4;
        *reinterpret_cast<float4*>(&sA[r][q]) =
            *reinterpret_cast<const float4*>(xhat + (long long)(t0 + r) * D_ + h * HD_ + q);
    }
    if (tid < DF_RB) sS[tid] = 0.f;
    __syncthreads();

    const int r0 = wm * 16 + gid;
    unsigned afr[8][4];
    #pragma unroll
    for (int ks = 0; ks < 8; ks++) {
        int kk = ks * 8;
        afr[ks][0] = __float_as_uint(sA[r0    ][kk + t4]);
        afr[ks][1] = __float_as_uint(sA[r0 + 8][kk + t4]);
        afr[ks][2] = __float_as_uint(sA[r0    ][kk + t4 + 4]);
        afr[ks][3] = __float_as_uint(sA[r0 + 8][kk + t4 + 4]);
    }

    const float* Eh = emb + (long long)h * V_ * HD_;
    auto loadE = [&](int st, int v0) {
        #pragma unroll
        for (int i = 0; i < 8; i++) {
            int l = tid + i * 128;
            int r = l >> 4, q = (l & 15) * 4;
            cp_async16(&sE[st][r][q], Eh + (long long)(v0 + r) * HD_ + q);
        }
    };

    float se0 = 0.f, se1 = 0.f;
    loadE(0, vbase);
    cp_commit();
    for (int c = 0; c < NCH; c++) {
        if (c + 1 < NCH) loadE((c + 1) & 1, vbase + (c + 1) * DF_VC);
        cp_commit();
        cp_wait<1>();
        __syncthreads();
        const int st = c & 1;

        #pragma unroll
        for (int j = 0; j < 4; j++) {
            float acc[4] = {0.f, 0.f, 0.f, 0.f};
            #pragma unroll
            for (int ks = 0; ks < 8; ks++) {
                int kk = ks * 8;
                int v = wn * 32 + j * 8 + gid;
                unsigned b[2];
                b[0] = __float_as_uint(sE[st][v][kk + t4]);
                b[1] = __float_as_uint(sE[st][v][kk + t4 + 4]);
                mma_tf32(acc, afr[ks], b);
            }
            se0 += __expf(acc[0]) + __expf(acc[1]);
            se1 += __expf(acc[2]) + __expf(acc[3]);
        }
        __syncthreads();
    }
    se0 += __shfl_xor_sync(0xffffffffu, se0, 1);
    se0 += __shfl_xor_sync(0xffffffffu, se0, 2);
    se1 += __shfl_xor_sync(0xffffffffu, se1, 1);
    se1 += __shfl_xor_sync(0xffffffffu, se1, 2);
    if (t4 == 0) {
        atomicAdd(&sS[r0], se0);
        atomicAdd(&sS[r0 + 8], se1);
    }
    __syncthreads();
    if (tid < DF_RB)
        dsum[((long long)h * T_ + t0 + tid) * 4 + vs] = sS[tid];
}

// ---------------------------------------------------------------------------
// Dict chain pass 2: weights out + recon partial over half of V.
// ---------------------------------------------------------------------------
__global__ void __launch_bounds__(128)
dict_pass2_kernel(const float* __restrict__ xhat, const float* __restrict__ emb,
                  const float* __restrict__ dsum, float* __restrict__ wout,
                  float* __restrict__ reconP)
{
    const int h  = blockIdx.y;
    const int t0 = blockIdx.x * DF_RB;
    const int vs = blockIdx.z;
    const int vbase = vs * (V_ / 2);
    const int NCH = (V_ / 2) / DF_VC;

    __shared__ __align__(16) float sA[DF_RB][68];
    __shared__ __align__(16) float sW[DF_RB][68];
    __shared__ __align__(16) float sE[2][DF_VC][68];
    __shared__ float sInv[DF_RB];

    const int tid  = threadIdx.x;
    const int lane = tid & 31;
    const int warp = tid >> 5;
    const int gid  = lane >> 2;
    const int t4   = lane & 3;
    const int wm   = warp >> 1;
    const int wn   = warp & 1;

    #pragma unroll
    for (int i = 0; i < 4; i++) {
        int l = tid + i * 128;
        int r = l >> 4, q = (l & 15) * 4;
        *reinterpret_cast<float4*>(&sA[r][q]) =
            *reinterpret_cast<const float4*>(xhat + (long long)(t0 + r) * D_ + h * HD_ + q);
    }
    if (tid < DF_RB) {
        const float* ds = dsum + ((long long)h * T_ + t0 + tid) * 4;
        sInv[tid] = 1.f / (ds[0] + ds[1] + ds[2] + ds[3]);
    }
    __syncthreads();

    const int r0 = wm * 16 + gid;
    unsigned afr[8][4];
    #pragma unroll
    for (int ks = 0; ks < 8; ks++) {
        int kk = ks * 8;
        afr[ks][0] = __float_as_uint(sA[r0    ][kk + t4]);
        afr[ks][1] = __float_as_uint(sA[r0 + 8][kk + t4]);
        afr[ks][2] = __float_as_uint(sA[r0    ][kk + t4 + 4]);
        afr[ks][3] = __float_as_uint(sA[r0 + 8][kk + t4 + 4]);
    }
    const float inv0 = sInv[r0], inv1 = sInv[r0 + 8];

    const float* Eh = emb + (long long)h * V_ * HD_;
    auto loadE = [&](int st, int v0) {
        #pragma unroll
        for (int i = 0; i < 8; i++) {
            int l = tid + i * 128;
            int r = l >> 4, q = (l & 15) * 4;
            cp_async16(&sE[st][r][q], Eh + (long long)(v0 + r) * HD_ + q);
        }
    };

    float racc[4][4];
    #pragma unroll
    for (int j = 0; j < 4; j++) {
        racc[j][0] = 0.f; racc[j][1] = 0.f; racc[j][2] = 0.f; racc[j][3] = 0.f;
    }

    loadE(0, vbase);
    cp_commit();
    for (int c = 0; c < NCH; c++) {
        if (c + 1 < NCH) loadE((c + 1) & 1, vbase + (c + 1) * DF_VC);
        cp_commit();
        cp_wait<1>();
        __syncthreads();
        const int st = c & 1;

        #pragma unroll
        for (int j = 0; j < 4; j++) {
            float acc[4] = {0.f, 0.f, 0.f, 0.f};
            #pragma unroll
            for (int ks = 0; ks < 8; ks++) {
                int kk = ks * 8;
                int v = wn * 32 + j * 8 + gid;
                unsigned b[2];
                b[0] = __float_as_uint(sE[st][v][kk + t4]);
                b[1] = __float_as_uint(sE[st][v][kk + t4 + 4]);
                mma_tf32(acc, afr[ks], b);
            }
            int vl = wn * 32 + j * 8 + t4 * 2;
            float w0 = __expf(acc[0]) * inv0;
            float w1 = __expf(acc[1]) * inv0;
            float w2 = __expf(acc[2]) * inv1;
            float w3 = __expf(acc[3]) * inv1;
            long long vg = (long long)vbase + c * DF_VC + vl;
            *reinterpret_cast<float2*>(wout + ((long long)(h*T_ + t0 + r0    ))*V_ + vg) = make_float2(w0, w1);
            *reinterpret_cast<float2*>(wout + ((long long)(h*T_ + t0 + r0 + 8))*V_ + vg) = make_float2(w2, w3);
            sW[r0    ][vl] = w0;  sW[r0    ][vl + 1] = w1;
            sW[r0 + 8][vl] = w2;  sW[r0 + 8][vl + 1] = w3;
        }
        __syncthreads();

        #pragma unroll
        for (int ks = 0; ks < 8; ks++) {
            int kk = ks * 8;
            unsigned aw[4];
            aw[0] = __float_as_uint(sW[r0    ][kk + t4]);
            aw[1] = __float_as_uint(sW[r0 + 8][kk + t4]);
            aw[2] = __float_as_uint(sW[r0    ][kk + t4 + 4]);
            aw[3] = __float_as_uint(sW[r0 + 8][kk + t4 + 4]);
            #pragma unroll
            for (int j = 0; j < 4; j++) {
                int e = wn * 32 + j * 8 + gid;
                unsigned b[2];
                b[0] = __float_as_uint(sE[st][kk + t4    ][e]);
                b[1] = __float_as_uint(sE[st][kk + t4 + 4][e]);
                mma_tf32(racc[j], aw, b);
            }
        }
        __syncthreads();
    }

    float* rp = reconP + (long long)vs * T_ * D_;
    #pragma unroll
    for (int j = 0; j < 4; j++) {
        int e = h * HD_ + wn * 32 + j * 8 + t4 * 2;
        *reinterpret_cast<float2*>(rp + (long long)(t0 + r0    ) * D_ + e) =
            make_float2(racc[j][0], racc[j][1]);
        *reinterpret_cast<float2*>(rp + (long long)(t0 + r0 + 8) * D_ + e) =
            make_float2(racc[j][2], racc[j][3]);
    }
}

// ---------------------------------------------------------------------------
// LayerNorm over D=768 of (a + b)
// ---------------------------------------------------------------------------
__global__ void ln2in_kernel(const float* __restrict__ a, const float* __restrict__ b,
                             const float* __restrict__ w, const float* __restrict__ bb,
                             float* __restrict__ out)
{
    const int t = blockIdx.x;
    const int tid = threadIdx.x;
    const float* pa = a + (long long)t * D_;
    const float* pb = b + (long long)t * D_;
    float x[3];
    float s = 0.f, ss = 0.f;
    #pragma unroll
    for (int i = 0; i < 3; i++) {
        int d = tid + i*256;
        float v = pa[d] + pb[d];
        x[i] = v; s += v; ss += v*v;
    }
    #pragma unroll
    for (int o = 16; o; o >>= 1) {
        s  += __shfl_xor_sync(0xffffffffu, s, o);
        ss += __shfl_xor_sync(0xffffffffu, ss, o);
    }
    __shared__ float rs[8], rss[8];
    __shared__ float s_mu, s_inv;
    if ((tid & 31) == 0) { rs[tid >> 5] = s; rss[tid >> 5] = ss; }
    __syncthreads();
    if (tid == 0) {
        float S = 0.f, SS = 0.f;
        #pragma unroll
        for (int i = 0; i < 8; i++) { S += rs[i]; SS += rss[i]; }
        float mu  = S * (1.f / D_);
        float var = SS * (1.f / D_) - mu*mu;
        s_mu = mu;
        s_inv = rsqrtf(var + 1e-5f);
    }
    __syncthreads();
    float mu = s_mu, inv = s_inv;
    #pragma unroll
    for (int i = 0; i < 3; i++) {
        int d = tid + i*256;
        out[(long long)t*D_ + d] = (x[i] - mu) * inv * w[d] + bb[d];
    }
}

// v[h,t,d] = sum_j v_fact[h,j] * xt[t, j*64+d]
__global__ void vmix_kernel(const float* __restrict__ xt, const float* __restrict__ vf,
                            float* __restrict__ v)
{
    int idx = blockIdx.x * 256 + threadIdx.x;
    int d = idx & (HD_-1);
    int t = (idx >> 6) & (T_-1);
    int h = idx >> 16;
    float s = 0.f;
    #pragma unroll
    for (int j = 0; j < H_; j++)
        s += vf[h*H_ + j] * xt[(long long)t*D_ + j*HD_ + d];
    v[idx] = s;
}

// xt_new[t, i*64+d] = xt + sum_j out_fact[i,j] * y[t, j*64+d]
__global__ void outmix_kernel(const float* __restrict__ xt, const float* __restrict__ of,
                              const float* __restrict__ y, float* __restrict__ o)
{
    int idx = blockIdx.x * 256 + threadIdx.x;
    int d = idx & (HD_-1);
    int i = (idx >> 6) % H_;
    int t = idx / D_;
    float s = 0.f;
    #pragma unroll
    for (int j = 0; j < H_; j++)
        s += of[i*H_ + j] * y[(long long)t*D_ + j*HD_ + d];
    o[idx] = xt[idx] + s;
}

// per-(h,t) LayerNorm over HD=64; input = sum of 4 split-K partials + proj bias
__global__ void dln_kernel(const float* __restrict__ xpP, const float* __restrict__ pb,
                           const float* __restrict__ w, const float* __restrict__ b,
                           float* __restrict__ xh)
{
    int bx = blockIdx.x;
    int t = bx & (T_-1);
    int h = bx >> 10;
    int lane = threadIdx.x;
    const long long base = (long long)t*D_ + h*HD_;
    const long long TD = (long long)T_*D_;
    float v0 = xpP[base + lane]      + xpP[base + lane + TD]
             + xpP[base + lane + 2*TD] + xpP[base + lane + 3*TD] + pb[h*HD_ + lane];
    float v1 = xpP[base + lane + 32] + xpP[base + lane + 32 + TD]
             + xpP[base + lane + 32 + 2*TD] + xpP[base + lane + 32 + 3*TD] + pb[h*HD_ + lane + 32];
    float s = v0 + v1, ss = v0*v0 + v1*v1;
    #pragma unroll
    for (int o = 16; o; o >>= 1) {
        s  += __shfl_xor_sync(0xffffffffu, s, o);
        ss += __shfl_xor_sync(0xffffffffu, ss, o);
    }
    float mu  = s * (1.f / HD_);
    float var = ss * (1.f / HD_) - mu*mu;
    float inv = rsqrtf(var + 1e-5f);
    float* q = xh + base;
    q[lane]      = (v0 - mu) * inv * w[h*HD_ + lane]      + b[h*HD_ + lane];
    q[lane + 32] = (v1 - mu) * inv * w[h*HD_ + lane + 32] + b[h*HD_ + lane + 32];
}

// xe_new = xe + reconP0 + reconP1 ; also store combined recon for the loss
__global__ void add2_kernel(const float* __restrict__ xe, const float* __restrict__ rp,
                            float* __restrict__ oxe, float* __restrict__ recon)
{
    int idx = blockIdx.x * 256 + threadIdx.x;
    float r = rp[idx] + rp[idx + T_*D_];
    recon[idx] = r;
    oxe[idx] = xe[idx] + r;
}

__global__ void loss_partial_kernel(const float* __restrict__ a, const float* __restrict__ b)
{
    double s = 0.0;
    for (int idx = blockIdx.x*256 + threadIdx.x; idx < T_*D_; idx += 256*256) {
        float d = a[idx] - b[idx];
        s += (double)d * (double)d;
    }
    __shared__ double sh[256];
    sh[threadIdx.x] = s;
    __syncthreads();
    for (int o = 128; o; o >>= 1) {
        if (threadIdx.x < o) sh[threadIdx.x] += sh[threadIdx.x + o];
        __syncthreads();
    }
    if (threadIdx.x == 0) g_lossPartial[blockIdx.x] = sh[0];
}

__global__ void loss_final_kernel(float* __restrict__ out)
{
    __shared__ double sh[256];
    sh[threadIdx.x] = g_lossPartial[threadIdx.x];
    __syncthreads();
    for (int o = 128; o; o >>= 1) {
        if (threadIdx.x < o) sh[threadIdx.x] += sh[threadIdx.x + o];
        __syncthreads();
    }
    if (threadIdx.x == 0) out[0] = (float)(sh[0] / (double)(T_*D_));
}

// ---------------------------------------------------------------------------
// Host launcher
// ---------------------------------------------------------------------------
extern "C" void kernel_launch(void* const* d_in, const int* in_sizes, int n_in,
                              void* d_out, int out_size)
{
    (void)in_sizes; (void)n_in; (void)out_size;
    const float* xt       = (const float*)d_in[0];
    const float* xe       = (const float*)d_in[1];
    const float* ln1_w    = (const float*)d_in[2];
    const float* ln1_b    = (const float*)d_in[3];
    const float* qk_w     = (const float*)d_in[4];
    const float* qk_b     = (const float*)d_in[5];
    const float* v_fact   = (const float*)d_in[6];
    const float* out_fact = (const float*)d_in[7];
    const float* ln2_w    = (const float*)d_in[8];
    const float* ln2_b    = (const float*)d_in[9];
    const float* fc_w     = (const float*)d_in[10];
    const float* fc_b     = (const float*)d_in[11];
    const float* proj_w   = (const float*)d_in[12];
    const float* proj_b   = (const float*)d_in[13];
    const float* dln_w    = (const float*)d_in[14];
    const float* dln_b    = (const float*)d_in[15];
    const float* dict_emb = (const float*)d_in[16];

    float* out    = (float*)d_out;
    float* o_xt   = out;
    float* o_xe   = out + OFF_XE;
    float* o_w    = out + OFF_W;
    float* o_loss = out + OFF_LOSS;

    float *p_xnorm, *p_qk, *p_v, *p_y, *p_x2, *p_h,
          *p_xpreP, *p_xhat, *p_dsum, *p_reconP, *p_recon;
    cudaGetSymbolAddress((void**)&p_xnorm,  g_xnorm);
    cudaGetSymbolAddress((void**)&p_qk,     g_qk);
    cudaGetSymbolAddress((void**)&p_v,      g_v);
    cudaGetSymbolAddress((void**)&p_y,      g_y);
    cudaGetSymbolAddress((void**)&p_x2,     g_x2);
    cudaGetSymbolAddress((void**)&p_h,      g_h);
    cudaGetSymbolAddress((void**)&p_xpreP,  g_xpreP);
    cudaGetSymbolAddress((void**)&p_xhat,   g_xhat);
    cudaGetSymbolAddress((void**)&p_dsum,   g_dsum);
    cudaGetSymbolAddress((void**)&p_reconP, g_reconP);
    cudaGetSymbolAddress((void**)&p_recon,  g_recon);

    // 1) x_norm = LN(xt + xe)
    ln2in_kernel<<<T_, 256>>>(xt, xe, ln1_w, ln1_b, p_xnorm);

    // 2) qk = x_norm @ qk_w^T + qk_b       [T, 1536]   (BK=32)
    gemm_tc<128,128,32,64,32,256><<<dim3(2*D_/128, T_/128, 1), 256>>>(
        p_xnorm, qk_w, p_qk, qk_b, D_, D_, D_, 2*D_, 0,0,0,0, 1.f, 1, 0, 0, 0, 1, 0, 0);

    // 3) v[h,t,d]
    vmix_kernel<<<H_*T_*HD_/256, 256>>>(xt, v_fact, p_v);

    // 4) fused flash attention -> g_y[t, h*64+d]
    flash_attn_kernel<<<dim3(T_/FA_RB, H_), 128>>>(p_qk, p_v, p_y);

    // 5) xt_new = xt + out_fact-mix(y)
    outmix_kernel<<<T_*D_/256, 256>>>(xt, out_fact, p_y, o_xt);

    // 6) x2 = LN(xt_new + xe)
    ln2in_kernel<<<T_, 256>>>(o_xt, xe, ln2_w, ln2_b, p_x2);

    // 7) h = gelu(x2 @ fc_w^T + fc_b)   [T, 36864]   (BK=32, dominant GEMM)
    gemm_tc<128,128,32,64,32,256><<<dim3(T_/128, H_*FF_/128, 1), 256>>>(
        p_x2, fc_w, p_h, fc_b, D_, D_, D_, H_*FF_, 0,0,0,0, 1.f, 2, 0, 0, 1, 1, 0, 0);

    // 8) proj split-K=4: xpreP[ks] = h[h][k-range] @ proj_w[h][k-range]^T
    gemm_tc<64,64,16,16,32,256><<<dim3(1, T_/64, H_*4), 256>>>(
        p_h, proj_w, p_xpreP, nullptr, FF_, H_*FF_, FF_, D_,
        FF_, (long long)HD_*FF_, 64, 0, 1.f, 0, 0, 0, 0, 4, FF_/4, (long long)T_*D_);

    // 9) x_hat = per-head LN(sum of partials + proj_b)
    dln_kernel<<<H_*T_, 32>>>(p_xpreP, proj_b, dln_w, dln_b, p_xhat);

    // 10) dict pass 1: partial exp-sums (V split 4-way)
    dict_pass1_kernel<<<dim3(T_/DF_RB, H_, 4), 128>>>(p_xhat, dict_emb, p_dsum);

    // 11) dict pass 2: weights + recon partials (V split 2-way)
    dict_pass2_kernel<<<dim3(T_/DF_RB, H_, 2), 128>>>(p_xhat, dict_emb, p_dsum, o_w, p_reconP);

    // 12) xe_new = xe + recon ; store combined recon
    add2_kernel<<<T_*D_/256, 256>>>(xe, p_reconP, o_xe, p_recon);

    // 13) dict_loss = mean((x_hat - x_recon)^2)
    loss_partial_kernel<<<256, 256>>>(p_xhat, p_recon);
    loss_final_kernel<<<1, 256>>>(o_loss);
}

// round 16
// speedup vs baseline: 1.2602x; 1.0462x over previous
#include <cuda_runtime.h>
#include <math.h>

// ---------------------------------------------------------------------------
// Problem constants
// ---------------------------------------------------------------------------
#define T_  1024
#define D_  768
#define H_  12
#define FF_ 3072
#define V_  8192
#define HD_ 64

// output layout: xt_new [T*D] | xe_new [T*D] | dict_weights [H*T*V] | loss [1]
#define OFF_XE   (T_*D_)
#define OFF_W    (2*T_*D_)
#define OFF_LOSS (2*T_*D_ + H_*T_*V_)

// ---------------------------------------------------------------------------
// Device scratch (allocation-free: __device__ globals)
// ---------------------------------------------------------------------------
__device__ __align__(16) float g_xnorm[T_*D_];
__device__ __align__(16) float g_qk[T_*2*D_];
__device__ __align__(16) float g_v[H_*T_*HD_];
__device__ __align__(16) float g_y[T_*D_];
__device__ __align__(16) float g_x2[T_*D_];
__device__ __align__(16) float g_h[T_*H_*FF_];              // 151 MB
__device__ __align__(16) float g_xpreP[4*T_*D_];            // proj split-K partials
__device__ __align__(16) float g_xhat[T_*D_];
__device__ __align__(16) float g_dsum[H_*T_*4];             // dict exp-sum partials
__device__ __align__(16) float g_reconP[2*T_*D_];           // recon v-split partials
__device__ __align__(16) float g_recon[T_*D_];
__device__ double g_lossPartial[256];

// ---------------------------------------------------------------------------
// Helpers
// ---------------------------------------------------------------------------
__device__ __forceinline__ float gelu_exact(float x) {
    return 0.5f * x * (1.0f + erff(x * 0.70710678118654752f));
}

__device__ __forceinline__ void cp_async16(void* s, const void* g) {
    unsigned sa = (unsigned)__cvta_generic_to_shared(s);
    asm volatile("cp.async.cg.shared.global [%0], [%1], 16;\n" :: "r"(sa), "l"(g));
}
__device__ __forceinline__ void cp_commit() {
    asm volatile("cp.async.commit_group;\n");
}
template<int N>
__device__ __forceinline__ void cp_wait() {
    asm volatile("cp.async.wait_group %0;\n" :: "n"(N));
}

__device__ __forceinline__ void mma_tf32(float* c, const unsigned* a, const unsigned* b) {
    asm volatile(
        "mma.sync.aligned.m16n8k8.row.col.f32.tf32.tf32.f32 "
        "{%0,%1,%2,%3}, {%4,%5,%6,%7}, {%8,%9}, {%0,%1,%2,%3};\n"
        : "+f"(c[0]), "+f"(c[1]), "+f"(c[2]), "+f"(c[3])
        : "r"(a[0]), "r"(a[1]), "r"(a[2]), "r"(a[3]), "r"(b[0]), "r"(b[1]));
}

// ---------------------------------------------------------------------------
// Tensor-core NT GEMM (tf32 mma.sync m16n8k8), cp.async 2-stage pipeline.
//   C[m,n] = alpha * sum_k A[m,k]*B[n,k]   (+bias, +gelu) ; batched over z
// nsplit>1: split-K — blockIdx.z = zb*nsplit+zs, K range [zs*klen,(zs+1)*klen),
//           C += zs*sCsplit (partial buffers, mode must be 0).
// ---------------------------------------------------------------------------
template<int BM, int BN, int BK, int WM, int WN, int THREADS>
__global__ void __launch_bounds__(THREADS)
gemm_tc(const float* __restrict__ A, const float* __restrict__ B,
        float* __restrict__ C, const float* __restrict__ bias,
        int K, int lda, int ldb, int ldc,
        long long sA, long long sB, long long sC, long long sBias,
        float alpha, int mode, int causal, int kcap, int swapxy,
        int nsplit, int klen, long long sCsplit)
{
    constexpr int NWN = BN / WN;          // warps along N
    constexpr int TM  = WM / 16;          // mma tiles per warp along M
    constexpr int TN  = WN / 8;           // mma tiles per warp along N
    constexpr int LK  = BK + 4;           // smem row stride (words) -> conflict-free
    constexpr int LA  = BM * (BK/4) / THREADS;
    constexpr int LB  = BN * (BK/4) / THREADS;

    const int bx = blockIdx.x, by = blockIdx.y;
    const int m0 = (swapxy ? bx : by) * BM;
    const int n0 = (swapxy ? by : bx) * BN;
    if (causal && n0 > m0 + BM - 1) return;

    __shared__ __align__(16) float As[2][BM][LK];
    __shared__ __align__(16) float Bs[2][BN][LK];

    int zb = blockIdx.z, koff = 0;
    if (nsplit > 1) {
        int zs = zb % nsplit;
        zb = zb / nsplit;
        koff = zs * klen;
        C += zs * sCsplit;
        K = klen;
    }
    A += zb * sA + koff;  B += zb * sB + koff;  C += zb * sC;
    if (mode >= 1) bias += zb * sBias;

    const int tid  = threadIdx.x;
    const int lane = tid & 31;
    const int warp = tid >> 5;
    const int gid  = lane >> 2;
    const int t4   = lane & 3;
    const int wm   = warp / NWN;
    const int wn   = warp % NWN;

    float acc[TM][TN][4];
    #pragma unroll
    for (int i = 0; i < TM; i++)
        #pragma unroll
        for (int j = 0; j < TN; j++) {
            acc[i][j][0] = 0.f; acc[i][j][1] = 0.f;
            acc[i][j][2] = 0.f; acc[i][j][3] = 0.f;
        }

    int Keff = K;
    if (kcap) { int ke = m0 + BM; if (ke < K) Keff = ke; }
    const int niter = Keff / BK;

    auto load_stage = [&](int st, int k0) {
        #pragma unroll
        for (int i = 0; i < LA; i++) {
            int l = tid + i * THREADS;
            int r = l / (BK/4), q = (l % (BK/4)) * 4;
            cp_async16(&As[st][r][q], A + (long long)(m0 + r) * lda + k0 + q);
        }
        #pragma unroll
        for (int i = 0; i < LB; i++) {
            int l = tid + i * THREADS;
            int r = l / (BK/4), q = (l % (BK/4)) * 4;
            cp_async16(&Bs[st][r][q], B + (long long)(n0 + r) * ldb + k0 + q);
        }
    };

    load_stage(0, 0);
    cp_commit();
    if (niter > 1) load_stage(1, BK);
    cp_commit();

    for (int it = 0; it < niter; it++) {
        cp_wait<1>();
        __syncthreads();

        const int st = it & 1;
        #pragma unroll
        for (int kk = 0; kk < BK; kk += 8) {
            unsigned a[TM][4], b[TN][2];
            #pragma unroll
            for (int i = 0; i < TM; i++) {
                int r = wm * WM + i * 16 + gid;
                a[i][0] = __float_as_uint(As[st][r    ][kk + t4]);
                a[i][1] = __float_as_uint(As[st][r + 8][kk + t4]);
                a[i][2] = __float_as_uint(As[st][r    ][kk + t4 + 4]);
                a[i][3] = __float_as_uint(As[st][r + 8][kk + t4 + 4]);
            }
            #pragma unroll
            for (int j = 0; j < TN; j++) {
                int c = wn * WN + j * 8 + gid;
                b[j][0] = __float_as_uint(Bs[st][c][kk + t4]);
                b[j][1] = __float_as_uint(Bs[st][c][kk + t4 + 4]);
            }
            #pragma unroll
            for (int i = 0; i < TM; i++)
                #pragma unroll
                for (int j = 0; j < TN; j++)
                    mma_tf32(acc[i][j], a[i], b[j]);
        }
        __syncthreads();

        if (it + 2 < niter) load_stage(st, (it + 2) * BK);
        cp_commit();
    }

    #pragma unroll
    for (int i = 0; i < TM; i++) {
        const int m = m0 + wm * WM + i * 16 + gid;
        #pragma unroll
        for (int j = 0; j < TN; j++) {
            const int n = n0 + wn * WN + j * 8 + t4 * 2;
            float c0 = acc[i][j][0] * alpha, c1 = acc[i][j][1] * alpha;
            float c2 = acc[i][j][2] * alpha, c3 = acc[i][j][3] * alpha;
            if (mode >= 1) {
                float b0 = bias[n], b1 = bias[n + 1];
                c0 += b0; c1 += b1; c2 += b0; c3 += b1;
            }
            if (mode == 2) {
                c0 = gelu_exact(c0); c1 = gelu_exact(c1);
                c2 = gelu_exact(c2); c3 = gelu_exact(c3);
            }
            *reinterpret_cast<float2*>(C + (long long)m       * ldc + n) = make_float2(c0, c1);
            *reinterpret_cast<float2*>(C + (long long)(m + 8) * ldc + n) = make_float2(c2, c3);
        }
    }
}

// ---------------------------------------------------------------------------
// Fused flash attention v2: double-buffered K/V, reversed block order.
// Block: 32 q-rows x 1 head, 128 threads. grid (T/32, H) = 384 CTAs.
// Max-free softmax (logits tiny + ALiBi bias <= 0).
// ---------------------------------------------------------------------------
#define FA_RB 32
#define FA_KC 64

__global__ void __launch_bounds__(128)
flash_attn_kernel(const float* __restrict__ qk,   // [T][2D] (q | k)
                  const float* __restrict__ v,    // [H][T][64]
                  float* __restrict__ y)          // [T][D]
{
    const int h  = blockIdx.y;
    const int t0 = (gridDim.x - 1 - blockIdx.x) * FA_RB;   // longest blocks first
    const float slope = (h < 8) ? exp2f(-(float)(h+1)) : exp2f(-0.5f * (float)(h-7));

    __shared__ __align__(16) float sQP[FA_RB][68];
    __shared__ __align__(16) float sK[2][FA_KC][68];
    __shared__ __align__(16) float sV[2][FA_KC][68];
    __shared__ float sL[FA_RB];

    const int tid  = threadIdx.x;
    const int lane = tid & 31;
    const int warp = tid >> 5;
    const int gid  = lane >> 2;
    const int t4   = lane & 3;
    const int wm   = warp >> 1;
    const int wn   = warp & 1;

    // load Q tile [32 x 64]
    #pragma unroll
    for (int i = 0; i < 4; i++) {
        int l = tid + i * 128;
        int r = l >> 4, q = (l & 15) * 4;
        *reinterpret_cast<float4*>(&sQP[r][q]) =
            *reinterpret_cast<const float4*>(qk + (long long)(t0 + r) * (2*D_) + h * HD_ + q);
    }
    if (tid < FA_RB) sL[tid] = 0.f;
    __syncthreads();

    const int r0 = wm * 16 + gid;
    unsigned afr[8][4];
    #pragma unroll
    for (int ks = 0; ks < 8; ks++) {
        int kk = ks * 8;
        afr[ks][0] = __float_as_uint(sQP[r0    ][kk + t4]);
        afr[ks][1] = __float_as_uint(sQP[r0 + 8][kk + t4]);
        afr[ks][2] = __float_as_uint(sQP[r0    ][kk + t4 + 4]);
        afr[ks][3] = __float_as_uint(sQP[r0 + 8][kk + t4 + 4]);
    }
    __syncthreads();   // sQP free -> becomes P tile

    float yacc[4][4];
    #pragma unroll
    for (int j = 0; j < 4; j++) {
        yacc[j][0] = 0.f; yacc[j][1] = 0.f; yacc[j][2] = 0.f; yacc[j][3] = 0.f;
    }
    float l0 = 0.f, l1 = 0.f;
    const int i0 = t0 + r0;
    const int nch = t0 / FA_KC + 1;

    auto loadKV = [&](int st, int c) {
        #pragma unroll
        for (int i = 0; i < 8; i++) {
            int l = tid + i * 128;
            int r = l >> 4, q = (l & 15) * 4;
            cp_async16(&sK[st][r][q], qk + (long long)(c*FA_KC + r) * (2*D_) + D_ + h * HD_ + q);
            cp_async16(&sV[st][r][q], v + ((long long)h * T_ + c*FA_KC + r) * HD_ + q);
        }
    };

    loadKV(0, 0);
    cp_commit();
    for (int c = 0; c < nch; c++) {
        if (c + 1 < nch) loadKV((c + 1) & 1, c + 1);
        cp_commit();
        cp_wait<1>();
        __syncthreads();
        const int st = c & 1;

        // S = Q @ K^T, then masked exp -> P into sQP
        #pragma unroll
        for (int j = 0; j < 4; j++) {
            float acc[4] = {0.f, 0.f, 0.f, 0.f};
            #pragma unroll
            for (int ks = 0; ks < 8; ks++) {
                int kk = ks * 8;
                int vv = wn * 32 + j * 8 + gid;
                unsigned b[2];
                b[0] = __float_as_uint(sK[st][vv][kk + t4]);
                b[1] = __float_as_uint(sK[st][vv][kk + t4 + 4]);
                mma_tf32(acc, afr[ks], b);
            }
            int jl = wn * 32 + j * 8 + t4 * 2;
            int jj = c * FA_KC + jl;
            float p0 = (jj     <= i0    ) ? __expf(acc[0]*0.125f + slope*(float)(jj     - i0    )) : 0.f;
            float p1 = (jj + 1 <= i0    ) ? __expf(acc[1]*0.125f + slope*(float)(jj + 1 - i0    )) : 0.f;
            float p2 = (jj     <= i0 + 8) ? __expf(acc[2]*0.125f + slope*(float)(jj     - i0 - 8)) : 0.f;
            float p3 = (jj + 1 <= i0 + 8) ? __expf(acc[3]*0.125f + slope*(float)(jj + 1 - i0 - 8)) : 0.f;
            l0 += p0 + p1;
            l1 += p2 + p3;
            sQP[r0    ][jl] = p0;  sQP[r0    ][jl + 1] = p1;
            sQP[r0 + 8][jl] = p2;  sQP[r0 + 8][jl + 1] = p3;
        }
        __syncthreads();

        // yacc += P @ V   (V read transposed from sV)
        #pragma unroll
        for (int ks = 0; ks < 8; ks++) {
            int kk = ks * 8;
            unsigned aw[4];
            aw[0] = __float_as_uint(sQP[r0    ][kk + t4]);
            aw[1] = __float_as_uint(sQP[r0 + 8][kk + t4]);
            aw[2] = __float_as_uint(sQP[r0    ][kk + t4 + 4]);
            aw[3] = __float_as_uint(sQP[r0 + 8][kk + t4 + 4]);
            #pragma unroll
            for (int j = 0; j < 4; j++) {
                int e = wn * 32 + j * 8 + gid;
                unsigned b[2];
                b[0] = __float_as_uint(sV[st][kk + t4    ][e]);
                b[1] = __float_as_uint(sV[st][kk + t4 + 4][e]);
                mma_tf32(yacc[j], aw, b);
            }
        }
        __syncthreads();
    }

    l0 += __shfl_xor_sync(0xffffffffu, l0, 1);
    l0 += __shfl_xor_sync(0xffffffffu, l0, 2);
    l1 += __shfl_xor_sync(0xffffffffu, l1, 1);
    l1 += __shfl_xor_sync(0xffffffffu, l1, 2);
    if (t4 == 0) {
        atomicAdd(&sL[r0], l0);
        atomicAdd(&sL[r0 + 8], l1);
    }
    __syncthreads();
    const float inv0 = 1.f / sL[r0], inv1 = 1.f / sL[r0 + 8];

    #pragma unroll
    for (int j = 0; j < 4; j++) {
        int e = h * HD_ + wn * 32 + j * 8 + t4 * 2;
        *reinterpret_cast<float2*>(y + (long long)(t0 + r0    ) * D_ + e) =
            make_float2(yacc[j][0] * inv0, yacc[j][1] * inv0);
        *reinterpret_cast<float2*>(y + (long long)(t0 + r0 + 8) * D_ + e) =
            make_float2(yacc[j][2] * inv1, yacc[j][3] * inv1);
    }
}

// ---------------------------------------------------------------------------
// Dict chain pass 1: partial exp-sums over a quarter of V.
// ---------------------------------------------------------------------------
#define DF_RB 32
#define DF_VC 64

__global__ void __launch_bounds__(128)
dict_pass1_kernel(const float* __restrict__ xhat, const float* __restrict__ emb,
                  float* __restrict__ dsum)
{
    const int h  = blockIdx.y;
    const int t0 = blockIdx.x * DF_RB;
    const int vs = blockIdx.z;
    const int vbase = vs * (V_ / 4);
    const int NCH = (V_ / 4) / DF_VC;

    __shared__ __align__(16) float sA[DF_RB][68];
    __shared__ __align__(16) float sE[2][DF_VC][68];
    __shared__ float sS[DF_RB];

    const int tid  = threadIdx.x;
    const int lane = tid & 31;
    const int warp = tid >> 5;
    const int gid  = lane >> 2;
    const int t4   = lane & 3;
    const int wm   = warp >> 1;
    const int wn   = warp & 1;

    #pragma unroll
    for (int i = 0; i < 4; i++) {
        int l = tid + i * 128;
        int r = l >> 4, q = (l & 15) * 4;
        *reinterpret_cast<float4*>(&sA[r][q]) =
            *reinterpret_cast<const float4*>(xhat + (long long)(t0 + r) * D_ + h * HD_ + q);
    }
    if (tid < DF_RB) sS[tid] = 0.f;
    __syncthreads();

    const int r0 = wm * 16 + gid;
    unsigned afr[8][4];
    #pragma unroll
    for (int ks = 0; ks < 8; ks++) {
        int kk = ks * 8;
        afr[ks][0] = __float_as_uint(sA[r0    ][kk + t4]);
        afr[ks][1] = __float_as_uint(sA[r0 + 8][kk + t4]);
        afr[ks][2] = __float_as_uint(sA[r0    ][kk + t4 + 4]);
        afr[ks][3] = __float_as_uint(sA[r0 + 8][kk + t4 + 4]);
    }

    const float* Eh = emb + (long long)h * V_ * HD_;
    auto loadE = [&](int st, int v0) {
        #pragma unroll
        for (int i = 0; i < 8; i++) {
            int l = tid + i * 128;
            int r = l >> 4, q = (l & 15) * 4;
            cp_async16(&sE[st][r][q], Eh + (long long)(v0 + r) * HD_ + q);
        }
    };

    float se0 = 0.f, se1 = 0.f;
    loadE(0, vbase);
    cp_commit();
    for (int c = 0; c < NCH; c++) {
        if (c + 1 < NCH) loadE((c + 1) & 1, vbase + (c + 1) * DF_VC);
        cp_commit();
        cp_wait<1>();
        __syncthreads();
        const int st = c & 1;

        #pragma unroll
        for (int j = 0; j < 4; j++) {
            float acc[4] = {0.f, 0.f, 0.f, 0.f};
            #pragma unroll
            for (int ks = 0; ks < 8; ks++) {
                int kk = ks * 8;
                int v = wn * 32 + j * 8 + gid;
                unsigned b[2];
                b[0] = __float_as_uint(sE[st][v][kk + t4]);
                b[1] = __float_as_uint(sE[st][v][kk + t4 + 4]);
                mma_tf32(acc, afr[ks], b);
            }
            se0 += __expf(acc[0]) + __expf(acc[1]);
            se1 += __expf(acc[2]) + __expf(acc[3]);
        }
        __syncthreads();
    }
    se0 += __shfl_xor_sync(0xffffffffu, se0, 1);
    se0 += __shfl_xor_sync(0xffffffffu, se0, 2);
    se1 += __shfl_xor_sync(0xffffffffu, se1, 1);
    se1 += __shfl_xor_sync(0xffffffffu, se1, 2);
    if (t4 == 0) {
        atomicAdd(&sS[r0], se0);
        atomicAdd(&sS[r0 + 8], se1);
    }
    __syncthreads();
    if (tid < DF_RB)
        dsum[((long long)h * T_ + t0 + tid) * 4 + vs] = sS[tid];
}

// ---------------------------------------------------------------------------
// Dict chain pass 2: weights out + recon partial over half of V.
// ---------------------------------------------------------------------------
__global__ void __launch_bounds__(128)
dict_pass2_kernel(const float* __restrict__ xhat, const float* __restrict__ emb,
                  const float* __restrict__ dsum, float* __restrict__ wout,
                  float* __restrict__ reconP)
{
    const int h  = blockIdx.y;
    const int t0 = blockIdx.x * DF_RB;
    const int vs = blockIdx.z;
    const int vbase = vs * (V_ / 2);
    const int NCH = (V_ / 2) / DF_VC;

    __shared__ __align__(16) float sA[DF_RB][68];
    __shared__ __align__(16) float sW[DF_RB][68];
    __shared__ __align__(16) float sE[2][DF_VC][68];
    __shared__ float sInv[DF_RB];

    const int tid  = threadIdx.x;
    const int lane = tid & 31;
    const int warp = tid >> 5;
    const int gid  = lane >> 2;
    const int t4   = lane & 3;
    const int wm   = warp >> 1;
    const int wn   = warp & 1;

    #pragma unroll
    for (int i = 0; i < 4; i++) {
        int l = tid + i * 128;
        int r = l >> 4, q = (l & 15) * 4;
        *reinterpret_cast<float4*>(&sA[r][q]) =
            *reinterpret_cast<const float4*>(xhat + (long long)(t0 + r) * D_ + h * HD_ + q);
    }
    if (tid < DF_RB) {
        const float* ds = dsum + ((long long)h * T_ + t0 + tid) * 4;
        sInv[tid] = 1.f / (ds[0] + ds[1] + ds[2] + ds[3]);
    }
    __syncthreads();

    const int r0 = wm * 16 + gid;
    unsigned afr[8][4];
    #pragma unroll
    for (int ks = 0; ks < 8; ks++) {
        int kk = ks * 8;
        afr[ks][0] = __float_as_uint(sA[r0    ][kk + t4]);
        afr[ks][1] = __float_as_uint(sA[r0 + 8][kk + t4]);
        afr[ks][2] = __float_as_uint(sA[r0    ][kk + t4 + 4]);
        afr[ks][3] = __float_as_uint(sA[r0 + 8][kk + t4 + 4]);
    }
    const float inv0 = sInv[r0], inv1 = sInv[r0 + 8];

    const float* Eh = emb + (long long)h * V_ * HD_;
    auto loadE = [&](int st, int v0) {
        #pragma unroll
        for (int i = 0; i < 8; i++) {
            int l = tid + i * 128;
            int r = l >> 4, q = (l & 15) * 4;
            cp_async16(&sE[st][r][q], Eh + (long long)(v0 + r) * HD_ + q);
        }
    };

    float racc[4][4];
    #pragma unroll
    for (int j = 0; j < 4; j++) {
        racc[j][0] = 0.f; racc[j][1] = 0.f; racc[j][2] = 0.f; racc[j][3] = 0.f;
    }

    loadE(0, vbase);
    cp_commit();
    for (int c = 0; c < NCH; c++) {
        if (c + 1 < NCH) loadE((c + 1) & 1, vbase + (c + 1) * DF_VC);
        cp_commit();
        cp_wait<1>();
        __syncthreads();
        const int st = c & 1;

        #pragma unroll
        for (int j = 0; j < 4; j++) {
            float acc[4] = {0.f, 0.f, 0.f, 0.f};
            #pragma unroll
            for (int ks = 0; ks < 8; ks++) {
                int kk = ks * 8;
                int v = wn * 32 + j * 8 + gid;
                unsigned b[2];
                b[0] = __float_as_uint(sE[st][v][kk + t4]);
                b[1] = __float_as_uint(sE[st][v][kk + t4 + 4]);
                mma_tf32(acc, afr[ks], b);
            }
            int vl = wn * 32 + j * 8 + t4 * 2;
            float w0 = __expf(acc[0]) * inv0;
            float w1 = __expf(acc[1]) * inv0;
            float w2 = __expf(acc[2]) * inv1;
            float w3 = __expf(acc[3]) * inv1;
            long long vg = (long long)vbase + c * DF_VC + vl;
            *reinterpret_cast<float2*>(wout + ((long long)(h*T_ + t0 + r0    ))*V_ + vg) = make_float2(w0, w1);
            *reinterpret_cast<float2*>(wout + ((long long)(h*T_ + t0 + r0 + 8))*V_ + vg) = make_float2(w2, w3);
            sW[r0    ][vl] = w0;  sW[r0    ][vl + 1] = w1;
            sW[r0 + 8][vl] = w2;  sW[r0 + 8][vl + 1] = w3;
        }
        __syncthreads();

        #pragma unroll
        for (int ks = 0; ks < 8; ks++) {
            int kk = ks * 8;
            unsigned aw[4];
            aw[0] = __float_as_uint(sW[r0    ][kk + t4]);
            aw[1] = __float_as_uint(sW[r0 + 8][kk + t4]);
            aw[2] = __float_as_uint(sW[r0    ][kk + t4 + 4]);
            aw[3] = __float_as_uint(sW[r0 + 8][kk + t4 + 4]);
            #pragma unroll
            for (int j = 0; j < 4; j++) {
                int e = wn * 32 + j * 8 + gid;
                unsigned b[2];
                b[0] = __float_as_uint(sE[st][kk + t4    ][e]);
                b[1] = __float_as_uint(sE[st][kk + t4 + 4][e]);
                mma_tf32(racc[j], aw, b);
            }
        }
        __syncthreads();
    }

    float* rp = reconP + (long long)vs * T_ * D_;
    #pragma unroll
    for (int j = 0; j < 4; j++) {
        int e = h * HD_ + wn * 32 + j * 8 + t4 * 2;
        *reinterpret_cast<float2*>(rp + (long long)(t0 + r0    ) * D_ + e) =
            make_float2(racc[j][0], racc[j][1]);
        *reinterpret_cast<float2*>(rp + (long long)(t0 + r0 + 8) * D_ + e) =
            make_float2(racc[j][2], racc[j][3]);
    }
}

// ---------------------------------------------------------------------------
// LayerNorm over D=768 of (a + b)
// ---------------------------------------------------------------------------
__global__ void ln2in_kernel(const float* __restrict__ a, const float* __restrict__ b,
                             const float* __restrict__ w, const float* __restrict__ bb,
                             float* __restrict__ out)
{
    const int t = blockIdx.x;
    const int tid = threadIdx.x;
    const float* pa = a + (long long)t * D_;
    const float* pb = b + (long long)t * D_;
    float x[3];
    float s = 0.f, ss = 0.f;
    #pragma unroll
    for (int i = 0; i < 3; i++) {
        int d = tid + i*256;
        float v = pa[d] + pb[d];
        x[i] = v; s += v; ss += v*v;
    }
    #pragma unroll
    for (int o = 16; o; o >>= 1) {
        s  += __shfl_xor_sync(0xffffffffu, s, o);
        ss += __shfl_xor_sync(0xffffffffu, ss, o);
    }
    __shared__ float rs[8], rss[8];
    __shared__ float s_mu, s_inv;
    if ((tid & 31) == 0) { rs[tid >> 5] = s; rss[tid >> 5] = ss; }
    __syncthreads();
    if (tid == 0) {
        float S = 0.f, SS = 0.f;
        #pragma unroll
        for (int i = 0; i < 8; i++) { S += rs[i]; SS += rss[i]; }
        float mu  = S * (1.f / D_);
        float var = SS * (1.f / D_) - mu*mu;
        s_mu = mu;
        s_inv = rsqrtf(var + 1e-5f);
    }
    __syncthreads();
    float mu = s_mu, inv = s_inv;
    #pragma unroll
    for (int i = 0; i < 3; i++) {
        int d = tid + i*256;
        out[(long long)t*D_ + d] = (x[i] - mu) * inv * w[d] + bb[d];
    }
}

// v[h,t,d] = sum_j v_fact[h,j] * xt[t, j*64+d]
__global__ void vmix_kernel(const float* __restrict__ xt, const float* __restrict__ vf,
                            float* __restrict__ v)
{
    int idx = blockIdx.x * 256 + threadIdx.x;
    int d = idx & (HD_-1);
    int t = (idx >> 6) & (T_-1);
    int h = idx >> 16;
    float s = 0.f;
    #pragma unroll
    for (int j = 0; j < H_; j++)
        s += vf[h*H_ + j] * xt[(long long)t*D_ + j*HD_ + d];
    v[idx] = s;
}

// xt_new[t, i*64+d] = xt + sum_j out_fact[i,j] * y[t, j*64+d]
__global__ void outmix_kernel(const float* __restrict__ xt, const float* __restrict__ of,
                              const float* __restrict__ y, float* __restrict__ o)
{
    int idx = blockIdx.x * 256 + threadIdx.x;
    int d = idx & (HD_-1);
    int i = (idx >> 6) % H_;
    int t = idx / D_;
    float s = 0.f;
    #pragma unroll
    for (int j = 0; j < H_; j++)
        s += of[i*H_ + j] * y[(long long)t*D_ + j*HD_ + d];
    o[idx] = xt[idx] + s;
}

// per-(h,t) LayerNorm over HD=64; input = sum of 4 split-K partials + proj bias
__global__ void dln_kernel(const float* __restrict__ xpP, const float* __restrict__ pb,
                           const float* __restrict__ w, const float* __restrict__ b,
                           float* __restrict__ xh)
{
    int bx = blockIdx.x;
    int t = bx & (T_-1);
    int h = bx >> 10;
    int lane = threadIdx.x;
    const long long base = (long long)t*D_ + h*HD_;
    const long long TD = (long long)T_*D_;
    float v0 = xpP[base + lane]      + xpP[base + lane + TD]
             + xpP[base + lane + 2*TD] + xpP[base + lane + 3*TD] + pb[h*HD_ + lane];
    float v1 = xpP[base + lane + 32] + xpP[base + lane + 32 + TD]
             + xpP[base + lane + 32 + 2*TD] + xpP[base + lane + 32 + 3*TD] + pb[h*HD_ + lane + 32];
    float s = v0 + v1, ss = v0*v0 + v1*v1;
    #pragma unroll
    for (int o = 16; o; o >>= 1) {
        s  += __shfl_xor_sync(0xffffffffu, s, o);
        ss += __shfl_xor_sync(0xffffffffu, ss, o);
    }
    float mu  = s * (1.f / HD_);
    float var = ss * (1.f / HD_) - mu*mu;
    float inv = rsqrtf(var + 1e-5f);
    float* q = xh + base;
    q[lane]      = (v0 - mu) * inv * w[h*HD_ + lane]      + b[h*HD_ + lane];
    q[lane + 32] = (v1 - mu) * inv * w[h*HD_ + lane + 32] + b[h*HD_ + lane + 32];
}

// xe_new = xe + reconP0 + reconP1 ; also store combined recon for the loss
__global__ void add2_kernel(const float* __restrict__ xe, const float* __restrict__ rp,
                            float* __restrict__ oxe, float* __restrict__ recon)
{
    int idx = blockIdx.x * 256 + threadIdx.x;
    float r = rp[idx] + rp[idx + T_*D_];
    recon[idx] = r;
    oxe[idx] = xe[idx] + r;
}

__global__ void loss_partial_kernel(const float* __restrict__ a, const float* __restrict__ b)
{
    double s = 0.0;
    for (int idx = blockIdx.x*256 + threadIdx.x; idx < T_*D_; idx += 256*256) {
        float d = a[idx] - b[idx];
        s += (double)d * (double)d;
    }
    __shared__ double sh[256];
    sh[threadIdx.x] = s;
    __syncthreads();
    for (int o = 128; o; o >>= 1) {
        if (threadIdx.x < o) sh[threadIdx.x] += sh[threadIdx.x + o];
        __syncthreads();
    }
    if (threadIdx.x == 0) g_lossPartial[blockIdx.x] = sh[0];
}

__global__ void loss_final_kernel(float* __restrict__ out)
{
    __shared__ double sh[256];
    sh[threadIdx.x] = g_lossPartial[threadIdx.x];
    __syncthreads();
    for (int o = 128; o; o >>= 1) {
        if (threadIdx.x < o) sh[threadIdx.x] += sh[threadIdx.x + o];
        __syncthreads();
    }
    if (threadIdx.x == 0) out[0] = (float)(sh[0] / (double)(T_*D_));
}

// ---------------------------------------------------------------------------
// Host launcher
// ---------------------------------------------------------------------------
extern "C" void kernel_launch(void* const* d_in, const int* in_sizes, int n_in,
                              void* d_out, int out_size)
{
    (void)in_sizes; (void)n_in; (void)out_size;
    const float* xt       = (const float*)d_in[0];
    const float* xe       = (const float*)d_in[1];
    const float* ln1_w    = (const float*)d_in[2];
    const float* ln1_b    = (const float*)d_in[3];
    const float* qk_w     = (const float*)d_in[4];
    const float* qk_b     = (const float*)d_in[5];
    const float* v_fact   = (const float*)d_in[6];
    const float* out_fact = (const float*)d_in[7];
    const float* ln2_w    = (const float*)d_in[8];
    const float* ln2_b    = (const float*)d_in[9];
    const float* fc_w     = (const float*)d_in[10];
    const float* fc_b     = (const float*)d_in[11];
    const float* proj_w   = (const float*)d_in[12];
    const float* proj_b   = (const float*)d_in[13];
    const float* dln_w    = (const float*)d_in[14];
    const float* dln_b    = (const float*)d_in[15];
    const float* dict_emb = (const float*)d_in[16];

    float* out    = (float*)d_out;
    float* o_xt   = out;
    float* o_xe   = out + OFF_XE;
    float* o_w    = out + OFF_W;
    float* o_loss = out + OFF_LOSS;

    float *p_xnorm, *p_qk, *p_v, *p_y, *p_x2, *p_h,
          *p_xpreP, *p_xhat, *p_dsum, *p_reconP, *p_recon;
    cudaGetSymbolAddress((void**)&p_xnorm,  g_xnorm);
    cudaGetSymbolAddress((void**)&p_qk,     g_qk);
    cudaGetSymbolAddress((void**)&p_v,      g_v);
    cudaGetSymbolAddress((void**)&p_y,      g_y);
    cudaGetSymbolAddress((void**)&p_x2,     g_x2);
    cudaGetSymbolAddress((void**)&p_h,      g_h);
    cudaGetSymbolAddress((void**)&p_xpreP,  g_xpreP);
    cudaGetSymbolAddress((void**)&p_xhat,   g_xhat);
    cudaGetSymbolAddress((void**)&p_dsum,   g_dsum);
    cudaGetSymbolAddress((void**)&p_reconP, g_reconP);
    cudaGetSymbolAddress((void**)&p_recon,  g_recon);

    // 1) x_norm = LN(xt + xe)
    ln2in_kernel<<<T_, 256>>>(xt, xe, ln1_w, ln1_b, p_xnorm);

    // 2) qk = x_norm @ qk_w^T + qk_b       [T, 1536]  (64x64 warp tile, 4 warps)
    gemm_tc<128,128,32,64,64,128><<<dim3(2*D_/128, T_/128, 1), 128>>>(
        p_xnorm, qk_w, p_qk, qk_b, D_, D_, D_, 2*D_, 0,0,0,0, 1.f, 1, 0, 0, 0, 1, 0, 0);

    // 3) v[h,t,d]
    vmix_kernel<<<H_*T_*HD_/256, 256>>>(xt, v_fact, p_v);

    // 4) fused flash attention v2 -> g_y[t, h*64+d]
    flash_attn_kernel<<<dim3(T_/FA_RB, H_), 128>>>(p_qk, p_v, p_y);

    // 5) xt_new = xt + out_fact-mix(y)
    outmix_kernel<<<T_*D_/256, 256>>>(xt, out_fact, p_y, o_xt);

    // 6) x2 = LN(xt_new + xe)
    ln2in_kernel<<<T_, 256>>>(o_xt, xe, ln2_w, ln2_b, p_x2);

    // 7) h = gelu(x2 @ fc_w^T + fc_b)   [T, 36864]  (64x64 warp tile, 1:1 LDS:mma)
    gemm_tc<128,128,32,64,64,128><<<dim3(T_/128, H_*FF_/128, 1), 128>>>(
        p_x2, fc_w, p_h, fc_b, D_, D_, D_, H_*FF_, 0,0,0,0, 1.f, 2, 0, 0, 1, 1, 0, 0);

    // 8) proj split-K=4: xpreP[ks] = h[h][k-range] @ proj_w[h][k-range]^T
    gemm_tc<64,64,32,32,32,128><<<dim3(1, T_/64, H_*4), 128>>>(
        p_h, proj_w, p_xpreP, nullptr, FF_, H_*FF_, FF_, D_,
        FF_, (long long)HD_*FF_, 64, 0, 1.f, 0, 0, 0, 0, 4, FF_/4, (long long)T_*D_);

    // 9) x_hat = per-head LN(sum of partials + proj_b)
    dln_kernel<<<H_*T_, 32>>>(p_xpreP, proj_b, dln_w, dln_b, p_xhat);

    // 10) dict pass 1: partial exp-sums (V split 4-way)
    dict_pass1_kernel<<<dim3(T_/DF_RB, H_, 4), 128>>>(p_xhat, dict_emb, p_dsum);

    // 11) dict pass 2: weights + recon partials (V split 2-way)
    dict_pass2_kernel<<<dim3(T_/DF_RB, H_, 2), 128>>>(p_xhat, dict_emb, p_dsum, o_w, p_reconP);

    // 12) xe_new = xe + recon ; store combined recon
    add2_kernel<<<T_*D_/256, 256>>>(xe, p_reconP, o_xe, p_recon);

    // 13) dict_loss = mean((x_hat - x_recon)^2)
    loss_partial_kernel<<<256, 256>>>(p_xhat, p_recon);
    loss_final_kernel<<<1, 256>>>(o_loss);
}

// round 17
// speedup vs baseline: 1.3073x; 1.0374x over previous
#include <cuda_runtime.h>
#include <math.h>

// ---------------------------------------------------------------------------
// Problem constants
// ---------------------------------------------------------------------------
#define T_  1024
#define D_  768
#define H_  12
#define FF_ 3072
#define V_  8192
#define HD_ 64

// output layout: xt_new [T*D] | xe_new [T*D] | dict_weights [H*T*V] | loss [1]
#define OFF_XE   (T_*D_)
#define OFF_W    (2*T_*D_)
#define OFF_LOSS (2*T_*D_ + H_*T_*V_)

// ---------------------------------------------------------------------------
// Device scratch (allocation-free: __device__ globals)
// ---------------------------------------------------------------------------
__device__ __align__(16) float g_xnorm[T_*D_];
__device__ __align__(16) float g_qk[T_*2*D_];
__device__ __align__(16) float g_v[H_*T_*HD_];
__device__ __align__(16) float g_y[T_*D_];
__device__ __align__(16) float g_x2[T_*D_];
__device__ __align__(16) float g_h[T_*H_*FF_];              // 151 MB
__device__ __align__(16) float g_xpreP[4*T_*D_];            // proj split-K partials
__device__ __align__(16) float g_xhat[T_*D_];
__device__ __align__(16) float g_dsum[H_*T_*4];             // dict exp-sum partials
__device__ __align__(16) float g_reconP[2*T_*D_];           // recon v-split partials
__device__ __align__(16) float g_recon[T_*D_];
__device__ double g_lossPartial[256];

// ---------------------------------------------------------------------------
// Helpers
// ---------------------------------------------------------------------------
__device__ __forceinline__ float gelu_exact(float x) {
    return 0.5f * x * (1.0f + erff(x * 0.70710678118654752f));
}

__device__ __forceinline__ void cp_async16(void* s, const void* g) {
    unsigned sa = (unsigned)__cvta_generic_to_shared(s);
    asm volatile("cp.async.cg.shared.global [%0], [%1], 16;\n" :: "r"(sa), "l"(g));
}
__device__ __forceinline__ void cp_commit() {
    asm volatile("cp.async.commit_group;\n");
}
template<int N>
__device__ __forceinline__ void cp_wait() {
    asm volatile("cp.async.wait_group %0;\n" :: "n"(N));
}

__device__ __forceinline__ void mma_tf32(float* c, const unsigned* a, const unsigned* b) {
    asm volatile(
        "mma.sync.aligned.m16n8k8.row.col.f32.tf32.tf32.f32 "
        "{%0,%1,%2,%3}, {%4,%5,%6,%7}, {%8,%9}, {%0,%1,%2,%3};\n"
        : "+f"(c[0]), "+f"(c[1]), "+f"(c[2]), "+f"(c[3])
        : "r"(a[0]), "r"(a[1]), "r"(a[2]), "r"(a[3]), "r"(b[0]), "r"(b[1]));
}

// ---------------------------------------------------------------------------
// Tensor-core NT GEMM (tf32 mma.sync m16n8k8), cp.async 2-stage pipeline.
//   C[m,n] = alpha * sum_k A[m,k]*B[n,k]   (+bias, +gelu) ; batched over z
// nsplit>1: split-K — blockIdx.z = zb*nsplit+zs, K range [zs*klen,(zs+1)*klen),
//           C += zs*sCsplit (partial buffers, mode must be 0).
// ---------------------------------------------------------------------------
template<int BM, int BN, int BK, int WM, int WN, int THREADS>
__global__ void __launch_bounds__(THREADS)
gemm_tc(const float* __restrict__ A, const float* __restrict__ B,
        float* __restrict__ C, const float* __restrict__ bias,
        int K, int lda, int ldb, int ldc,
        long long sA, long long sB, long long sC, long long sBias,
        float alpha, int mode, int causal, int kcap, int swapxy,
        int nsplit, int klen, long long sCsplit)
{
    constexpr int NWN = BN / WN;          // warps along N
    constexpr int TM  = WM / 16;          // mma tiles per warp along M
    constexpr int TN  = WN / 8;           // mma tiles per warp along N
    constexpr int LK  = BK + 4;           // smem row stride (words) -> conflict-free
    constexpr int LA  = BM * (BK/4) / THREADS;
    constexpr int LB  = BN * (BK/4) / THREADS;

    const int bx = blockIdx.x, by = blockIdx.y;
    const int m0 = (swapxy ? bx : by) * BM;
    const int n0 = (swapxy ? by : bx) * BN;
    if (causal && n0 > m0 + BM - 1) return;

    __shared__ __align__(16) float As[2][BM][LK];
    __shared__ __align__(16) float Bs[2][BN][LK];

    int zb = blockIdx.z, koff = 0;
    if (nsplit > 1) {
        int zs = zb % nsplit;
        zb = zb / nsplit;
        koff = zs * klen;
        C += zs * sCsplit;
        K = klen;
    }
    A += zb * sA + koff;  B += zb * sB + koff;  C += zb * sC;
    if (mode >= 1) bias += zb * sBias;

    const int tid  = threadIdx.x;
    const int lane = tid & 31;
    const int warp = tid >> 5;
    const int gid  = lane >> 2;
    const int t4   = lane & 3;
    const int wm   = warp / NWN;
    const int wn   = warp % NWN;

    float acc[TM][TN][4];
    #pragma unroll
    for (int i = 0; i < TM; i++)
        #pragma unroll
        for (int j = 0; j < TN; j++) {
            acc[i][j][0] = 0.f; acc[i][j][1] = 0.f;
            acc[i][j][2] = 0.f; acc[i][j][3] = 0.f;
        }

    int Keff = K;
    if (kcap) { int ke = m0 + BM; if (ke < K) Keff = ke; }
    const int niter = Keff / BK;

    auto load_stage = [&](int st, int k0) {
        #pragma unroll
        for (int i = 0; i < LA; i++) {
            int l = tid + i * THREADS;
            int r = l / (BK/4), q = (l % (BK/4)) * 4;
            cp_async16(&As[st][r][q], A + (long long)(m0 + r) * lda + k0 + q);
        }
        #pragma unroll
        for (int i = 0; i < LB; i++) {
            int l = tid + i * THREADS;
            int r = l / (BK/4), q = (l % (BK/4)) * 4;
            cp_async16(&Bs[st][r][q], B + (long long)(n0 + r) * ldb + k0 + q);
        }
    };

    load_stage(0, 0);
    cp_commit();
    if (niter > 1) load_stage(1, BK);
    cp_commit();

    for (int it = 0; it < niter; it++) {
        cp_wait<1>();
        __syncthreads();

        const int st = it & 1;
        #pragma unroll
        for (int kk = 0; kk < BK; kk += 8) {
            unsigned a[TM][4], b[TN][2];
            #pragma unroll
            for (int i = 0; i < TM; i++) {
                int r = wm * WM + i * 16 + gid;
                a[i][0] = __float_as_uint(As[st][r    ][kk + t4]);
                a[i][1] = __float_as_uint(As[st][r + 8][kk + t4]);
                a[i][2] = __float_as_uint(As[st][r    ][kk + t4 + 4]);
                a[i][3] = __float_as_uint(As[st][r + 8][kk + t4 + 4]);
            }
            #pragma unroll
            for (int j = 0; j < TN; j++) {
                int c = wn * WN + j * 8 + gid;
                b[j][0] = __float_as_uint(Bs[st][c][kk + t4]);
                b[j][1] = __float_as_uint(Bs[st][c][kk + t4 + 4]);
            }
            #pragma unroll
            for (int i = 0; i < TM; i++)
                #pragma unroll
                for (int j = 0; j < TN; j++)
                    mma_tf32(acc[i][j], a[i], b[j]);
        }
        __syncthreads();

        if (it + 2 < niter) load_stage(st, (it + 2) * BK);
        cp_commit();
    }

    #pragma unroll
    for (int i = 0; i < TM; i++) {
        const int m = m0 + wm * WM + i * 16 + gid;
        #pragma unroll
        for (int j = 0; j < TN; j++) {
            const int n = n0 + wn * WN + j * 8 + t4 * 2;
            float c0 = acc[i][j][0] * alpha, c1 = acc[i][j][1] * alpha;
            float c2 = acc[i][j][2] * alpha, c3 = acc[i][j][3] * alpha;
            if (mode >= 1) {
                float b0 = bias[n], b1 = bias[n + 1];
                c0 += b0; c1 += b1; c2 += b0; c3 += b1;
            }
            if (mode == 2) {
                c0 = gelu_exact(c0); c1 = gelu_exact(c1);
                c2 = gelu_exact(c2); c3 = gelu_exact(c3);
            }
            *reinterpret_cast<float2*>(C + (long long)m       * ldc + n) = make_float2(c0, c1);
            *reinterpret_cast<float2*>(C + (long long)(m + 8) * ldc + n) = make_float2(c2, c3);
        }
    }
}

// ---------------------------------------------------------------------------
// Fused flash attention v2: double-buffered K/V, reversed block order.
// Block: 32 q-rows x 1 head, 128 threads. grid (T/32, H) = 384 CTAs.
// ---------------------------------------------------------------------------
#define FA_RB 32
#define FA_KC 64

__global__ void __launch_bounds__(128)
flash_attn_kernel(const float* __restrict__ qk,   // [T][2D] (q | k)
                  const float* __restrict__ v,    // [H][T][64]
                  float* __restrict__ y)          // [T][D]
{
    const int h  = blockIdx.y;
    const int t0 = (gridDim.x - 1 - blockIdx.x) * FA_RB;   // longest blocks first
    const float slope = (h < 8) ? exp2f(-(float)(h+1)) : exp2f(-0.5f * (float)(h-7));

    __shared__ __align__(16) float sQP[FA_RB][68];
    __shared__ __align__(16) float sK[2][FA_KC][68];
    __shared__ __align__(16) float sV[2][FA_KC][68];
    __shared__ float sL[FA_RB];

    const int tid  = threadIdx.x;
    const int lane = tid & 31;
    const int warp = tid >> 5;
    const int gid  = lane >> 2;
    const int t4   = lane & 3;
    const int wm   = warp >> 1;
    const int wn   = warp & 1;

    #pragma unroll
    for (int i = 0; i < 4; i++) {
        int l = tid + i * 128;
        int r = l >> 4, q = (l & 15) * 4;
        *reinterpret_cast<float4*>(&sQP[r][q]) =
            *reinterpret_cast<const float4*>(qk + (long long)(t0 + r) * (2*D_) + h * HD_ + q);
    }
    if (tid < FA_RB) sL[tid] = 0.f;
    __syncthreads();

    const int r0 = wm * 16 + gid;
    unsigned afr[8][4];
    #pragma unroll
    for (int ks = 0; ks < 8; ks++) {
        int kk = ks * 8;
        afr[ks][0] = __float_as_uint(sQP[r0    ][kk + t4]);
        afr[ks][1] = __float_as_uint(sQP[r0 + 8][kk + t4]);
        afr[ks][2] = __float_as_uint(sQP[r0    ][kk + t4 + 4]);
        afr[ks][3] = __float_as_uint(sQP[r0 + 8][kk + t4 + 4]);
    }
    __syncthreads();   // sQP free -> becomes P tile

    float yacc[4][4];
    #pragma unroll
    for (int j = 0; j < 4; j++) {
        yacc[j][0] = 0.f; yacc[j][1] = 0.f; yacc[j][2] = 0.f; yacc[j][3] = 0.f;
    }
    float l0 = 0.f, l1 = 0.f;
    const int i0 = t0 + r0;
    const int nch = t0 / FA_KC + 1;

    auto loadKV = [&](int st, int c) {
        #pragma unroll
        for (int i = 0; i < 8; i++) {
            int l = tid + i * 128;
            int r = l >> 4, q = (l & 15) * 4;
            cp_async16(&sK[st][r][q], qk + (long long)(c*FA_KC + r) * (2*D_) + D_ + h * HD_ + q);
            cp_async16(&sV[st][r][q], v + ((long long)h * T_ + c*FA_KC + r) * HD_ + q);
        }
    };

    loadKV(0, 0);
    cp_commit();
    for (int c = 0; c < nch; c++) {
        if (c + 1 < nch) loadKV((c + 1) & 1, c + 1);
        cp_commit();
        cp_wait<1>();
        __syncthreads();
        const int st = c & 1;

        #pragma unroll
        for (int j = 0; j < 4; j++) {
            float acc[4] = {0.f, 0.f, 0.f, 0.f};
            #pragma unroll
            for (int ks = 0; ks < 8; ks++) {
                int kk = ks * 8;
                int vv = wn * 32 + j * 8 + gid;
                unsigned b[2];
                b[0] = __float_as_uint(sK[st][vv][kk + t4]);
                b[1] = __float_as_uint(sK[st][vv][kk + t4 + 4]);
                mma_tf32(acc, afr[ks], b);
            }
            int jl = wn * 32 + j * 8 + t4 * 2;
            int jj = c * FA_KC + jl;
            float p0 = (jj     <= i0    ) ? __expf(acc[0]*0.125f + slope*(float)(jj     - i0    )) : 0.f;
            float p1 = (jj + 1 <= i0    ) ? __expf(acc[1]*0.125f + slope*(float)(jj + 1 - i0    )) : 0.f;
            float p2 = (jj     <= i0 + 8) ? __expf(acc[2]*0.125f + slope*(float)(jj     - i0 - 8)) : 0.f;
            float p3 = (jj + 1 <= i0 + 8) ? __expf(acc[3]*0.125f + slope*(float)(jj + 1 - i0 - 8)) : 0.f;
            l0 += p0 + p1;
            l1 += p2 + p3;
            sQP[r0    ][jl] = p0;  sQP[r0    ][jl + 1] = p1;
            sQP[r0 + 8][jl] = p2;  sQP[r0 + 8][jl + 1] = p3;
        }
        __syncthreads();

        #pragma unroll
        for (int ks = 0; ks < 8; ks++) {
            int kk = ks * 8;
            unsigned aw[4];
            aw[0] = __float_as_uint(sQP[r0    ][kk + t4]);
            aw[1] = __float_as_uint(sQP[r0 + 8][kk + t4]);
            aw[2] = __float_as_uint(sQP[r0    ][kk + t4 + 4]);
            aw[3] = __float_as_uint(sQP[r0 + 8][kk + t4 + 4]);
            #pragma unroll
            for (int j = 0; j < 4; j++) {
                int e = wn * 32 + j * 8 + gid;
                unsigned b[2];
                b[0] = __float_as_uint(sV[st][kk + t4    ][e]);
                b[1] = __float_as_uint(sV[st][kk + t4 + 4][e]);
                mma_tf32(yacc[j], aw, b);
            }
        }
        __syncthreads();
    }

    l0 += __shfl_xor_sync(0xffffffffu, l0, 1);
    l0 += __shfl_xor_sync(0xffffffffu, l0, 2);
    l1 += __shfl_xor_sync(0xffffffffu, l1, 1);
    l1 += __shfl_xor_sync(0xffffffffu, l1, 2);
    if (t4 == 0) {
        atomicAdd(&sL[r0], l0);
        atomicAdd(&sL[r0 + 8], l1);
    }
    __syncthreads();
    const float inv0 = 1.f / sL[r0], inv1 = 1.f / sL[r0 + 8];

    #pragma unroll
    for (int j = 0; j < 4; j++) {
        int e = h * HD_ + wn * 32 + j * 8 + t4 * 2;
        *reinterpret_cast<float2*>(y + (long long)(t0 + r0    ) * D_ + e) =
            make_float2(yacc[j][0] * inv0, yacc[j][1] * inv0);
        *reinterpret_cast<float2*>(y + (long long)(t0 + r0 + 8) * D_ + e) =
            make_float2(yacc[j][2] * inv1, yacc[j][3] * inv1);
    }
}

// ---------------------------------------------------------------------------
// Dict chain pass 1 (RB=64, 256 threads): partial exp-sums over a quarter of V.
// grid (T/64, H, 4). Warps: wm=warp>>1 row-group, wn=warp&1 col-half.
// ---------------------------------------------------------------------------
#define DF_RB 64
#define DF_VC 64

__global__ void __launch_bounds__(256)
dict_pass1_kernel(const float* __restrict__ xhat, const float* __restrict__ emb,
                  float* __restrict__ dsum)
{
    const int h  = blockIdx.y;
    const int t0 = blockIdx.x * DF_RB;
    const int vs = blockIdx.z;
    const int vbase = vs * (V_ / 4);
    const int NCH = (V_ / 4) / DF_VC;     // 32

    __shared__ __align__(16) float sA[DF_RB][68];
    __shared__ __align__(16) float sE[2][DF_VC][68];
    __shared__ float sS[DF_RB];

    const int tid  = threadIdx.x;
    const int lane = tid & 31;
    const int warp = tid >> 5;
    const int gid  = lane >> 2;
    const int t4   = lane & 3;
    const int wm   = warp >> 1;           // 0..3
    const int wn   = warp & 1;            // 0..1

    #pragma unroll
    for (int i = 0; i < 4; i++) {
        int l = tid + i * 256;            // 64 rows * 16 float4
        int r = l >> 4, q = (l & 15) * 4;
        *reinterpret_cast<float4*>(&sA[r][q]) =
            *reinterpret_cast<const float4*>(xhat + (long long)(t0 + r) * D_ + h * HD_ + q);
    }
    if (tid < DF_RB) sS[tid] = 0.f;
    __syncthreads();

    const int r0 = wm * 16 + gid;
    unsigned afr[8][4];
    #pragma unroll
    for (int ks = 0; ks < 8; ks++) {
        int kk = ks * 8;
        afr[ks][0] = __float_as_uint(sA[r0    ][kk + t4]);
        afr[ks][1] = __float_as_uint(sA[r0 + 8][kk + t4]);
        afr[ks][2] = __float_as_uint(sA[r0    ][kk + t4 + 4]);
        afr[ks][3] = __float_as_uint(sA[r0 + 8][kk + t4 + 4]);
    }

    const float* Eh = emb + (long long)h * V_ * HD_;
    auto loadE = [&](int st, int v0) {
        #pragma unroll
        for (int i = 0; i < 4; i++) {     // 64 rows * 16 float4 = 1024 -> 4/thread
            int l = tid + i * 256;
            int r = l >> 4, q = (l & 15) * 4;
            cp_async16(&sE[st][r][q], Eh + (long long)(v0 + r) * HD_ + q);
        }
    };

    float se0 = 0.f, se1 = 0.f;
    loadE(0, vbase);
    cp_commit();
    for (int c = 0; c < NCH; c++) {
        if (c + 1 < NCH) loadE((c + 1) & 1, vbase + (c + 1) * DF_VC);
        cp_commit();
        cp_wait<1>();
        __syncthreads();
        const int st = c & 1;

        #pragma unroll
        for (int j = 0; j < 4; j++) {
            float acc[4] = {0.f, 0.f, 0.f, 0.f};
            #pragma unroll
            for (int ks = 0; ks < 8; ks++) {
                int kk = ks * 8;
                int v = wn * 32 + j * 8 + gid;
                unsigned b[2];
                b[0] = __float_as_uint(sE[st][v][kk + t4]);
                b[1] = __float_as_uint(sE[st][v][kk + t4 + 4]);
                mma_tf32(acc, afr[ks], b);
            }
            se0 += __expf(acc[0]) + __expf(acc[1]);
            se1 += __expf(acc[2]) + __expf(acc[3]);
        }
        __syncthreads();
    }
    se0 += __shfl_xor_sync(0xffffffffu, se0, 1);
    se0 += __shfl_xor_sync(0xffffffffu, se0, 2);
    se1 += __shfl_xor_sync(0xffffffffu, se1, 1);
    se1 += __shfl_xor_sync(0xffffffffu, se1, 2);
    if (t4 == 0) {
        atomicAdd(&sS[r0], se0);
        atomicAdd(&sS[r0 + 8], se1);
    }
    __syncthreads();
    if (tid < DF_RB)
        dsum[((long long)h * T_ + t0 + tid) * 4 + vs] = sS[tid];
}

// ---------------------------------------------------------------------------
// Dict chain pass 2 (RB=64, 256 threads): weights out + recon partial, half of V.
// grid (T/64, H, 2).
// ---------------------------------------------------------------------------
__global__ void __launch_bounds__(256)
dict_pass2_kernel(const float* __restrict__ xhat, const float* __restrict__ emb,
                  const float* __restrict__ dsum, float* __restrict__ wout,
                  float* __restrict__ reconP)
{
    const int h  = blockIdx.y;
    const int t0 = blockIdx.x * DF_RB;
    const int vs = blockIdx.z;
    const int vbase = vs * (V_ / 2);
    const int NCH = (V_ / 2) / DF_VC;     // 64

    __shared__ __align__(16) float sA[DF_RB][68];
    __shared__ __align__(16) float sW[DF_RB][68];
    __shared__ __align__(16) float sE[2][DF_VC][68];
    __shared__ float sInv[DF_RB];

    const int tid  = threadIdx.x;
    const int lane = tid & 31;
    const int warp = tid >> 5;
    const int gid  = lane >> 2;
    const int t4   = lane & 3;
    const int wm   = warp >> 1;
    const int wn   = warp & 1;

    #pragma unroll
    for (int i = 0; i < 4; i++) {
        int l = tid + i * 256;
        int r = l >> 4, q = (l & 15) * 4;
        *reinterpret_cast<float4*>(&sA[r][q]) =
            *reinterpret_cast<const float4*>(xhat + (long long)(t0 + r) * D_ + h * HD_ + q);
    }
    if (tid < DF_RB) {
        const float* ds = dsum + ((long long)h * T_ + t0 + tid) * 4;
        sInv[tid] = 1.f / (ds[0] + ds[1] + ds[2] + ds[3]);
    }
    __syncthreads();

    const int r0 = wm * 16 + gid;
    unsigned afr[8][4];
    #pragma unroll
    for (int ks = 0; ks < 8; ks++) {
        int kk = ks * 8;
        afr[ks][0] = __float_as_uint(sA[r0    ][kk + t4]);
        afr[ks][1] = __float_as_uint(sA[r0 + 8][kk + t4]);
        afr[ks][2] = __float_as_uint(sA[r0    ][kk + t4 + 4]);
        afr[ks][3] = __float_as_uint(sA[r0 + 8][kk + t4 + 4]);
    }
    const float inv0 = sInv[r0], inv1 = sInv[r0 + 8];

    const float* Eh = emb + (long long)h * V_ * HD_;
    auto loadE = [&](int st, int v0) {
        #pragma unroll
        for (int i = 0; i < 4; i++) {
            int l = tid + i * 256;
            int r = l >> 4, q = (l & 15) * 4;
            cp_async16(&sE[st][r][q], Eh + (long long)(v0 + r) * HD_ + q);
        }
    };

    float racc[4][4];
    #pragma unroll
    for (int j = 0; j < 4; j++) {
        racc[j][0] = 0.f; racc[j][1] = 0.f; racc[j][2] = 0.f; racc[j][3] = 0.f;
    }

    loadE(0, vbase);
    cp_commit();
    for (int c = 0; c < NCH; c++) {
        if (c + 1 < NCH) loadE((c + 1) & 1, vbase + (c + 1) * DF_VC);
        cp_commit();
        cp_wait<1>();
        __syncthreads();
        const int st = c & 1;

        #pragma unroll
        for (int j = 0; j < 4; j++) {
            float acc[4] = {0.f, 0.f, 0.f, 0.f};
            #pragma unroll
            for (int ks = 0; ks < 8; ks++) {
                int kk = ks * 8;
                int v = wn * 32 + j * 8 + gid;
                unsigned b[2];
                b[0] = __float_as_uint(sE[st][v][kk + t4]);
                b[1] = __float_as_uint(sE[st][v][kk + t4 + 4]);
                mma_tf32(acc, afr[ks], b);
            }
            int vl = wn * 32 + j * 8 + t4 * 2;
            float w0 = __expf(acc[0]) * inv0;
            float w1 = __expf(acc[1]) * inv0;
            float w2 = __expf(acc[2]) * inv1;
            float w3 = __expf(acc[3]) * inv1;
            long long vg = (long long)vbase + c * DF_VC + vl;
            *reinterpret_cast<float2*>(wout + ((long long)(h*T_ + t0 + r0    ))*V_ + vg) = make_float2(w0, w1);
            *reinterpret_cast<float2*>(wout + ((long long)(h*T_ + t0 + r0 + 8))*V_ + vg) = make_float2(w2, w3);
            sW[r0    ][vl] = w0;  sW[r0    ][vl + 1] = w1;
            sW[r0 + 8][vl] = w2;  sW[r0 + 8][vl + 1] = w3;
        }
        __syncthreads();

        #pragma unroll
        for (int ks = 0; ks < 8; ks++) {
            int kk = ks * 8;
            unsigned aw[4];
            aw[0] = __float_as_uint(sW[r0    ][kk + t4]);
            aw[1] = __float_as_uint(sW[r0 + 8][kk + t4]);
            aw[2] = __float_as_uint(sW[r0    ][kk + t4 + 4]);
            aw[3] = __float_as_uint(sW[r0 + 8][kk + t4 + 4]);
            #pragma unroll
            for (int j = 0; j < 4; j++) {
                int e = wn * 32 + j * 8 + gid;
                unsigned b[2];
                b[0] = __float_as_uint(sE[st][kk + t4    ][e]);
                b[1] = __float_as_uint(sE[st][kk + t4 + 4][e]);
                mma_tf32(racc[j], aw, b);
            }
        }
        __syncthreads();
    }

    float* rp = reconP + (long long)vs * T_ * D_;
    #pragma unroll
    for (int j = 0; j < 4; j++) {
        int e = h * HD_ + wn * 32 + j * 8 + t4 * 2;
        *reinterpret_cast<float2*>(rp + (long long)(t0 + r0    ) * D_ + e) =
            make_float2(racc[j][0], racc[j][1]);
        *reinterpret_cast<float2*>(rp + (long long)(t0 + r0 + 8) * D_ + e) =
            make_float2(racc[j][2], racc[j][3]);
    }
}

// ---------------------------------------------------------------------------
// LayerNorm over D=768 of (a + b)
// ---------------------------------------------------------------------------
__global__ void ln2in_kernel(const float* __restrict__ a, const float* __restrict__ b,
                             const float* __restrict__ w, const float* __restrict__ bb,
                             float* __restrict__ out)
{
    const int t = blockIdx.x;
    const int tid = threadIdx.x;
    const float* pa = a + (long long)t * D_;
    const float* pb = b + (long long)t * D_;
    float x[3];
    float s = 0.f, ss = 0.f;
    #pragma unroll
    for (int i = 0; i < 3; i++) {
        int d = tid + i*256;
        float v = pa[d] + pb[d];
        x[i] = v; s += v; ss += v*v;
    }
    #pragma unroll
    for (int o = 16; o; o >>= 1) {
        s  += __shfl_xor_sync(0xffffffffu, s, o);
        ss += __shfl_xor_sync(0xffffffffu, ss, o);
    }
    __shared__ float rs[8], rss[8];
    __shared__ float s_mu, s_inv;
    if ((tid & 31) == 0) { rs[tid >> 5] = s; rss[tid >> 5] = ss; }
    __syncthreads();
    if (tid == 0) {
        float S = 0.f, SS = 0.f;
        #pragma unroll
        for (int i = 0; i < 8; i++) { S += rs[i]; SS += rss[i]; }
        float mu  = S * (1.f / D_);
        float var = SS * (1.f / D_) - mu*mu;
        s_mu = mu;
        s_inv = rsqrtf(var + 1e-5f);
    }
    __syncthreads();
    float mu = s_mu, inv = s_inv;
    #pragma unroll
    for (int i = 0; i < 3; i++) {
        int d = tid + i*256;
        out[(long long)t*D_ + d] = (x[i] - mu) * inv * w[d] + bb[d];
    }
}

// v[h,t,d] = sum_j v_fact[h,j] * xt[t, j*64+d]
__global__ void vmix_kernel(const float* __restrict__ xt, const float* __restrict__ vf,
                            float* __restrict__ v)
{
    int idx = blockIdx.x * 256 + threadIdx.x;
    int d = idx & (HD_-1);
    int t = (idx >> 6) & (T_-1);
    int h = idx >> 16;
    float s = 0.f;
    #pragma unroll
    for (int j = 0; j < H_; j++)
        s += vf[h*H_ + j] * xt[(long long)t*D_ + j*HD_ + d];
    v[idx] = s;
}

// xt_new[t, i*64+d] = xt + sum_j out_fact[i,j] * y[t, j*64+d]
__global__ void outmix_kernel(const float* __restrict__ xt, const float* __restrict__ of,
                              const float* __restrict__ y, float* __restrict__ o)
{
    int idx = blockIdx.x * 256 + threadIdx.x;
    int d = idx & (HD_-1);
    int i = (idx >> 6) % H_;
    int t = idx / D_;
    float s = 0.f;
    #pragma unroll
    for (int j = 0; j < H_; j++)
        s += of[i*H_ + j] * y[(long long)t*D_ + j*HD_ + d];
    o[idx] = xt[idx] + s;
}

// per-(h,t) LayerNorm over HD=64; input = sum of 4 split-K partials + proj bias
__global__ void dln_kernel(const float* __restrict__ xpP, const float* __restrict__ pb,
                           const float* __restrict__ w, const float* __restrict__ b,
                           float* __restrict__ xh)
{
    int bx = blockIdx.x;
    int t = bx & (T_-1);
    int h = bx >> 10;
    int lane = threadIdx.x;
    const long long base = (long long)t*D_ + h*HD_;
    const long long TD = (long long)T_*D_;
    float v0 = xpP[base + lane]      + xpP[base + lane + TD]
             + xpP[base + lane + 2*TD] + xpP[base + lane + 3*TD] + pb[h*HD_ + lane];
    float v1 = xpP[base + lane + 32] + xpP[base + lane + 32 + TD]
             + xpP[base + lane + 32 + 2*TD] + xpP[base + lane + 32 + 3*TD] + pb[h*HD_ + lane + 32];
    float s = v0 + v1, ss = v0*v0 + v1*v1;
    #pragma unroll
    for (int o = 16; o; o >>= 1) {
        s  += __shfl_xor_sync(0xffffffffu, s, o);
        ss += __shfl_xor_sync(0xffffffffu, ss, o);
    }
    float mu  = s * (1.f / HD_);
    float var = ss * (1.f / HD_) - mu*mu;
    float inv = rsqrtf(var + 1e-5f);
    float* q = xh + base;
    q[lane]      = (v0 - mu) * inv * w[h*HD_ + lane]      + b[h*HD_ + lane];
    q[lane + 32] = (v1 - mu) * inv * w[h*HD_ + lane + 32] + b[h*HD_ + lane + 32];
}

// xe_new = xe + reconP0 + reconP1 ; also store combined recon for the loss
__global__ void add2_kernel(const float* __restrict__ xe, const float* __restrict__ rp,
                            float* __restrict__ oxe, float* __restrict__ recon)
{
    int idx = blockIdx.x * 256 + threadIdx.x;
    float r = rp[idx] + rp[idx + T_*D_];
    recon[idx] = r;
    oxe[idx] = xe[idx] + r;
}

__global__ void loss_partial_kernel(const float* __restrict__ a, const float* __restrict__ b)
{
    double s = 0.0;
    for (int idx = blockIdx.x*256 + threadIdx.x; idx < T_*D_; idx += 256*256) {
        float d = a[idx] - b[idx];
        s += (double)d * (double)d;
    }
    __shared__ double sh[256];
    sh[threadIdx.x] = s;
    __syncthreads();
    for (int o = 128; o; o >>= 1) {
        if (threadIdx.x < o) sh[threadIdx.x] += sh[threadIdx.x + o];
        __syncthreads();
    }
    if (threadIdx.x == 0) g_lossPartial[blockIdx.x] = sh[0];
}

__global__ void loss_final_kernel(float* __restrict__ out)
{
    __shared__ double sh[256];
    sh[threadIdx.x] = g_lossPartial[threadIdx.x];
    __syncthreads();
    for (int o = 128; o; o >>= 1) {
        if (threadIdx.x < o) sh[threadIdx.x] += sh[threadIdx.x + o];
        __syncthreads();
    }
    if (threadIdx.x == 0) out[0] = (float)(sh[0] / (double)(T_*D_));
}

// ---------------------------------------------------------------------------
// Host launcher
// ---------------------------------------------------------------------------
extern "C" void kernel_launch(void* const* d_in, const int* in_sizes, int n_in,
                              void* d_out, int out_size)
{
    (void)in_sizes; (void)n_in; (void)out_size;
    const float* xt       = (const float*)d_in[0];
    const float* xe       = (const float*)d_in[1];
    const float* ln1_w    = (const float*)d_in[2];
    const float* ln1_b    = (const float*)d_in[3];
    const float* qk_w     = (const float*)d_in[4];
    const float* qk_b     = (const float*)d_in[5];
    const float* v_fact   = (const float*)d_in[6];
    const float* out_fact = (const float*)d_in[7];
    const float* ln2_w    = (const float*)d_in[8];
    const float* ln2_b    = (const float*)d_in[9];
    const float* fc_w     = (const float*)d_in[10];
    const float* fc_b     = (const float*)d_in[11];
    const float* proj_w   = (const float*)d_in[12];
    const float* proj_b   = (const float*)d_in[13];
    const float* dln_w    = (const float*)d_in[14];
    const float* dln_b    = (const float*)d_in[15];
    const float* dict_emb = (const float*)d_in[16];

    float* out    = (float*)d_out;
    float* o_xt   = out;
    float* o_xe   = out + OFF_XE;
    float* o_w    = out + OFF_W;
    float* o_loss = out + OFF_LOSS;

    float *p_xnorm, *p_qk, *p_v, *p_y, *p_x2, *p_h,
          *p_xpreP, *p_xhat, *p_dsum, *p_reconP, *p_recon;
    cudaGetSymbolAddress((void**)&p_xnorm,  g_xnorm);
    cudaGetSymbolAddress((void**)&p_qk,     g_qk);
    cudaGetSymbolAddress((void**)&p_v,      g_v);
    cudaGetSymbolAddress((void**)&p_y,      g_y);
    cudaGetSymbolAddress((void**)&p_x2,     g_x2);
    cudaGetSymbolAddress((void**)&p_h,      g_h);
    cudaGetSymbolAddress((void**)&p_xpreP,  g_xpreP);
    cudaGetSymbolAddress((void**)&p_xhat,   g_xhat);
    cudaGetSymbolAddress((void**)&p_dsum,   g_dsum);
    cudaGetSymbolAddress((void**)&p_reconP, g_reconP);
    cudaGetSymbolAddress((void**)&p_recon,  g_recon);

    // 1) x_norm = LN(xt + xe)
    ln2in_kernel<<<T_, 256>>>(xt, xe, ln1_w, ln1_b, p_xnorm);

    // 2) qk = x_norm @ qk_w^T + qk_b       [T, 1536]
    gemm_tc<128,128,32,64,64,128><<<dim3(2*D_/128, T_/128, 1), 128>>>(
        p_xnorm, qk_w, p_qk, qk_b, D_, D_, D_, 2*D_, 0,0,0,0, 1.f, 1, 0, 0, 0, 1, 0, 0);

    // 3) v[h,t,d]
    vmix_kernel<<<H_*T_*HD_/256, 256>>>(xt, v_fact, p_v);

    // 4) fused flash attention v2 -> g_y[t, h*64+d]
    flash_attn_kernel<<<dim3(T_/FA_RB, H_), 128>>>(p_qk, p_v, p_y);

    // 5) xt_new = xt + out_fact-mix(y)
    outmix_kernel<<<T_*D_/256, 256>>>(xt, out_fact, p_y, o_xt);

    // 6) x2 = LN(xt_new + xe)
    ln2in_kernel<<<T_, 256>>>(o_xt, xe, ln2_w, ln2_b, p_x2);

    // 7) h = gelu(x2 @ fc_w^T + fc_b)   [T, 36864]
    gemm_tc<128,128,32,64,64,128><<<dim3(T_/128, H_*FF_/128, 1), 128>>>(
        p_x2, fc_w, p_h, fc_b, D_, D_, D_, H_*FF_, 0,0,0,0, 1.f, 2, 0, 0, 1, 1, 0, 0);

    // 8) proj split-K=4: xpreP[ks] = h[h][k-range] @ proj_w[h][k-range]^T
    gemm_tc<64,64,32,32,32,128><<<dim3(1, T_/64, H_*4), 128>>>(
        p_h, proj_w, p_xpreP, nullptr, FF_, H_*FF_, FF_, D_,
        FF_, (long long)HD_*FF_, 64, 0, 1.f, 0, 0, 0, 0, 4, FF_/4, (long long)T_*D_);

    // 9) x_hat = per-head LN(sum of partials + proj_b)
    dln_kernel<<<H_*T_, 32>>>(p_xpreP, proj_b, dln_w, dln_b, p_xhat);

    // 10) dict pass 1: partial exp-sums (RB=64, V split 4-way)
    dict_pass1_kernel<<<dim3(T_/DF_RB, H_, 4), 256>>>(p_xhat, dict_emb, p_dsum);

    // 11) dict pass 2: weights + recon partials (RB=64, V split 2-way)
    dict_pass2_kernel<<<dim3(T_/DF_RB, H_, 2), 256>>>(p_xhat, dict_emb, p_dsum, o_w, p_reconP);

    // 12) xe_new = xe + recon ; store combined recon
    add2_kernel<<<T_*D_/256, 256>>>(xe, p_reconP, o_xe, p_recon);

    // 13) dict_loss = mean((x_hat - x_recon)^2)
    loss_partial_kernel<<<256, 256>>>(p_xhat, p_recon);
    loss_final_kernel<<<1, 256>>>(o_loss);
}